// round 5
// baseline (speedup 1.0000x reference)
#include <cuda_runtime.h>
#include <cuda_bf16.h>
#include <cstdint>

#define DMm  1024
#define Hh   16
#define Dd   64
#define Bb   2
#define Ss   2048
#define NTOK (Bb*Ss)   // 4096

// ---------------------------------------------------------------------------
// Static device scratch
// ---------------------------------------------------------------------------
__device__ float g_QH [(size_t)Bb*Hh*Ss*Dd];
__device__ float g_KH [(size_t)Bb*Hh*Ss*Dd];
__device__ float g_VH [(size_t)Bb*Hh*Ss*Dd];
__device__ float g_CTX[(size_t)NTOK*DMm];
__device__ __nv_bfloat16 g_Xhi [(size_t)NTOK*DMm];
__device__ __nv_bfloat16 g_Xlo [(size_t)NTOK*DMm];
__device__ __nv_bfloat16 g_WThi[(size_t)DMm*DMm];   // [N][K]
__device__ __nv_bfloat16 g_WTlo[(size_t)DMm*DMm];

// ---------------------------------------------------------------------------
// Warp MMA helpers (base ISA sm_80+, valid on compute_103)
// ---------------------------------------------------------------------------
__device__ __forceinline__ uint32_t smem_u32(const void* p) {
    uint32_t a;
    asm("{ .reg .u64 t; cvta.to.shared.u64 t, %1; cvt.u32.u64 %0, t; }"
        : "=r"(a) : "l"(p));
    return a;
}

__device__ __forceinline__ void ldsm_x4(uint32_t* r, uint32_t addr) {
    asm volatile("ldmatrix.sync.aligned.m8n8.x4.shared.b16 {%0,%1,%2,%3}, [%4];"
        : "=r"(r[0]), "=r"(r[1]), "=r"(r[2]), "=r"(r[3]) : "r"(addr));
}

__device__ __forceinline__ void ldsm_x4_t(uint32_t* r, uint32_t addr) {
    asm volatile("ldmatrix.sync.aligned.m8n8.x4.trans.shared.b16 {%0,%1,%2,%3}, [%4];"
        : "=r"(r[0]), "=r"(r[1]), "=r"(r[2]), "=r"(r[3]) : "r"(addr));
}

__device__ __forceinline__ void mma16816(float* c, const uint32_t* a, const uint32_t* b) {
    asm volatile(
        "mma.sync.aligned.m16n8k16.row.col.f32.bf16.bf16.f32 "
        "{%0,%1,%2,%3}, {%4,%5,%6,%7}, {%8,%9}, {%0,%1,%2,%3};"
        : "+f"(c[0]), "+f"(c[1]), "+f"(c[2]), "+f"(c[3])
        : "r"(a[0]), "r"(a[1]), "r"(a[2]), "r"(a[3]), "r"(b[0]), "r"(b[1]));
}

// FFMA-pipe exp: 2^(x*log2e), deg-6 poly on [-0.5,0.5], rel err ~1e-6
__device__ __forceinline__ float exp_fast(float x) {
    float t = x * 1.4426950408889634f;
    t = fminf(fmaxf(t, -126.f), 126.f);
    float fi = rintf(t);
    float f  = t - fi;
    int   ei = (int)fi;
    float p = 1.5403530e-4f;
    p = fmaf(p, f, 1.33335581e-3f);
    p = fmaf(p, f, 9.61812911e-3f);
    p = fmaf(p, f, 5.55041087e-2f);
    p = fmaf(p, f, 2.40226507e-1f);
    p = fmaf(p, f, 6.93147181e-1f);
    p = fmaf(p, f, 1.0f);
    return __int_as_float(__float_as_int(p) + (ei << 23));
}

__device__ __forceinline__ ushort bfu(__nv_bfloat16 h) {
    return __bfloat16_as_ushort(h);
}

// split a float4 into hi/lo bf16 quads
__device__ __forceinline__ void split4(float4 v, uint2& hi, uint2& lo) {
    __nv_bfloat16 h0 = __float2bfloat16_rn(v.x);
    __nv_bfloat16 h1 = __float2bfloat16_rn(v.y);
    __nv_bfloat16 h2 = __float2bfloat16_rn(v.z);
    __nv_bfloat16 h3 = __float2bfloat16_rn(v.w);
    hi.x = (uint32_t)bfu(h0) | ((uint32_t)bfu(h1) << 16);
    hi.y = (uint32_t)bfu(h2) | ((uint32_t)bfu(h3) << 16);
    __nv_bfloat16 l0 = __float2bfloat16_rn(v.x - __bfloat162float(h0));
    __nv_bfloat16 l1 = __float2bfloat16_rn(v.y - __bfloat162float(h1));
    __nv_bfloat16 l2 = __float2bfloat16_rn(v.z - __bfloat162float(h2));
    __nv_bfloat16 l3 = __float2bfloat16_rn(v.w - __bfloat162float(h3));
    lo.x = (uint32_t)bfu(l0) | ((uint32_t)bfu(l1) << 16);
    lo.y = (uint32_t)bfu(l2) | ((uint32_t)bfu(l3) << 16);
}

// ---------------------------------------------------------------------------
// fp32 -> bf16 hi/lo split of X (or g_CTX)
// ---------------------------------------------------------------------------
__global__ __launch_bounds__(256) void convert_split_kernel(
    const float* __restrict__ Xext, int use_ctx)
{
    const float* X = use_ctx ? g_CTX : Xext;
    size_t i = ((size_t)blockIdx.x * 256 + threadIdx.x) * 4;
    float4 v = *(const float4*)(X + i);
    uint2 hi, lo;
    split4(v, hi, lo);
    *(uint2*)(g_Xhi + i) = hi;
    *(uint2*)(g_Xlo + i) = lo;
}

// ---------------------------------------------------------------------------
// W [K][N] fp32 -> WT [N][K] bf16 hi/lo
// ---------------------------------------------------------------------------
__global__ __launch_bounds__(256) void transW_kernel(const float* __restrict__ W)
{
    __shared__ float t[32][33];
    int nx = blockIdx.x * 32, ky = blockIdx.y * 32;
    int txx = threadIdx.x, tyy = threadIdx.y;   // block (32, 8)
#pragma unroll
    for (int j = 0; j < 4; j++)
        t[tyy + j*8][txx] = W[(size_t)(ky + tyy + j*8)*DMm + nx + txx];
    __syncthreads();
#pragma unroll
    for (int j = 0; j < 4; j++) {
        float val = t[txx][tyy + j*8];
        __nv_bfloat16 h = __float2bfloat16_rn(val);
        size_t o = (size_t)(nx + tyy + j*8)*DMm + ky + txx;
        g_WThi[o] = h;
        g_WTlo[o] = __float2bfloat16_rn(val - __bfloat162float(h));
    }
}

// ---------------------------------------------------------------------------
// HMMA projection GEMM (proven in R4): D = X @ W + bias, bf16x3 split.
// ---------------------------------------------------------------------------
__global__ __launch_bounds__(256, 1) void proj_mma_kernel(
    const float* __restrict__ bias, float* __restrict__ Yext, int mode)
{
    __shared__ __align__(16) __nv_bfloat16 sA[2][128][40];
    __shared__ __align__(16) __nv_bfloat16 sB[2][128][40];

    int tid  = threadIdx.x;
    int lane = tid & 31, wid = tid >> 5;
    int warp_m = wid & 1, warp_n = wid >> 1;
    int row0 = blockIdx.y * 128;
    int col0 = blockIdx.x * 128;

    float acc[4][4][4];
#pragma unroll
    for (int mt = 0; mt < 4; mt++)
#pragma unroll
        for (int nt = 0; nt < 4; nt++)
#pragma unroll
            for (int e = 0; e < 4; e++) acc[mt][nt][e] = 0.f;

    uint32_t sA_hi = smem_u32(&sA[0][0][0]);
    uint32_t sB_hi = smem_u32(&sB[0][0][0]);
    const uint32_t LO_OFF = 128*40*2;

    int a_row = lane & 15;
    int a_kb  = (lane >> 4) * 16;
    int b_row = (lane & 7) + ((lane >> 4) << 3);
    int b_kb  = ((lane >> 3) & 1) * 16;

    for (int k0 = 0; k0 < DMm; k0 += 32) {
#pragma unroll
        for (int i = 0; i < 2; i++) {
            int id = tid + i*256;
            int r = id >> 2, c = id & 3;
            size_t ga = (size_t)(row0 + r)*DMm + k0 + c*8;
            *(uint4*)&sA[0][r][c*8] = *(const uint4*)(g_Xhi + ga);
            *(uint4*)&sA[1][r][c*8] = *(const uint4*)(g_Xlo + ga);
            size_t gb = (size_t)(col0 + r)*DMm + k0 + c*8;
            *(uint4*)&sB[0][r][c*8] = *(const uint4*)(g_WThi + gb);
            *(uint4*)&sB[1][r][c*8] = *(const uint4*)(g_WTlo + gb);
        }
        __syncthreads();

#pragma unroll
        for (int kk = 0; kk < 2; kk++) {
            int kbyte = kk * 32;
            uint32_t ahi[4][4], alo[4][4];
            uint32_t bhi[4][2], blo[4][2];

#pragma unroll
            for (int mt = 0; mt < 4; mt++) {
                uint32_t ad = sA_hi + (uint32_t)(warp_m*64 + mt*16 + a_row)*80
                            + kbyte + a_kb;
                ldsm_x4(ahi[mt], ad);
                ldsm_x4(alo[mt], ad + LO_OFF);
            }
#pragma unroll
            for (int p = 0; p < 2; p++) {
                uint32_t bd = sB_hi + (uint32_t)(warp_n*32 + p*16 + b_row)*80
                            + kbyte + b_kb;
                uint32_t t[4];
                ldsm_x4(t, bd);
                bhi[2*p][0] = t[0]; bhi[2*p][1] = t[1];
                bhi[2*p+1][0] = t[2]; bhi[2*p+1][1] = t[3];
                ldsm_x4(t, bd + LO_OFF);
                blo[2*p][0] = t[0]; blo[2*p][1] = t[1];
                blo[2*p+1][0] = t[2]; blo[2*p+1][1] = t[3];
            }

#pragma unroll
            for (int mt = 0; mt < 4; mt++)
#pragma unroll
                for (int nt = 0; nt < 4; nt++) {
                    mma16816(acc[mt][nt], ahi[mt], bhi[nt]);
                    mma16816(acc[mt][nt], alo[mt], bhi[nt]);
                    mma16816(acc[mt][nt], ahi[mt], blo[nt]);
                }
        }
        __syncthreads();
    }

    int tg = lane >> 2, t4 = lane & 3;
#pragma unroll
    for (int mt = 0; mt < 4; mt++) {
        int rbase = row0 + warp_m*64 + mt*16 + tg;
#pragma unroll
        for (int nt = 0; nt < 4; nt++) {
            int col = col0 + warp_n*32 + nt*8 + t4*2;
            float b0 = bias[col], b1 = bias[col + 1];
#pragma unroll
            for (int half = 0; half < 2; half++) {
                int r = rbase + half*8;
                float2 val = make_float2(acc[mt][nt][half*2 + 0] + b0,
                                         acc[mt][nt][half*2 + 1] + b1);
                float* dst;
                if (mode == 3) {
                    dst = Yext + (size_t)r*DMm + col;
                } else {
                    int bi = r >> 11, s = r & (Ss - 1);
                    int h = col >> 6, d = col & 63;
                    float* Y = (mode == 0) ? g_QH : (mode == 1) ? g_KH : g_VH;
                    dst = Y + (((size_t)bi*Hh + h)*Ss + s)*Dd + d;
                }
                *(float2*)dst = val;
            }
        }
    }
}

// ---------------------------------------------------------------------------
// Fused HMMA flash attention.
// CTA = (128 q rows, h, b), 8 warps, warp = 16 q rows x full 128 keys.
// Per 128-key tile: S = QK^T (bf16x3), p~ = exp(S/8 + mask) via FFMA poly,
// attn <- p~ (unnormalized), rowsum += p~, O += P~ V (bf16x3, P from regs).
// Tail: normalize O -> g_CTX, rescale attn rows by 1/rowsum.
// ---------------------------------------------------------------------------
#define RS   144            // smem row stride in bytes (72 bf16)
#define SQHI 0
#define SQLO 18432
#define SKHI 36864
#define SKLO 55296
#define SVHI 73728
#define SVLO 92160
#define SMSK 110592         // 2048 floats
#define SROW 118784         // 128 floats
#define ATT_SMEM (118784 + 512)

__global__ __launch_bounds__(256, 1) void attn_mma_kernel(
    const float* __restrict__ mask, float* __restrict__ attn, int write_attn)
{
    extern __shared__ __align__(16) char sm[];
    uint32_t sb = smem_u32(sm);
    float* smask = (float*)(sm + SMSK);
    float* srow  = (float*)(sm + SROW);

    int tid  = threadIdx.x;
    int lane = tid & 31, w = tid >> 5;
    int tg = lane >> 2, t4 = lane & 3;
    int qt = blockIdx.x, h = blockIdx.y, b = blockIdx.z;

    const float* Qbase = g_QH + (((size_t)b*Hh + h)*Ss + (size_t)qt*128)*Dd;
    const float* Kbase = g_KH + (((size_t)b*Hh + h)*Ss)*Dd;
    const float* Vbase = g_VH + (((size_t)b*Hh + h)*Ss)*Dd;
    float* attn_base   = attn + (((size_t)b*Hh + h)*Ss + (size_t)qt*128)*Ss;

    // ---- load mask (2048 floats) + Q tile (fp32 -> bf16 hi/lo smem) ----
#pragma unroll
    for (int i = 0; i < 2; i++) {
        int f = tid + i*256;
        *(float4*)&smask[f*4] = *(const float4*)(mask + (size_t)b*Ss + f*4);
    }
#pragma unroll
    for (int i = 0; i < 8; i++) {
        int f = tid + i*256;              // 2048 float4
        int row = f >> 4, c = (f & 15) * 4;
        float4 v = *(const float4*)(Qbase + (size_t)row*Dd + c);
        uint2 hi, lo;
        split4(v, hi, lo);
        *(uint2*)(sm + SQHI + row*RS + c*2) = hi;
        *(uint2*)(sm + SQLO + row*RS + c*2) = lo;
    }
    __syncthreads();

    // ---- Q fragments in registers (warp rows w*16..w*16+15) ----
    int a_row = lane & 15;
    int a_kb  = (lane >> 4) * 16;
    uint32_t qhi[4][4], qlo[4][4];
#pragma unroll
    for (int ks = 0; ks < 4; ks++) {
        uint32_t ad = sb + SQHI + (uint32_t)(w*16 + a_row)*RS + ks*32 + a_kb;
        ldsm_x4(qhi[ks], ad);
        ldsm_x4(qlo[ks], ad + (SQLO - SQHI));
    }

    int b_row = (lane & 7) + ((lane >> 4) << 3);
    int b_kb  = ((lane >> 3) & 1) * 16;
    int v_koff = ((lane >> 3) & 1) * 8 + (lane & 7);
    int v_noff = (lane >> 4) * 8;

    float accO[8][4];
#pragma unroll
    for (int nt = 0; nt < 8; nt++)
#pragma unroll
        for (int e = 0; e < 4; e++) accO[nt][e] = 0.f;
    float rs0 = 0.f, rs1 = 0.f;

    for (int kt = 0; kt < Ss; kt += 128) {
        __syncthreads();
        // ---- load K,V fp32 -> bf16 hi/lo smem ----
#pragma unroll
        for (int i = 0; i < 8; i++) {
            int f = tid + i*256;
            int row = f >> 4, c = (f & 15) * 4;
            uint2 hi, lo;
            float4 kv = *(const float4*)(Kbase + (size_t)(kt + row)*Dd + c);
            split4(kv, hi, lo);
            *(uint2*)(sm + SKHI + row*RS + c*2) = hi;
            *(uint2*)(sm + SKLO + row*RS + c*2) = lo;
            float4 vv = *(const float4*)(Vbase + (size_t)(kt + row)*Dd + c);
            split4(vv, hi, lo);
            *(uint2*)(sm + SVHI + row*RS + c*2) = hi;
            *(uint2*)(sm + SVLO + row*RS + c*2) = lo;
        }
        __syncthreads();

        // ---- S = Q K^T ----
        float accS[16][4];
#pragma unroll
        for (int nt = 0; nt < 16; nt++)
#pragma unroll
            for (int e = 0; e < 4; e++) accS[nt][e] = 0.f;

#pragma unroll
        for (int ks = 0; ks < 4; ks++) {
#pragma unroll
            for (int nb = 0; nb < 8; nb++) {
                uint32_t th[4], tl[4];
                uint32_t ad = sb + SKHI + (uint32_t)(nb*16 + b_row)*RS + ks*32 + b_kb;
                ldsm_x4(th, ad);
                ldsm_x4(tl, ad + (SKLO - SKHI));
                int nt0 = nb*2;
                mma16816(accS[nt0],   qhi[ks], th);
                mma16816(accS[nt0],   qlo[ks], th);
                mma16816(accS[nt0],   qhi[ks], tl);
                mma16816(accS[nt0+1], qhi[ks], th+2);
                mma16816(accS[nt0+1], qlo[ks], th+2);
                mma16816(accS[nt0+1], qhi[ks], tl+2);
            }
        }

        // ---- exp, rowsum, attn write, pack P to bf16 hi/lo frags ----
        uint32_t php0[16], php1[16], plp0[16], plp1[16];
        int r0g = w*16 + tg;
#pragma unroll
        for (int j = 0; j < 16; j++) {
            int col = j*8 + t4*2;
            float2 mv = *(float2*)&smask[kt + col];
            float m0 = mv.x * -1e9f, m1 = mv.y * -1e9f;
            float p0 = exp_fast(fmaf(accS[j][0], 0.125f, m0));
            float p1 = exp_fast(fmaf(accS[j][1], 0.125f, m1));
            float p2 = exp_fast(fmaf(accS[j][2], 0.125f, m0));
            float p3 = exp_fast(fmaf(accS[j][3], 0.125f, m1));
            rs0 += p0 + p1;
            rs1 += p2 + p3;
            if (write_attn) {
                *(float2*)&attn_base[(size_t)r0g*Ss + kt + col]       = make_float2(p0, p1);
                *(float2*)&attn_base[(size_t)(r0g + 8)*Ss + kt + col] = make_float2(p2, p3);
            }
            __nv_bfloat16 h0 = __float2bfloat16_rn(p0);
            __nv_bfloat16 h1 = __float2bfloat16_rn(p1);
            __nv_bfloat16 h2 = __float2bfloat16_rn(p2);
            __nv_bfloat16 h3 = __float2bfloat16_rn(p3);
            php0[j] = (uint32_t)bfu(h0) | ((uint32_t)bfu(h1) << 16);
            php1[j] = (uint32_t)bfu(h2) | ((uint32_t)bfu(h3) << 16);
            __nv_bfloat16 l0 = __float2bfloat16_rn(p0 - __bfloat162float(h0));
            __nv_bfloat16 l1 = __float2bfloat16_rn(p1 - __bfloat162float(h1));
            __nv_bfloat16 l2 = __float2bfloat16_rn(p2 - __bfloat162float(h2));
            __nv_bfloat16 l3 = __float2bfloat16_rn(p3 - __bfloat162float(h3));
            plp0[j] = (uint32_t)bfu(l0) | ((uint32_t)bfu(l1) << 16);
            plp1[j] = (uint32_t)bfu(l2) | ((uint32_t)bfu(l3) << 16);
        }

        // ---- O += P~ @ V ----
#pragma unroll
        for (int ksv = 0; ksv < 8; ksv++) {
            uint32_t ah[4] = {php0[2*ksv], php1[2*ksv], php0[2*ksv+1], php1[2*ksv+1]};
            uint32_t al[4] = {plp0[2*ksv], plp1[2*ksv], plp0[2*ksv+1], plp1[2*ksv+1]};
#pragma unroll
            for (int vb = 0; vb < 4; vb++) {
                uint32_t th[4], tl[4];
                uint32_t ad = sb + SVHI + (uint32_t)(ksv*16 + v_koff)*RS
                            + (vb*16 + v_noff)*2;
                ldsm_x4_t(th, ad);
                ldsm_x4_t(tl, ad + (SVLO - SVHI));
                int nt0 = vb*2;
                mma16816(accO[nt0],   ah, th);
                mma16816(accO[nt0],   al, th);
                mma16816(accO[nt0],   ah, tl);
                mma16816(accO[nt0+1], ah, th+2);
                mma16816(accO[nt0+1], al, th+2);
                mma16816(accO[nt0+1], ah, tl+2);
            }
        }
    }

    // ---- rowsum reduce over quad lanes (same tg) ----
    rs0 += __shfl_xor_sync(0xffffffffu, rs0, 1);
    rs0 += __shfl_xor_sync(0xffffffffu, rs0, 2);
    rs1 += __shfl_xor_sync(0xffffffffu, rs1, 1);
    rs1 += __shfl_xor_sync(0xffffffffu, rs1, 2);
    if (t4 == 0) {
        srow[w*16 + tg]     = rs0;
        srow[w*16 + tg + 8] = rs1;
    }

    // ---- normalize O, write to g_CTX ----
    float ri0 = 1.0f / rs0, ri1 = 1.0f / rs1;
    int q0 = qt*128 + w*16 + tg;
#pragma unroll
    for (int nt = 0; nt < 8; nt++) {
        int d = nt*8 + t4*2;
        float* c0 = g_CTX + ((size_t)b*Ss + q0)*DMm + h*64 + d;
        *(float2*)c0 = make_float2(accO[nt][0]*ri0, accO[nt][1]*ri0);
        float* c1 = g_CTX + ((size_t)b*Ss + q0 + 8)*DMm + h*64 + d;
        *(float2*)c1 = make_float2(accO[nt][2]*ri1, accO[nt][3]*ri1);
    }
    __syncthreads();

    // ---- rescale attn rows by 1/rowsum (coalesced) ----
    if (write_attn) {
        float4* ab = (float4*)attn_base;
#pragma unroll 4
        for (int it = 0; it < 256; it++) {
            int f = it*256 + tid;          // 65536 float4 = 128 rows x 512
            int r = f >> 9;
            float rinv = 1.0f / srow[r];
            float4 vv = ab[f];
            vv.x *= rinv; vv.y *= rinv; vv.z *= rinv; vv.w *= rinv;
            ab[f] = vv;
        }
    }
}

// ---------------------------------------------------------------------------
// Launch
// ---------------------------------------------------------------------------
extern "C" void kernel_launch(void* const* d_in, const int* in_sizes, int n_in,
                              void* d_out, int out_size)
{
    const float* q    = (const float*)d_in[0];
    const float* k    = (const float*)d_in[1];
    const float* v    = (const float*)d_in[2];
    const float* mask = (const float*)d_in[3];
    const float* Wq   = (const float*)d_in[4];
    const float* bq   = (const float*)d_in[5];
    const float* Wk   = (const float*)d_in[6];
    const float* bk   = (const float*)d_in[7];
    const float* Wv   = (const float*)d_in[8];
    const float* bv   = (const float*)d_in[9];
    const float* Wo   = (const float*)d_in[10];
    const float* bo   = (const float*)d_in[11];

    float* out  = (float*)d_out;
    float* attn = out + (size_t)NTOK*DMm;

    long long need = (long long)NTOK*DMm + (long long)Bb*Hh*Ss*Ss;
    int write_attn = ((long long)out_size >= need) ? 1 : 0;

    cudaFuncSetAttribute(attn_mma_kernel,
                         cudaFuncAttributeMaxDynamicSharedMemorySize, ATT_SMEM);

    dim3 cgrid((NTOK*DMm)/(256*4));
    dim3 tgrid(DMm/32, DMm/32);
    dim3 tblk(32, 8);
    dim3 ggrid(DMm/128, NTOK/128);

    convert_split_kernel<<<cgrid, 256>>>(q, 0);
    transW_kernel<<<tgrid, tblk>>>(Wq);
    proj_mma_kernel<<<ggrid, 256>>>(bq, nullptr, 0);

    convert_split_kernel<<<cgrid, 256>>>(k, 0);
    transW_kernel<<<tgrid, tblk>>>(Wk);
    proj_mma_kernel<<<ggrid, 256>>>(bk, nullptr, 1);

    convert_split_kernel<<<cgrid, 256>>>(v, 0);
    transW_kernel<<<tgrid, tblk>>>(Wv);
    proj_mma_kernel<<<ggrid, 256>>>(bv, nullptr, 2);

    dim3 agrid(Ss/128, Hh, Bb);          // (16, 16, 2)
    attn_mma_kernel<<<agrid, 256, ATT_SMEM>>>(mask, attn, write_attn);

    convert_split_kernel<<<cgrid, 256>>>(nullptr, 1);
    transW_kernel<<<tgrid, tblk>>>(Wo);
    proj_mma_kernel<<<ggrid, 256>>>(bo, out, 3);
}

// round 6
// speedup vs baseline: 1.1734x; 1.1734x over previous
#include <cuda_runtime.h>
#include <cuda_bf16.h>
#include <cstdint>

#define DMm  1024
#define Hh   16
#define Dd   64
#define Bb   2
#define Ss   2048
#define NTOK (Bb*Ss)   // 4096

// ---------------------------------------------------------------------------
// Static device scratch
// ---------------------------------------------------------------------------
__device__ float g_QH [(size_t)Bb*Hh*Ss*Dd];
__device__ float g_KH [(size_t)Bb*Hh*Ss*Dd];
__device__ float g_VH [(size_t)Bb*Hh*Ss*Dd];
__device__ float g_CTX[(size_t)NTOK*DMm];
__device__ float g_SUM[(size_t)Bb*Hh*Ss];
__device__ __nv_bfloat16 g_Xhi [(size_t)NTOK*DMm];
__device__ __nv_bfloat16 g_Xlo [(size_t)NTOK*DMm];
__device__ __nv_bfloat16 g_WThi[(size_t)DMm*DMm];   // [N][K]
__device__ __nv_bfloat16 g_WTlo[(size_t)DMm*DMm];

// ---------------------------------------------------------------------------
// Warp MMA helpers (base ISA sm_80+, valid on compute_103)
// ---------------------------------------------------------------------------
__device__ __forceinline__ uint32_t smem_u32(const void* p) {
    uint32_t a;
    asm("{ .reg .u64 t; cvta.to.shared.u64 t, %1; cvt.u32.u64 %0, t; }"
        : "=r"(a) : "l"(p));
    return a;
}

__device__ __forceinline__ void ldsm_x4(uint32_t* r, uint32_t addr) {
    asm volatile("ldmatrix.sync.aligned.m8n8.x4.shared.b16 {%0,%1,%2,%3}, [%4];"
        : "=r"(r[0]), "=r"(r[1]), "=r"(r[2]), "=r"(r[3]) : "r"(addr));
}

__device__ __forceinline__ void ldsm_x4_t(uint32_t* r, uint32_t addr) {
    asm volatile("ldmatrix.sync.aligned.m8n8.x4.trans.shared.b16 {%0,%1,%2,%3}, [%4];"
        : "=r"(r[0]), "=r"(r[1]), "=r"(r[2]), "=r"(r[3]) : "r"(addr));
}

__device__ __forceinline__ void mma16816(float* c, const uint32_t* a, const uint32_t* b) {
    asm volatile(
        "mma.sync.aligned.m16n8k16.row.col.f32.bf16.bf16.f32 "
        "{%0,%1,%2,%3}, {%4,%5,%6,%7}, {%8,%9}, {%0,%1,%2,%3};"
        : "+f"(c[0]), "+f"(c[1]), "+f"(c[2]), "+f"(c[3])
        : "r"(a[0]), "r"(a[1]), "r"(a[2]), "r"(a[3]), "r"(b[0]), "r"(b[1]));
}

// FFMA-pipe exp: 2^(x*log2e), deg-6 poly on [-0.5,0.5], rel err ~1e-6
__device__ __forceinline__ float exp_fast(float x) {
    float t = x * 1.4426950408889634f;
    t = fminf(fmaxf(t, -126.f), 126.f);
    float fi = rintf(t);
    float f  = t - fi;
    int   ei = (int)fi;
    float p = 1.5403530e-4f;
    p = fmaf(p, f, 1.33335581e-3f);
    p = fmaf(p, f, 9.61812911e-3f);
    p = fmaf(p, f, 5.55041087e-2f);
    p = fmaf(p, f, 2.40226507e-1f);
    p = fmaf(p, f, 6.93147181e-1f);
    p = fmaf(p, f, 1.0f);
    return __int_as_float(__float_as_int(p) + (ei << 23));
}

__device__ __forceinline__ ushort bfu(__nv_bfloat16 h) {
    return __bfloat16_as_ushort(h);
}

__device__ __forceinline__ void split4(float4 v, uint2& hi, uint2& lo) {
    __nv_bfloat16 h0 = __float2bfloat16_rn(v.x);
    __nv_bfloat16 h1 = __float2bfloat16_rn(v.y);
    __nv_bfloat16 h2 = __float2bfloat16_rn(v.z);
    __nv_bfloat16 h3 = __float2bfloat16_rn(v.w);
    hi.x = (uint32_t)bfu(h0) | ((uint32_t)bfu(h1) << 16);
    hi.y = (uint32_t)bfu(h2) | ((uint32_t)bfu(h3) << 16);
    __nv_bfloat16 l0 = __float2bfloat16_rn(v.x - __bfloat162float(h0));
    __nv_bfloat16 l1 = __float2bfloat16_rn(v.y - __bfloat162float(h1));
    __nv_bfloat16 l2 = __float2bfloat16_rn(v.z - __bfloat162float(h2));
    __nv_bfloat16 l3 = __float2bfloat16_rn(v.w - __bfloat162float(h3));
    lo.x = (uint32_t)bfu(l0) | ((uint32_t)bfu(l1) << 16);
    lo.y = (uint32_t)bfu(l2) | ((uint32_t)bfu(l3) << 16);
}

// pack two floats into bf16 hi / lo halves of a uint32
__device__ __forceinline__ void pack2(float a, float b, uint32_t& hi, uint32_t& lo) {
    __nv_bfloat16 ha = __float2bfloat16_rn(a);
    __nv_bfloat16 hb = __float2bfloat16_rn(b);
    hi = (uint32_t)bfu(ha) | ((uint32_t)bfu(hb) << 16);
    __nv_bfloat16 la = __float2bfloat16_rn(a - __bfloat162float(ha));
    __nv_bfloat16 lb = __float2bfloat16_rn(b - __bfloat162float(hb));
    lo = (uint32_t)bfu(la) | ((uint32_t)bfu(lb) << 16);
}

// ---------------------------------------------------------------------------
// fp32 -> bf16 hi/lo split of X (or g_CTX)
// ---------------------------------------------------------------------------
__global__ __launch_bounds__(256) void convert_split_kernel(
    const float* __restrict__ Xext, int use_ctx)
{
    const float* X = use_ctx ? g_CTX : Xext;
    size_t i = ((size_t)blockIdx.x * 256 + threadIdx.x) * 4;
    float4 v = *(const float4*)(X + i);
    uint2 hi, lo;
    split4(v, hi, lo);
    *(uint2*)(g_Xhi + i) = hi;
    *(uint2*)(g_Xlo + i) = lo;
}

// ---------------------------------------------------------------------------
// W [K][N] fp32 -> WT [N][K] bf16 hi/lo
// ---------------------------------------------------------------------------
__global__ __launch_bounds__(256) void transW_kernel(const float* __restrict__ W)
{
    __shared__ float t[32][33];
    int nx = blockIdx.x * 32, ky = blockIdx.y * 32;
    int txx = threadIdx.x, tyy = threadIdx.y;   // block (32, 8)
#pragma unroll
    for (int j = 0; j < 4; j++)
        t[tyy + j*8][txx] = W[(size_t)(ky + tyy + j*8)*DMm + nx + txx];
    __syncthreads();
#pragma unroll
    for (int j = 0; j < 4; j++) {
        float val = t[txx][tyy + j*8];
        __nv_bfloat16 h = __float2bfloat16_rn(val);
        size_t o = (size_t)(nx + tyy + j*8)*DMm + ky + txx;
        g_WThi[o] = h;
        g_WTlo[o] = __float2bfloat16_rn(val - __bfloat162float(h));
    }
}

// ---------------------------------------------------------------------------
// HMMA projection GEMM (proven R4): D = X @ W + bias, bf16x3 split.
// ---------------------------------------------------------------------------
__global__ __launch_bounds__(256, 1) void proj_mma_kernel(
    const float* __restrict__ bias, float* __restrict__ Yext, int mode)
{
    __shared__ __align__(16) __nv_bfloat16 sA[2][128][40];
    __shared__ __align__(16) __nv_bfloat16 sB[2][128][40];

    int tid  = threadIdx.x;
    int lane = tid & 31, wid = tid >> 5;
    int warp_m = wid & 1, warp_n = wid >> 1;
    int row0 = blockIdx.y * 128;
    int col0 = blockIdx.x * 128;

    float acc[4][4][4];
#pragma unroll
    for (int mt = 0; mt < 4; mt++)
#pragma unroll
        for (int nt = 0; nt < 4; nt++)
#pragma unroll
            for (int e = 0; e < 4; e++) acc[mt][nt][e] = 0.f;

    uint32_t sA_hi = smem_u32(&sA[0][0][0]);
    uint32_t sB_hi = smem_u32(&sB[0][0][0]);
    const uint32_t LO_OFF = 128*40*2;

    int a_row = lane & 15;
    int a_kb  = (lane >> 4) * 16;
    int b_row = (lane & 7) + ((lane >> 4) << 3);
    int b_kb  = ((lane >> 3) & 1) * 16;

    for (int k0 = 0; k0 < DMm; k0 += 32) {
#pragma unroll
        for (int i = 0; i < 2; i++) {
            int id = tid + i*256;
            int r = id >> 2, c = id & 3;
            size_t ga = (size_t)(row0 + r)*DMm + k0 + c*8;
            *(uint4*)&sA[0][r][c*8] = *(const uint4*)(g_Xhi + ga);
            *(uint4*)&sA[1][r][c*8] = *(const uint4*)(g_Xlo + ga);
            size_t gb = (size_t)(col0 + r)*DMm + k0 + c*8;
            *(uint4*)&sB[0][r][c*8] = *(const uint4*)(g_WThi + gb);
            *(uint4*)&sB[1][r][c*8] = *(const uint4*)(g_WTlo + gb);
        }
        __syncthreads();

#pragma unroll
        for (int kk = 0; kk < 2; kk++) {
            int kbyte = kk * 32;
            uint32_t ahi[4][4], alo[4][4];
            uint32_t bhi[4][2], blo[4][2];

#pragma unroll
            for (int mt = 0; mt < 4; mt++) {
                uint32_t ad = sA_hi + (uint32_t)(warp_m*64 + mt*16 + a_row)*80
                            + kbyte + a_kb;
                ldsm_x4(ahi[mt], ad);
                ldsm_x4(alo[mt], ad + LO_OFF);
            }
#pragma unroll
            for (int p = 0; p < 2; p++) {
                uint32_t bd = sB_hi + (uint32_t)(warp_n*32 + p*16 + b_row)*80
                            + kbyte + b_kb;
                uint32_t t[4];
                ldsm_x4(t, bd);
                bhi[2*p][0] = t[0]; bhi[2*p][1] = t[1];
                bhi[2*p+1][0] = t[2]; bhi[2*p+1][1] = t[3];
                ldsm_x4(t, bd + LO_OFF);
                blo[2*p][0] = t[0]; blo[2*p][1] = t[1];
                blo[2*p+1][0] = t[2]; blo[2*p+1][1] = t[3];
            }

#pragma unroll
            for (int mt = 0; mt < 4; mt++)
#pragma unroll
                for (int nt = 0; nt < 4; nt++) {
                    mma16816(acc[mt][nt], ahi[mt], bhi[nt]);
                    mma16816(acc[mt][nt], alo[mt], bhi[nt]);
                    mma16816(acc[mt][nt], ahi[mt], blo[nt]);
                }
        }
        __syncthreads();
    }

    int tg = lane >> 2, t4 = lane & 3;
#pragma unroll
    for (int mt = 0; mt < 4; mt++) {
        int rbase = row0 + warp_m*64 + mt*16 + tg;
#pragma unroll
        for (int nt = 0; nt < 4; nt++) {
            int col = col0 + warp_n*32 + nt*8 + t4*2;
            float b0 = bias[col], b1 = bias[col + 1];
#pragma unroll
            for (int half = 0; half < 2; half++) {
                int r = rbase + half*8;
                float2 val = make_float2(acc[mt][nt][half*2 + 0] + b0,
                                         acc[mt][nt][half*2 + 1] + b1);
                float* dst;
                if (mode == 3) {
                    dst = Yext + (size_t)r*DMm + col;
                } else {
                    int bi = r >> 11, s = r & (Ss - 1);
                    int h = col >> 6, d = col & 63;
                    float* Y = (mode == 0) ? g_QH : (mode == 1) ? g_KH : g_VH;
                    dst = Y + (((size_t)bi*Hh + h)*Ss + s)*Dd + d;
                }
                *(float2*)dst = val;
            }
        }
    }
}

// ---------------------------------------------------------------------------
// Attention smem layout (shared by both passes).  RS = 144B row stride
// (36 words, 36 mod 32 = 4 -> ldmatrix conflict-free).
// ---------------------------------------------------------------------------
#define RS    144
#define SQHI  0
#define SQLO  18432
#define SKHI  36864
#define SKLO  46080
#define SVHI  55296
#define SVLO  64512
#define SMSK1 55296                     // pass1: mask right after K
#define SMSK2 73728                     // pass2: after V
#define SUM_SMEM (SMSK1 + 8192)        // 63488
#define PV_SMEM  (SMSK2 + 8192)        // 81920

// ---------------------------------------------------------------------------
// Pass 1: rowsums of exp(QK^T/8 + mask).  HMMA bf16x3 + FFMA exp.
// CTA = 128 q rows; 8 warps x 16 q rows; key tiles of 64.
// ---------------------------------------------------------------------------
__global__ __launch_bounds__(256, 1) void attn_sum_mma(const float* __restrict__ mask)
{
    extern __shared__ __align__(16) char sm[];
    uint32_t sb = smem_u32(sm);
    float* smask = (float*)(sm + SMSK1);

    int tid  = threadIdx.x;
    int lane = tid & 31, w = tid >> 5;
    int tg = lane >> 2, t4 = lane & 3;
    int qt = blockIdx.x, h = blockIdx.y, b = blockIdx.z;

    const float* Qbase = g_QH + (((size_t)b*Hh + h)*Ss + (size_t)qt*128)*Dd;
    const float* Kbase = g_KH + (((size_t)b*Hh + h)*Ss)*Dd;

#pragma unroll
    for (int i = 0; i < 2; i++) {
        int f = tid + i*256;
        *(float4*)&smask[f*4] = *(const float4*)(mask + (size_t)b*Ss + f*4);
    }
#pragma unroll
    for (int i = 0; i < 8; i++) {
        int f = tid + i*256;
        int row = f >> 4, c = (f & 15) * 4;
        float4 v = *(const float4*)(Qbase + (size_t)row*Dd + c);
        uint2 hi, lo;
        split4(v, hi, lo);
        *(uint2*)(sm + SQHI + row*RS + c*2) = hi;
        *(uint2*)(sm + SQLO + row*RS + c*2) = lo;
    }
    __syncthreads();

    int a_row = lane & 15;
    int a_kb  = (lane >> 4) * 16;
    uint32_t qhi[4][4], qlo[4][4];
#pragma unroll
    for (int ks = 0; ks < 4; ks++) {
        uint32_t ad = sb + SQHI + (uint32_t)(w*16 + a_row)*RS + ks*32 + a_kb;
        ldsm_x4(qhi[ks], ad);
        ldsm_x4(qlo[ks], ad + (SQLO - SQHI));
    }

    int b_row = (lane & 7) + ((lane >> 4) << 3);
    int b_kb  = ((lane >> 3) & 1) * 16;

    float rs0 = 0.f, rs1 = 0.f;

    for (int kt = 0; kt < Ss; kt += 64) {
        __syncthreads();
#pragma unroll
        for (int i = 0; i < 4; i++) {
            int f = tid + i*256;           // 1024 float4 = 64 rows x 16
            int row = f >> 4, c = (f & 15) * 4;
            float4 kv = *(const float4*)(Kbase + (size_t)(kt + row)*Dd + c);
            uint2 hi, lo;
            split4(kv, hi, lo);
            *(uint2*)(sm + SKHI + row*RS + c*2) = hi;
            *(uint2*)(sm + SKLO + row*RS + c*2) = lo;
        }
        __syncthreads();

        float accS[8][4];
#pragma unroll
        for (int j = 0; j < 8; j++)
#pragma unroll
            for (int e = 0; e < 4; e++) accS[j][e] = 0.f;

#pragma unroll
        for (int ks = 0; ks < 4; ks++) {
#pragma unroll
            for (int nb = 0; nb < 4; nb++) {
                uint32_t th[4], tl[4];
                uint32_t ad = sb + SKHI + (uint32_t)(nb*16 + b_row)*RS + ks*32 + b_kb;
                ldsm_x4(th, ad);
                ldsm_x4(tl, ad + (SKLO - SKHI));
                int j0 = nb*2;
                mma16816(accS[j0],   qhi[ks], th);
                mma16816(accS[j0],   qlo[ks], th);
                mma16816(accS[j0],   qhi[ks], tl);
                mma16816(accS[j0+1], qhi[ks], th+2);
                mma16816(accS[j0+1], qlo[ks], th+2);
                mma16816(accS[j0+1], qhi[ks], tl+2);
            }
        }

#pragma unroll
        for (int j = 0; j < 8; j++) {
            int col = j*8 + t4*2;
            float2 mv = *(float2*)&smask[kt + col];
            float m0 = mv.x * -1e9f, m1 = mv.y * -1e9f;
            rs0 += exp_fast(fmaf(accS[j][0], 0.125f, m0))
                 + exp_fast(fmaf(accS[j][1], 0.125f, m1));
            rs1 += exp_fast(fmaf(accS[j][2], 0.125f, m0))
                 + exp_fast(fmaf(accS[j][3], 0.125f, m1));
        }
    }

    rs0 += __shfl_xor_sync(0xffffffffu, rs0, 1);
    rs0 += __shfl_xor_sync(0xffffffffu, rs0, 2);
    rs1 += __shfl_xor_sync(0xffffffffu, rs1, 1);
    rs1 += __shfl_xor_sync(0xffffffffu, rs1, 2);
    if (t4 == 0) {
        size_t base = ((size_t)b*Hh + h)*Ss + (size_t)qt*128;
        g_SUM[base + w*16 + tg]     = rs0;
        g_SUM[base + w*16 + tg + 8] = rs1;
    }
}

// ---------------------------------------------------------------------------
// Pass 2: recompute QK, p = exp(...)/rowsum, write attn (once, normalized),
// O += P @ V (bf16x3, P packed in regs), write O to g_CTX.
// ---------------------------------------------------------------------------
__global__ __launch_bounds__(256, 1) void attn_pv_mma(
    const float* __restrict__ mask, float* __restrict__ attn, int write_attn)
{
    extern __shared__ __align__(16) char sm[];
    uint32_t sb = smem_u32(sm);
    float* smask = (float*)(sm + SMSK2);

    int tid  = threadIdx.x;
    int lane = tid & 31, w = tid >> 5;
    int tg = lane >> 2, t4 = lane & 3;
    int qt = blockIdx.x, h = blockIdx.y, b = blockIdx.z;

    const float* Qbase = g_QH + (((size_t)b*Hh + h)*Ss + (size_t)qt*128)*Dd;
    const float* Kbase = g_KH + (((size_t)b*Hh + h)*Ss)*Dd;
    const float* Vbase = g_VH + (((size_t)b*Hh + h)*Ss)*Dd;
    float* attn_base   = attn + (((size_t)b*Hh + h)*Ss + (size_t)qt*128)*Ss;

#pragma unroll
    for (int i = 0; i < 2; i++) {
        int f = tid + i*256;
        *(float4*)&smask[f*4] = *(const float4*)(mask + (size_t)b*Ss + f*4);
    }
#pragma unroll
    for (int i = 0; i < 8; i++) {
        int f = tid + i*256;
        int row = f >> 4, c = (f & 15) * 4;
        float4 v = *(const float4*)(Qbase + (size_t)row*Dd + c);
        uint2 hi, lo;
        split4(v, hi, lo);
        *(uint2*)(sm + SQHI + row*RS + c*2) = hi;
        *(uint2*)(sm + SQLO + row*RS + c*2) = lo;
    }
    __syncthreads();

    int a_row = lane & 15;
    int a_kb  = (lane >> 4) * 16;
    uint32_t qhi[4][4], qlo[4][4];
#pragma unroll
    for (int ks = 0; ks < 4; ks++) {
        uint32_t ad = sb + SQHI + (uint32_t)(w*16 + a_row)*RS + ks*32 + a_kb;
        ldsm_x4(qhi[ks], ad);
        ldsm_x4(qlo[ks], ad + (SQLO - SQHI));
    }

    int b_row = (lane & 7) + ((lane >> 4) << 3);
    int b_kb  = ((lane >> 3) & 1) * 16;
    int v_koff = ((lane >> 3) & 1) * 8 + (lane & 7);
    int v_noff = (lane >> 4) * 8;

    {
        size_t base = ((size_t)b*Hh + h)*Ss + (size_t)qt*128;
        // rinv kept in two regs below
        float rinv0 = 1.0f / g_SUM[base + w*16 + tg];
        float rinv1 = 1.0f / g_SUM[base + w*16 + tg + 8];

        float accO[8][4];
#pragma unroll
        for (int nt = 0; nt < 8; nt++)
#pragma unroll
            for (int e = 0; e < 4; e++) accO[nt][e] = 0.f;

        int r0g = w*16 + tg;

        for (int kt = 0; kt < Ss; kt += 64) {
            __syncthreads();
#pragma unroll
            for (int i = 0; i < 4; i++) {
                int f = tid + i*256;
                int row = f >> 4, c = (f & 15) * 4;
                uint2 hi, lo;
                float4 kv = *(const float4*)(Kbase + (size_t)(kt + row)*Dd + c);
                split4(kv, hi, lo);
                *(uint2*)(sm + SKHI + row*RS + c*2) = hi;
                *(uint2*)(sm + SKLO + row*RS + c*2) = lo;
                float4 vv = *(const float4*)(Vbase + (size_t)(kt + row)*Dd + c);
                split4(vv, hi, lo);
                *(uint2*)(sm + SVHI + row*RS + c*2) = hi;
                *(uint2*)(sm + SVLO + row*RS + c*2) = lo;
            }
            __syncthreads();

            float accS[8][4];
#pragma unroll
            for (int j = 0; j < 8; j++)
#pragma unroll
                for (int e = 0; e < 4; e++) accS[j][e] = 0.f;

#pragma unroll
            for (int ks = 0; ks < 4; ks++) {
#pragma unroll
                for (int nb = 0; nb < 4; nb++) {
                    uint32_t th[4], tl[4];
                    uint32_t ad = sb + SKHI + (uint32_t)(nb*16 + b_row)*RS + ks*32 + b_kb;
                    ldsm_x4(th, ad);
                    ldsm_x4(tl, ad + (SKLO - SKHI));
                    int j0 = nb*2;
                    mma16816(accS[j0],   qhi[ks], th);
                    mma16816(accS[j0],   qlo[ks], th);
                    mma16816(accS[j0],   qhi[ks], tl);
                    mma16816(accS[j0+1], qhi[ks], th+2);
                    mma16816(accS[j0+1], qlo[ks], th+2);
                    mma16816(accS[j0+1], qhi[ks], tl+2);
                }
            }

            // exp -> normalize -> write attn -> pack P (hi/lo)
            uint32_t php0[8], php1[8], plp0[8], plp1[8];
#pragma unroll
            for (int j = 0; j < 8; j++) {
                int col = j*8 + t4*2;
                float2 mv = *(float2*)&smask[kt + col];
                float m0 = mv.x * -1e9f, m1 = mv.y * -1e9f;
                float p0 = exp_fast(fmaf(accS[j][0], 0.125f, m0)) * rinv0;
                float p1 = exp_fast(fmaf(accS[j][1], 0.125f, m1)) * rinv0;
                float p2 = exp_fast(fmaf(accS[j][2], 0.125f, m0)) * rinv1;
                float p3 = exp_fast(fmaf(accS[j][3], 0.125f, m1)) * rinv1;
                if (write_attn) {
                    *(float2*)&attn_base[(size_t)r0g*Ss + kt + col]       = make_float2(p0, p1);
                    *(float2*)&attn_base[(size_t)(r0g + 8)*Ss + kt + col] = make_float2(p2, p3);
                }
                pack2(p0, p1, php0[j], plp0[j]);
                pack2(p2, p3, php1[j], plp1[j]);
            }

            // O += P @ V
#pragma unroll
            for (int ksv = 0; ksv < 4; ksv++) {
                uint32_t ah[4] = {php0[2*ksv], php1[2*ksv], php0[2*ksv+1], php1[2*ksv+1]};
                uint32_t al[4] = {plp0[2*ksv], plp1[2*ksv], plp0[2*ksv+1], plp1[2*ksv+1]};
#pragma unroll
                for (int vb = 0; vb < 4; vb++) {
                    uint32_t th[4], tl[4];
                    uint32_t ad = sb + SVHI + (uint32_t)(ksv*16 + v_koff)*RS
                                + (vb*16 + v_noff)*2;
                    ldsm_x4_t(th, ad);
                    ldsm_x4_t(tl, ad + (SVLO - SVHI));
                    int nt0 = vb*2;
                    mma16816(accO[nt0],   ah, th);
                    mma16816(accO[nt0],   al, th);
                    mma16816(accO[nt0],   ah, tl);
                    mma16816(accO[nt0+1], ah, th+2);
                    mma16816(accO[nt0+1], al, th+2);
                    mma16816(accO[nt0+1], ah, tl+2);
                }
            }
        }

        // O already normalized (P was) -> write to g_CTX
        int q0 = qt*128 + w*16 + tg;
#pragma unroll
        for (int nt = 0; nt < 8; nt++) {
            int d = nt*8 + t4*2;
            float* c0 = g_CTX + ((size_t)b*Ss + q0)*DMm + h*64 + d;
            *(float2*)c0 = make_float2(accO[nt][0], accO[nt][1]);
            float* c1 = g_CTX + ((size_t)b*Ss + q0 + 8)*DMm + h*64 + d;
            *(float2*)c1 = make_float2(accO[nt][2], accO[nt][3]);
        }
    }
}

// ---------------------------------------------------------------------------
// Launch
// ---------------------------------------------------------------------------
extern "C" void kernel_launch(void* const* d_in, const int* in_sizes, int n_in,
                              void* d_out, int out_size)
{
    const float* q    = (const float*)d_in[0];
    const float* k    = (const float*)d_in[1];
    const float* v    = (const float*)d_in[2];
    const float* mask = (const float*)d_in[3];
    const float* Wq   = (const float*)d_in[4];
    const float* bq   = (const float*)d_in[5];
    const float* Wk   = (const float*)d_in[6];
    const float* bk   = (const float*)d_in[7];
    const float* Wv   = (const float*)d_in[8];
    const float* bv   = (const float*)d_in[9];
    const float* Wo   = (const float*)d_in[10];
    const float* bo   = (const float*)d_in[11];

    float* out  = (float*)d_out;
    float* attn = out + (size_t)NTOK*DMm;

    long long need = (long long)NTOK*DMm + (long long)Bb*Hh*Ss*Ss;
    int write_attn = ((long long)out_size >= need) ? 1 : 0;

    cudaFuncSetAttribute(attn_sum_mma,
                         cudaFuncAttributeMaxDynamicSharedMemorySize, SUM_SMEM);
    cudaFuncSetAttribute(attn_pv_mma,
                         cudaFuncAttributeMaxDynamicSharedMemorySize, PV_SMEM);

    dim3 cgrid((NTOK*DMm)/(256*4));
    dim3 tgrid(DMm/32, DMm/32);
    dim3 tblk(32, 8);
    dim3 ggrid(DMm/128, NTOK/128);

    convert_split_kernel<<<cgrid, 256>>>(q, 0);
    transW_kernel<<<tgrid, tblk>>>(Wq);
    proj_mma_kernel<<<ggrid, 256>>>(bq, nullptr, 0);

    convert_split_kernel<<<cgrid, 256>>>(k, 0);
    transW_kernel<<<tgrid, tblk>>>(Wk);
    proj_mma_kernel<<<ggrid, 256>>>(bk, nullptr, 1);

    convert_split_kernel<<<cgrid, 256>>>(v, 0);
    transW_kernel<<<tgrid, tblk>>>(Wv);
    proj_mma_kernel<<<ggrid, 256>>>(bv, nullptr, 2);

    dim3 agrid(Ss/128, Hh, Bb);          // (16, 16, 2)
    attn_sum_mma<<<agrid, 256, SUM_SMEM>>>(mask);
    attn_pv_mma<<<agrid, 256, PV_SMEM>>>(mask, attn, write_attn);

    convert_split_kernel<<<cgrid, 256>>>(nullptr, 1);
    transW_kernel<<<tgrid, tblk>>>(Wo);
    proj_mma_kernel<<<ggrid, 256>>>(bo, out, 3);
}

// round 7
// speedup vs baseline: 1.9548x; 1.6659x over previous
#include <cuda_runtime.h>
#include <cuda_bf16.h>
#include <cstdint>

#define DMm  1024
#define Hh   16
#define Dd   64
#define Bb   2
#define Ss   2048
#define NTOK (Bb*Ss)   // 4096

// ---------------------------------------------------------------------------
// Static device scratch
// ---------------------------------------------------------------------------
__device__ float g_CTX[(size_t)NTOK*DMm];
__device__ float g_SUM[(size_t)Bb*Hh*Ss];
__device__ __nv_bfloat16 g_Xhi [(size_t)NTOK*DMm];
__device__ __nv_bfloat16 g_Xlo [(size_t)NTOK*DMm];
__device__ __nv_bfloat16 g_WThi[(size_t)DMm*DMm];   // [N][K]
__device__ __nv_bfloat16 g_WTlo[(size_t)DMm*DMm];
// head-split Q/K/V, bf16 hi/lo  [b][h][s][d]
__device__ __nv_bfloat16 g_Qhi[(size_t)Bb*Hh*Ss*Dd];
__device__ __nv_bfloat16 g_Qlo[(size_t)Bb*Hh*Ss*Dd];
__device__ __nv_bfloat16 g_Khi[(size_t)Bb*Hh*Ss*Dd];
__device__ __nv_bfloat16 g_Klo[(size_t)Bb*Hh*Ss*Dd];
__device__ __nv_bfloat16 g_Vhi[(size_t)Bb*Hh*Ss*Dd];
__device__ __nv_bfloat16 g_Vlo[(size_t)Bb*Hh*Ss*Dd];

// ---------------------------------------------------------------------------
// Warp MMA helpers (base ISA sm_80+, valid on compute_103)
// ---------------------------------------------------------------------------
__device__ __forceinline__ uint32_t smem_u32(const void* p) {
    uint32_t a;
    asm("{ .reg .u64 t; cvta.to.shared.u64 t, %1; cvt.u32.u64 %0, t; }"
        : "=r"(a) : "l"(p));
    return a;
}

__device__ __forceinline__ void ldsm_x4(uint32_t* r, uint32_t addr) {
    asm volatile("ldmatrix.sync.aligned.m8n8.x4.shared.b16 {%0,%1,%2,%3}, [%4];"
        : "=r"(r[0]), "=r"(r[1]), "=r"(r[2]), "=r"(r[3]) : "r"(addr));
}

__device__ __forceinline__ void ldsm_x4_t(uint32_t* r, uint32_t addr) {
    asm volatile("ldmatrix.sync.aligned.m8n8.x4.trans.shared.b16 {%0,%1,%2,%3}, [%4];"
        : "=r"(r[0]), "=r"(r[1]), "=r"(r[2]), "=r"(r[3]) : "r"(addr));
}

__device__ __forceinline__ void mma16816(float* c, const uint32_t* a, const uint32_t* b) {
    asm volatile(
        "mma.sync.aligned.m16n8k16.row.col.f32.bf16.bf16.f32 "
        "{%0,%1,%2,%3}, {%4,%5,%6,%7}, {%8,%9}, {%0,%1,%2,%3};"
        : "+f"(c[0]), "+f"(c[1]), "+f"(c[2]), "+f"(c[3])
        : "r"(a[0]), "r"(a[1]), "r"(a[2]), "r"(a[3]), "r"(b[0]), "r"(b[1]));
}

// FFMA-pipe exp: 2^(x*log2e), deg-6 poly on [-0.5,0.5], rel err ~1e-6
__device__ __forceinline__ float exp_fast(float x) {
    float t = x * 1.4426950408889634f;
    t = fminf(fmaxf(t, -126.f), 126.f);
    float fi = rintf(t);
    float f  = t - fi;
    int   ei = (int)fi;
    float p = 1.5403530e-4f;
    p = fmaf(p, f, 1.33335581e-3f);
    p = fmaf(p, f, 9.61812911e-3f);
    p = fmaf(p, f, 5.55041087e-2f);
    p = fmaf(p, f, 2.40226507e-1f);
    p = fmaf(p, f, 6.93147181e-1f);
    p = fmaf(p, f, 1.0f);
    return __int_as_float(__float_as_int(p) + (ei << 23));
}

__device__ __forceinline__ ushort bfu(__nv_bfloat16 h) {
    return __bfloat16_as_ushort(h);
}

__device__ __forceinline__ void split4(float4 v, uint2& hi, uint2& lo) {
    __nv_bfloat16 h0 = __float2bfloat16_rn(v.x);
    __nv_bfloat16 h1 = __float2bfloat16_rn(v.y);
    __nv_bfloat16 h2 = __float2bfloat16_rn(v.z);
    __nv_bfloat16 h3 = __float2bfloat16_rn(v.w);
    hi.x = (uint32_t)bfu(h0) | ((uint32_t)bfu(h1) << 16);
    hi.y = (uint32_t)bfu(h2) | ((uint32_t)bfu(h3) << 16);
    __nv_bfloat16 l0 = __float2bfloat16_rn(v.x - __bfloat162float(h0));
    __nv_bfloat16 l1 = __float2bfloat16_rn(v.y - __bfloat162float(h1));
    __nv_bfloat16 l2 = __float2bfloat16_rn(v.z - __bfloat162float(h2));
    __nv_bfloat16 l3 = __float2bfloat16_rn(v.w - __bfloat162float(h3));
    lo.x = (uint32_t)bfu(l0) | ((uint32_t)bfu(l1) << 16);
    lo.y = (uint32_t)bfu(l2) | ((uint32_t)bfu(l3) << 16);
}

__device__ __forceinline__ void pack2(float a, float b, uint32_t& hi, uint32_t& lo) {
    __nv_bfloat16 ha = __float2bfloat16_rn(a);
    __nv_bfloat16 hb = __float2bfloat16_rn(b);
    hi = (uint32_t)bfu(ha) | ((uint32_t)bfu(hb) << 16);
    __nv_bfloat16 la = __float2bfloat16_rn(a - __bfloat162float(ha));
    __nv_bfloat16 lb = __float2bfloat16_rn(b - __bfloat162float(hb));
    lo = (uint32_t)bfu(la) | ((uint32_t)bfu(lb) << 16);
}

// ---------------------------------------------------------------------------
// fp32 -> bf16 hi/lo split of X (or g_CTX)
// ---------------------------------------------------------------------------
__global__ __launch_bounds__(256) void convert_split_kernel(
    const float* __restrict__ Xext, int use_ctx)
{
    const float* X = use_ctx ? g_CTX : Xext;
    size_t i = ((size_t)blockIdx.x * 256 + threadIdx.x) * 4;
    float4 v = *(const float4*)(X + i);
    uint2 hi, lo;
    split4(v, hi, lo);
    *(uint2*)(g_Xhi + i) = hi;
    *(uint2*)(g_Xlo + i) = lo;
}

// ---------------------------------------------------------------------------
// W [K][N] fp32 -> WT [N][K] bf16 hi/lo
// ---------------------------------------------------------------------------
__global__ __launch_bounds__(256) void transW_kernel(const float* __restrict__ W)
{
    __shared__ float t[32][33];
    int nx = blockIdx.x * 32, ky = blockIdx.y * 32;
    int txx = threadIdx.x, tyy = threadIdx.y;   // block (32, 8)
#pragma unroll
    for (int j = 0; j < 4; j++)
        t[tyy + j*8][txx] = W[(size_t)(ky + tyy + j*8)*DMm + nx + txx];
    __syncthreads();
#pragma unroll
    for (int j = 0; j < 4; j++) {
        float val = t[txx][tyy + j*8];
        __nv_bfloat16 h = __float2bfloat16_rn(val);
        size_t o = (size_t)(nx + tyy + j*8)*DMm + ky + txx;
        g_WThi[o] = h;
        g_WTlo[o] = __float2bfloat16_rn(val - __bfloat162float(h));
    }
}

// ---------------------------------------------------------------------------
// HMMA projection GEMM: D = X @ W + bias, bf16x3 split.
// modes 0/1/2: head-split epilogue -> bf16 hi/lo Q/K/V; mode 3: fp32 flat.
// ---------------------------------------------------------------------------
__global__ __launch_bounds__(256, 1) void proj_mma_kernel(
    const float* __restrict__ bias, float* __restrict__ Yext, int mode)
{
    __shared__ __align__(16) __nv_bfloat16 sA[2][128][40];
    __shared__ __align__(16) __nv_bfloat16 sB[2][128][40];

    int tid  = threadIdx.x;
    int lane = tid & 31, wid = tid >> 5;
    int warp_m = wid & 1, warp_n = wid >> 1;
    int row0 = blockIdx.y * 128;
    int col0 = blockIdx.x * 128;

    float acc[4][4][4];
#pragma unroll
    for (int mt = 0; mt < 4; mt++)
#pragma unroll
        for (int nt = 0; nt < 4; nt++)
#pragma unroll
            for (int e = 0; e < 4; e++) acc[mt][nt][e] = 0.f;

    uint32_t sA_hi = smem_u32(&sA[0][0][0]);
    uint32_t sB_hi = smem_u32(&sB[0][0][0]);
    const uint32_t LO_OFF = 128*40*2;

    int a_row = lane & 15;
    int a_kb  = (lane >> 4) * 16;
    int b_row = (lane & 7) + ((lane >> 4) << 3);
    int b_kb  = ((lane >> 3) & 1) * 16;

    for (int k0 = 0; k0 < DMm; k0 += 32) {
#pragma unroll
        for (int i = 0; i < 2; i++) {
            int id = tid + i*256;
            int r = id >> 2, c = id & 3;
            size_t ga = (size_t)(row0 + r)*DMm + k0 + c*8;
            *(uint4*)&sA[0][r][c*8] = *(const uint4*)(g_Xhi + ga);
            *(uint4*)&sA[1][r][c*8] = *(const uint4*)(g_Xlo + ga);
            size_t gb = (size_t)(col0 + r)*DMm + k0 + c*8;
            *(uint4*)&sB[0][r][c*8] = *(const uint4*)(g_WThi + gb);
            *(uint4*)&sB[1][r][c*8] = *(const uint4*)(g_WTlo + gb);
        }
        __syncthreads();

#pragma unroll
        for (int kk = 0; kk < 2; kk++) {
            int kbyte = kk * 32;
            uint32_t ahi[4][4], alo[4][4];
            uint32_t bhi[4][2], blo[4][2];

#pragma unroll
            for (int mt = 0; mt < 4; mt++) {
                uint32_t ad = sA_hi + (uint32_t)(warp_m*64 + mt*16 + a_row)*80
                            + kbyte + a_kb;
                ldsm_x4(ahi[mt], ad);
                ldsm_x4(alo[mt], ad + LO_OFF);
            }
#pragma unroll
            for (int p = 0; p < 2; p++) {
                uint32_t bd = sB_hi + (uint32_t)(warp_n*32 + p*16 + b_row)*80
                            + kbyte + b_kb;
                uint32_t t[4];
                ldsm_x4(t, bd);
                bhi[2*p][0] = t[0]; bhi[2*p][1] = t[1];
                bhi[2*p+1][0] = t[2]; bhi[2*p+1][1] = t[3];
                ldsm_x4(t, bd + LO_OFF);
                blo[2*p][0] = t[0]; blo[2*p][1] = t[1];
                blo[2*p+1][0] = t[2]; blo[2*p+1][1] = t[3];
            }

#pragma unroll
            for (int mt = 0; mt < 4; mt++)
#pragma unroll
                for (int nt = 0; nt < 4; nt++) {
                    mma16816(acc[mt][nt], ahi[mt], bhi[nt]);
                    mma16816(acc[mt][nt], alo[mt], bhi[nt]);
                    mma16816(acc[mt][nt], ahi[mt], blo[nt]);
                }
        }
        __syncthreads();
    }

    int tg = lane >> 2, t4 = lane & 3;
    __nv_bfloat16 *Yhi = nullptr, *Ylo = nullptr;
    if (mode == 0) { Yhi = g_Qhi; Ylo = g_Qlo; }
    else if (mode == 1) { Yhi = g_Khi; Ylo = g_Klo; }
    else if (mode == 2) { Yhi = g_Vhi; Ylo = g_Vlo; }

#pragma unroll
    for (int mt = 0; mt < 4; mt++) {
        int rbase = row0 + warp_m*64 + mt*16 + tg;
#pragma unroll
        for (int nt = 0; nt < 4; nt++) {
            int col = col0 + warp_n*32 + nt*8 + t4*2;
            float b0 = bias[col], b1 = bias[col + 1];
#pragma unroll
            for (int half = 0; half < 2; half++) {
                int r = rbase + half*8;
                float v0 = acc[mt][nt][half*2 + 0] + b0;
                float v1 = acc[mt][nt][half*2 + 1] + b1;
                if (mode == 3) {
                    *(float2*)(Yext + (size_t)r*DMm + col) = make_float2(v0, v1);
                } else {
                    int bi = r >> 11, s = r & (Ss - 1);
                    int h = col >> 6, d = col & 63;
                    size_t off = (((size_t)bi*Hh + h)*Ss + s)*Dd + d;
                    uint32_t hi, lo;
                    pack2(v0, v1, hi, lo);
                    *(uint32_t*)(Yhi + off) = hi;
                    *(uint32_t*)(Ylo + off) = lo;
                }
            }
        }
    }
}

// ---------------------------------------------------------------------------
// Attention smem layout.  RS = 144B row stride (ldmatrix conflict-free).
// ---------------------------------------------------------------------------
#define RS    144
#define SQHI  0
#define SQLO  18432
#define SKHI  36864
#define SKLO  46080
#define SVHI  55296
#define SVLO  64512
#define SMSK1 55296
#define SMSK2 73728
#define SUM_SMEM (SMSK1 + 8192)        // 63488
#define PV_SMEM  (SMSK2 + 8192)        // 81920

// load a 128-row (Q) or 64-row (K/V) bf16 tile into smem at RS stride
#define LOAD_TILE_64(SRC, SOFF)                                              \
    _Pragma("unroll")                                                        \
    for (int i = 0; i < 2; i++) {                                            \
        int f = tid + i*256;              /* 512 uint4 */                    \
        int row = f >> 3, c8 = (f & 7) * 8;                                  \
        *(uint4*)(sm + (SOFF) + row*RS + c8*2) =                             \
            *(const uint4*)((SRC) + (size_t)row*Dd + c8);                    \
    }

// ---------------------------------------------------------------------------
// Pass 1: rowsums of exp(QK^T/8 + mask).
// ---------------------------------------------------------------------------
__global__ __launch_bounds__(256, 2) void attn_sum_mma(const float* __restrict__ mask)
{
    extern __shared__ __align__(16) char sm[];
    uint32_t sb = smem_u32(sm);
    float* smask = (float*)(sm + SMSK1);

    int tid  = threadIdx.x;
    int lane = tid & 31, w = tid >> 5;
    int tg = lane >> 2, t4 = lane & 3;
    int qt = blockIdx.x, h = blockIdx.y, b = blockIdx.z;

    size_t hb = ((size_t)b*Hh + h)*Ss;
    const __nv_bfloat16* Qh = g_Qhi + (hb + (size_t)qt*128)*Dd;
    const __nv_bfloat16* Ql = g_Qlo + (hb + (size_t)qt*128)*Dd;
    const __nv_bfloat16* Kh = g_Khi + hb*Dd;
    const __nv_bfloat16* Kl = g_Klo + hb*Dd;

#pragma unroll
    for (int i = 0; i < 2; i++) {
        int f = tid + i*256;
        *(float4*)&smask[f*4] = *(const float4*)(mask + (size_t)b*Ss + f*4);
    }
#pragma unroll
    for (int i = 0; i < 4; i++) {
        int f = tid + i*256;              // 1024 uint4
        int row = f >> 3, c8 = (f & 7) * 8;
        *(uint4*)(sm + SQHI + row*RS + c8*2) = *(const uint4*)(Qh + (size_t)row*Dd + c8);
        *(uint4*)(sm + SQLO + row*RS + c8*2) = *(const uint4*)(Ql + (size_t)row*Dd + c8);
    }
    __syncthreads();

    int a_row = lane & 15;
    int a_kb  = (lane >> 4) * 16;
    int b_row = (lane & 7) + ((lane >> 4) << 3);
    int b_kb  = ((lane >> 3) & 1) * 16;

    float rs0 = 0.f, rs1 = 0.f;

    for (int kt = 0; kt < Ss; kt += 64) {
        __syncthreads();
        LOAD_TILE_64(Kh + (size_t)kt*Dd, SKHI)
        LOAD_TILE_64(Kl + (size_t)kt*Dd, SKLO)
        __syncthreads();

#pragma unroll
        for (int nbp = 0; nbp < 2; nbp++) {
            float accS[4][4];
#pragma unroll
            for (int j = 0; j < 4; j++)
#pragma unroll
                for (int e = 0; e < 4; e++) accS[j][e] = 0.f;

#pragma unroll
            for (int ks = 0; ks < 4; ks++) {
                uint32_t qh[4], ql[4];
                uint32_t qa = sb + SQHI + (uint32_t)(w*16 + a_row)*RS + ks*32 + a_kb;
                ldsm_x4(qh, qa);
                ldsm_x4(ql, qa + (SQLO - SQHI));
#pragma unroll
                for (int nb2 = 0; nb2 < 2; nb2++) {
                    int nb = nbp*2 + nb2;
                    uint32_t th[4], tl[4];
                    uint32_t ad = sb + SKHI + (uint32_t)(nb*16 + b_row)*RS + ks*32 + b_kb;
                    ldsm_x4(th, ad);
                    ldsm_x4(tl, ad + (SKLO - SKHI));
                    int j0 = nb2*2;
                    mma16816(accS[j0],   qh, th);
                    mma16816(accS[j0],   ql, th);
                    mma16816(accS[j0],   qh, tl);
                    mma16816(accS[j0+1], qh, th+2);
                    mma16816(accS[j0+1], ql, th+2);
                    mma16816(accS[j0+1], qh, tl+2);
                }
            }

#pragma unroll
            for (int idx = 0; idx < 4; idx++) {
                int col = (nbp*4 + idx)*8 + t4*2;
                float2 mv = *(float2*)&smask[kt + col];
                float m0 = mv.x * -1e9f, m1 = mv.y * -1e9f;
                rs0 += exp_fast(fmaf(accS[idx][0], 0.125f, m0))
                     + exp_fast(fmaf(accS[idx][1], 0.125f, m1));
                rs1 += exp_fast(fmaf(accS[idx][2], 0.125f, m0))
                     + exp_fast(fmaf(accS[idx][3], 0.125f, m1));
            }
        }
    }

    rs0 += __shfl_xor_sync(0xffffffffu, rs0, 1);
    rs0 += __shfl_xor_sync(0xffffffffu, rs0, 2);
    rs1 += __shfl_xor_sync(0xffffffffu, rs1, 1);
    rs1 += __shfl_xor_sync(0xffffffffu, rs1, 2);
    if (t4 == 0) {
        size_t base = hb + (size_t)qt*128;
        g_SUM[base + w*16 + tg]     = rs0;
        g_SUM[base + w*16 + tg + 8] = rs1;
    }
}

// ---------------------------------------------------------------------------
// Pass 2: recompute QK, p = exp/rowsum, write attn once, O += P V, O -> g_CTX.
// ---------------------------------------------------------------------------
__global__ __launch_bounds__(256, 2) void attn_pv_mma(
    const float* __restrict__ mask, float* __restrict__ attn, int write_attn)
{
    extern __shared__ __align__(16) char sm[];
    uint32_t sb = smem_u32(sm);
    float* smask = (float*)(sm + SMSK2);

    int tid  = threadIdx.x;
    int lane = tid & 31, w = tid >> 5;
    int tg = lane >> 2, t4 = lane & 3;
    int qt = blockIdx.x, h = blockIdx.y, b = blockIdx.z;

    size_t hb = ((size_t)b*Hh + h)*Ss;
    const __nv_bfloat16* Qh = g_Qhi + (hb + (size_t)qt*128)*Dd;
    const __nv_bfloat16* Ql = g_Qlo + (hb + (size_t)qt*128)*Dd;
    const __nv_bfloat16* Kh = g_Khi + hb*Dd;
    const __nv_bfloat16* Kl = g_Klo + hb*Dd;
    const __nv_bfloat16* Vh = g_Vhi + hb*Dd;
    const __nv_bfloat16* Vl = g_Vlo + hb*Dd;
    float* attn_base = attn + (hb + (size_t)qt*128)*Ss;

#pragma unroll
    for (int i = 0; i < 2; i++) {
        int f = tid + i*256;
        *(float4*)&smask[f*4] = *(const float4*)(mask + (size_t)b*Ss + f*4);
    }
#pragma unroll
    for (int i = 0; i < 4; i++) {
        int f = tid + i*256;
        int row = f >> 3, c8 = (f & 7) * 8;
        *(uint4*)(sm + SQHI + row*RS + c8*2) = *(const uint4*)(Qh + (size_t)row*Dd + c8);
        *(uint4*)(sm + SQLO + row*RS + c8*2) = *(const uint4*)(Ql + (size_t)row*Dd + c8);
    }
    __syncthreads();

    int a_row = lane & 15;
    int a_kb  = (lane >> 4) * 16;
    int b_row = (lane & 7) + ((lane >> 4) << 3);
    int b_kb  = ((lane >> 3) & 1) * 16;
    int v_koff = ((lane >> 3) & 1) * 8 + (lane & 7);
    int v_noff = (lane >> 4) * 8;

    size_t base = hb + (size_t)qt*128;
    float rinv0 = 1.0f / g_SUM[base + w*16 + tg];
    float rinv1 = 1.0f / g_SUM[base + w*16 + tg + 8];
    int r0g = w*16 + tg;

    float accO[8][4];
#pragma unroll
    for (int nt = 0; nt < 8; nt++)
#pragma unroll
        for (int e = 0; e < 4; e++) accO[nt][e] = 0.f;

    for (int kt = 0; kt < Ss; kt += 64) {
        __syncthreads();
        LOAD_TILE_64(Kh + (size_t)kt*Dd, SKHI)
        LOAD_TILE_64(Kl + (size_t)kt*Dd, SKLO)
        LOAD_TILE_64(Vh + (size_t)kt*Dd, SVHI)
        LOAD_TILE_64(Vl + (size_t)kt*Dd, SVLO)
        __syncthreads();

#pragma unroll
        for (int nbp = 0; nbp < 2; nbp++) {
            // ---- QK for 32 keys ----
            float accS[4][4];
#pragma unroll
            for (int j = 0; j < 4; j++)
#pragma unroll
                for (int e = 0; e < 4; e++) accS[j][e] = 0.f;

#pragma unroll
            for (int ks = 0; ks < 4; ks++) {
                uint32_t qh[4], ql[4];
                uint32_t qa = sb + SQHI + (uint32_t)(w*16 + a_row)*RS + ks*32 + a_kb;
                ldsm_x4(qh, qa);
                ldsm_x4(ql, qa + (SQLO - SQHI));
#pragma unroll
                for (int nb2 = 0; nb2 < 2; nb2++) {
                    int nb = nbp*2 + nb2;
                    uint32_t th[4], tl[4];
                    uint32_t ad = sb + SKHI + (uint32_t)(nb*16 + b_row)*RS + ks*32 + b_kb;
                    ldsm_x4(th, ad);
                    ldsm_x4(tl, ad + (SKLO - SKHI));
                    int j0 = nb2*2;
                    mma16816(accS[j0],   qh, th);
                    mma16816(accS[j0],   ql, th);
                    mma16816(accS[j0],   qh, tl);
                    mma16816(accS[j0+1], qh, th+2);
                    mma16816(accS[j0+1], ql, th+2);
                    mma16816(accS[j0+1], qh, tl+2);
                }
            }

            // ---- exp, normalize, attn write, pack ----
            uint32_t ph0[4], ph1[4], pl0[4], pl1[4];
#pragma unroll
            for (int idx = 0; idx < 4; idx++) {
                int col = (nbp*4 + idx)*8 + t4*2;
                float2 mv = *(float2*)&smask[kt + col];
                float m0 = mv.x * -1e9f, m1 = mv.y * -1e9f;
                float p0 = exp_fast(fmaf(accS[idx][0], 0.125f, m0)) * rinv0;
                float p1 = exp_fast(fmaf(accS[idx][1], 0.125f, m1)) * rinv0;
                float p2 = exp_fast(fmaf(accS[idx][2], 0.125f, m0)) * rinv1;
                float p3 = exp_fast(fmaf(accS[idx][3], 0.125f, m1)) * rinv1;
                if (write_attn) {
                    *(float2*)&attn_base[(size_t)r0g*Ss + kt + col]       = make_float2(p0, p1);
                    *(float2*)&attn_base[(size_t)(r0g + 8)*Ss + kt + col] = make_float2(p2, p3);
                }
                pack2(p0, p1, ph0[idx], pl0[idx]);
                pack2(p2, p3, ph1[idx], pl1[idx]);
            }

            // ---- PV for the same 32 keys ----
#pragma unroll
            for (int nb2 = 0; nb2 < 2; nb2++) {
                int ksv = nbp*2 + nb2;
                uint32_t ah[4] = {ph0[2*nb2], ph1[2*nb2], ph0[2*nb2+1], ph1[2*nb2+1]};
                uint32_t al[4] = {pl0[2*nb2], pl1[2*nb2], pl0[2*nb2+1], pl1[2*nb2+1]};
#pragma unroll
                for (int vb = 0; vb < 4; vb++) {
                    uint32_t th[4], tl[4];
                    uint32_t ad = sb + SVHI + (uint32_t)(ksv*16 + v_koff)*RS
                                + (vb*16 + v_noff)*2;
                    ldsm_x4_t(th, ad);
                    ldsm_x4_t(tl, ad + (SVLO - SVHI));
                    int nt0 = vb*2;
                    mma16816(accO[nt0],   ah, th);
                    mma16816(accO[nt0],   al, th);
                    mma16816(accO[nt0],   ah, tl);
                    mma16816(accO[nt0+1], ah, th+2);
                    mma16816(accO[nt0+1], al, th+2);
                    mma16816(accO[nt0+1], ah, tl+2);
                }
            }
        }
    }

    int q0 = qt*128 + w*16 + tg;
#pragma unroll
    for (int nt = 0; nt < 8; nt++) {
        int d = nt*8 + t4*2;
        float* c0 = g_CTX + ((size_t)b*Ss + q0)*DMm + h*64 + d;
        *(float2*)c0 = make_float2(accO[nt][0], accO[nt][1]);
        float* c1 = g_CTX + ((size_t)b*Ss + q0 + 8)*DMm + h*64 + d;
        *(float2*)c1 = make_float2(accO[nt][2], accO[nt][3]);
    }
}

// ---------------------------------------------------------------------------
// Launch
// ---------------------------------------------------------------------------
extern "C" void kernel_launch(void* const* d_in, const int* in_sizes, int n_in,
                              void* d_out, int out_size)
{
    const float* q    = (const float*)d_in[0];
    const float* k    = (const float*)d_in[1];
    const float* v    = (const float*)d_in[2];
    const float* mask = (const float*)d_in[3];
    const float* Wq   = (const float*)d_in[4];
    const float* bq   = (const float*)d_in[5];
    const float* Wk   = (const float*)d_in[6];
    const float* bk   = (const float*)d_in[7];
    const float* Wv   = (const float*)d_in[8];
    const float* bv   = (const float*)d_in[9];
    const float* Wo   = (const float*)d_in[10];
    const float* bo   = (const float*)d_in[11];

    float* out  = (float*)d_out;
    float* attn = out + (size_t)NTOK*DMm;

    long long need = (long long)NTOK*DMm + (long long)Bb*Hh*Ss*Ss;
    int write_attn = ((long long)out_size >= need) ? 1 : 0;

    cudaFuncSetAttribute(attn_sum_mma,
                         cudaFuncAttributeMaxDynamicSharedMemorySize, SUM_SMEM);
    cudaFuncSetAttribute(attn_pv_mma,
                         cudaFuncAttributeMaxDynamicSharedMemorySize, PV_SMEM);

    dim3 cgrid((NTOK*DMm)/(256*4));
    dim3 tgrid(DMm/32, DMm/32);
    dim3 tblk(32, 8);
    dim3 ggrid(DMm/128, NTOK/128);

    convert_split_kernel<<<cgrid, 256>>>(q, 0);
    transW_kernel<<<tgrid, tblk>>>(Wq);
    proj_mma_kernel<<<ggrid, 256>>>(bq, nullptr, 0);

    convert_split_kernel<<<cgrid, 256>>>(k, 0);
    transW_kernel<<<tgrid, tblk>>>(Wk);
    proj_mma_kernel<<<ggrid, 256>>>(bk, nullptr, 1);

    convert_split_kernel<<<cgrid, 256>>>(v, 0);
    transW_kernel<<<tgrid, tblk>>>(Wv);
    proj_mma_kernel<<<ggrid, 256>>>(bv, nullptr, 2);

    dim3 agrid(Ss/128, Hh, Bb);          // (16, 16, 2)
    attn_sum_mma<<<agrid, 256, SUM_SMEM>>>(mask);
    attn_pv_mma<<<agrid, 256, PV_SMEM>>>(mask, attn, write_attn);

    convert_split_kernel<<<cgrid, 256>>>(nullptr, 1);
    transW_kernel<<<tgrid, tblk>>>(Wo);
    proj_mma_kernel<<<ggrid, 256>>>(bo, out, 3);
}

// round 8
// speedup vs baseline: 2.0113x; 1.0289x over previous
#include <cuda_runtime.h>
#include <cuda_bf16.h>
#include <cstdint>

#define DMm  1024
#define Hh   16
#define Dd   64
#define Bb   2
#define Ss   2048
#define NTOK (Bb*Ss)   // 4096

// ---------------------------------------------------------------------------
// Static device scratch
// ---------------------------------------------------------------------------
__device__ float g_CTX[(size_t)NTOK*DMm];
__device__ float g_SUM[(size_t)Bb*Hh*Ss];
// X splits: slots 0/1/2 = q/k/v (slot 0 reused for CTX before out-proj)
__device__ __nv_bfloat16 g_Xhi [(size_t)3*NTOK*DMm];
__device__ __nv_bfloat16 g_Xlo [(size_t)3*NTOK*DMm];
// W^T splits: slots 0..3 = Wq,Wk,Wv,Wo   [N][K]
__device__ __nv_bfloat16 g_WThi[(size_t)4*DMm*DMm];
__device__ __nv_bfloat16 g_WTlo[(size_t)4*DMm*DMm];
// head-split Q/K/V, bf16 hi/lo  [b][h][s][d]
__device__ __nv_bfloat16 g_Qhi[(size_t)Bb*Hh*Ss*Dd];
__device__ __nv_bfloat16 g_Qlo[(size_t)Bb*Hh*Ss*Dd];
__device__ __nv_bfloat16 g_Khi[(size_t)Bb*Hh*Ss*Dd];
__device__ __nv_bfloat16 g_Klo[(size_t)Bb*Hh*Ss*Dd];
__device__ __nv_bfloat16 g_Vhi[(size_t)Bb*Hh*Ss*Dd];
__device__ __nv_bfloat16 g_Vlo[(size_t)Bb*Hh*Ss*Dd];

// ---------------------------------------------------------------------------
// Helpers (base ISA sm_80+, valid on compute_103)
// ---------------------------------------------------------------------------
__device__ __forceinline__ uint32_t smem_u32(const void* p) {
    uint32_t a;
    asm("{ .reg .u64 t; cvta.to.shared.u64 t, %1; cvt.u32.u64 %0, t; }"
        : "=r"(a) : "l"(p));
    return a;
}

__device__ __forceinline__ void ldsm_x4(uint32_t* r, uint32_t addr) {
    asm volatile("ldmatrix.sync.aligned.m8n8.x4.shared.b16 {%0,%1,%2,%3}, [%4];"
        : "=r"(r[0]), "=r"(r[1]), "=r"(r[2]), "=r"(r[3]) : "r"(addr));
}

__device__ __forceinline__ void ldsm_x4_t(uint32_t* r, uint32_t addr) {
    asm volatile("ldmatrix.sync.aligned.m8n8.x4.trans.shared.b16 {%0,%1,%2,%3}, [%4];"
        : "=r"(r[0]), "=r"(r[1]), "=r"(r[2]), "=r"(r[3]) : "r"(addr));
}

__device__ __forceinline__ void mma16816(float* c, const uint32_t* a, const uint32_t* b) {
    asm volatile(
        "mma.sync.aligned.m16n8k16.row.col.f32.bf16.bf16.f32 "
        "{%0,%1,%2,%3}, {%4,%5,%6,%7}, {%8,%9}, {%0,%1,%2,%3};"
        : "+f"(c[0]), "+f"(c[1]), "+f"(c[2]), "+f"(c[3])
        : "r"(a[0]), "r"(a[1]), "r"(a[2]), "r"(a[3]), "r"(b[0]), "r"(b[1]));
}

#define CP_ASYNC16(dst, src) \
    asm volatile("cp.async.cg.shared.global [%0], [%1], 16;" \
        :: "r"(dst), "l"(src))
#define CP_COMMIT() asm volatile("cp.async.commit_group;")
#define CP_WAIT1()  asm volatile("cp.async.wait_group 1;")
#define CP_WAIT0()  asm volatile("cp.async.wait_group 0;")

// FFMA-pipe exp: 2^(x*log2e), deg-6 poly on [-0.5,0.5], rel err ~1e-6
__device__ __forceinline__ float exp_fast(float x) {
    float t = x * 1.4426950408889634f;
    t = fminf(fmaxf(t, -126.f), 126.f);
    float fi = rintf(t);
    float f  = t - fi;
    int   ei = (int)fi;
    float p = 1.5403530e-4f;
    p = fmaf(p, f, 1.33335581e-3f);
    p = fmaf(p, f, 9.61812911e-3f);
    p = fmaf(p, f, 5.55041087e-2f);
    p = fmaf(p, f, 2.40226507e-1f);
    p = fmaf(p, f, 6.93147181e-1f);
    p = fmaf(p, f, 1.0f);
    return __int_as_float(__float_as_int(p) + (ei << 23));
}

__device__ __forceinline__ ushort bfu(__nv_bfloat16 h) {
    return __bfloat16_as_ushort(h);
}

__device__ __forceinline__ void split4(float4 v, uint2& hi, uint2& lo) {
    __nv_bfloat16 h0 = __float2bfloat16_rn(v.x);
    __nv_bfloat16 h1 = __float2bfloat16_rn(v.y);
    __nv_bfloat16 h2 = __float2bfloat16_rn(v.z);
    __nv_bfloat16 h3 = __float2bfloat16_rn(v.w);
    hi.x = (uint32_t)bfu(h0) | ((uint32_t)bfu(h1) << 16);
    hi.y = (uint32_t)bfu(h2) | ((uint32_t)bfu(h3) << 16);
    __nv_bfloat16 l0 = __float2bfloat16_rn(v.x - __bfloat162float(h0));
    __nv_bfloat16 l1 = __float2bfloat16_rn(v.y - __bfloat162float(h1));
    __nv_bfloat16 l2 = __float2bfloat16_rn(v.z - __bfloat162float(h2));
    __nv_bfloat16 l3 = __float2bfloat16_rn(v.w - __bfloat162float(h3));
    lo.x = (uint32_t)bfu(l0) | ((uint32_t)bfu(l1) << 16);
    lo.y = (uint32_t)bfu(l2) | ((uint32_t)bfu(l3) << 16);
}

__device__ __forceinline__ void pack2(float a, float b, uint32_t& hi, uint32_t& lo) {
    __nv_bfloat16 ha = __float2bfloat16_rn(a);
    __nv_bfloat16 hb = __float2bfloat16_rn(b);
    hi = (uint32_t)bfu(ha) | ((uint32_t)bfu(hb) << 16);
    __nv_bfloat16 la = __float2bfloat16_rn(a - __bfloat162float(ha));
    __nv_bfloat16 lb = __float2bfloat16_rn(b - __bfloat162float(hb));
    lo = (uint32_t)bfu(la) | ((uint32_t)bfu(lb) << 16);
}

// ---------------------------------------------------------------------------
// fp32 -> bf16 hi/lo split.  grid.y selects input (q/k/v); use_ctx reads CTX.
// ---------------------------------------------------------------------------
__global__ __launch_bounds__(256) void convert_split_kernel(
    const float* __restrict__ xq, const float* __restrict__ xk,
    const float* __restrict__ xv, int use_ctx)
{
    int z = blockIdx.y;
    const float* X = use_ctx ? g_CTX : (z == 0 ? xq : (z == 1 ? xk : xv));
    size_t slot = (size_t)z * NTOK * DMm;
    size_t i = ((size_t)blockIdx.x * 256 + threadIdx.x) * 4;
    float4 v = *(const float4*)(X + i);
    uint2 hi, lo;
    split4(v, hi, lo);
    *(uint2*)(g_Xhi + slot + i) = hi;
    *(uint2*)(g_Xlo + slot + i) = lo;
}

// ---------------------------------------------------------------------------
// W [K][N] fp32 -> WT [N][K] bf16 hi/lo.  grid.z selects weight slot.
// ---------------------------------------------------------------------------
__global__ __launch_bounds__(256) void transW_kernel(
    const float* __restrict__ Wq, const float* __restrict__ Wk,
    const float* __restrict__ Wv, const float* __restrict__ Wo)
{
    __shared__ float t[32][33];
    int z = blockIdx.z;
    const float* W = (z == 0) ? Wq : (z == 1) ? Wk : (z == 2) ? Wv : Wo;
    size_t slot = (size_t)z * DMm * DMm;
    int nx = blockIdx.x * 32, ky = blockIdx.y * 32;
    int txx = threadIdx.x, tyy = threadIdx.y;   // block (32, 8)
#pragma unroll
    for (int j = 0; j < 4; j++)
        t[tyy + j*8][txx] = W[(size_t)(ky + tyy + j*8)*DMm + nx + txx];
    __syncthreads();
#pragma unroll
    for (int j = 0; j < 4; j++) {
        float val = t[txx][tyy + j*8];
        __nv_bfloat16 h = __float2bfloat16_rn(val);
        size_t o = slot + (size_t)(nx + tyy + j*8)*DMm + ky + txx;
        g_WThi[o] = h;
        g_WTlo[o] = __float2bfloat16_rn(val - __bfloat162float(h));
    }
}

// ---------------------------------------------------------------------------
// HMMA projection GEMM, cp.async double-buffered.  bf16x3 split.
// grid.z + base_mode selects mode: 0/1/2 -> Q/K/V head-split; 3 -> flat out.
// Dynamic smem: 2 stages x (Ahi,Alo,Bhi,Blo) x 128x32 bf16 @80B rows.
// ---------------------------------------------------------------------------
#define PRS    80                    // smem row stride bytes (40 bf16)
#define P_AHI  0
#define P_ALO  10240
#define P_BHI  20480
#define P_BLO  30720
#define P_SSTR 40960                 // stage stride
#define PROJ_SMEM (2*P_SSTR)         // 81920

__global__ __launch_bounds__(256, 1) void proj_mma_kernel(
    const float* __restrict__ bq, const float* __restrict__ bk,
    const float* __restrict__ bv, float* __restrict__ Yext, int base_mode)
{
    extern __shared__ __align__(16) char psm[];
    uint32_t sb = smem_u32(psm);

    int mode = base_mode + blockIdx.z;
    const float* bias = (blockIdx.z == 0) ? bq : (blockIdx.z == 1) ? bk : bv;

    const __nv_bfloat16* Xhi = g_Xhi + (size_t)(mode == 3 ? 0 : mode) * NTOK * DMm;
    const __nv_bfloat16* Xlo = g_Xlo + (size_t)(mode == 3 ? 0 : mode) * NTOK * DMm;
    const __nv_bfloat16* WThi = g_WThi + (size_t)mode * DMm * DMm;
    const __nv_bfloat16* WTlo = g_WTlo + (size_t)mode * DMm * DMm;

    int tid  = threadIdx.x;
    int lane = tid & 31, wid = tid >> 5;
    int warp_m = wid & 1, warp_n = wid >> 1;
    int row0 = blockIdx.y * 128;
    int col0 = blockIdx.x * 128;

    float acc[4][4][4];
#pragma unroll
    for (int mt = 0; mt < 4; mt++)
#pragma unroll
        for (int nt = 0; nt < 4; nt++)
#pragma unroll
            for (int e = 0; e < 4; e++) acc[mt][nt][e] = 0.f;

    int ld_r = tid >> 1;             // 0..127
    int ld_c = (tid & 1) * 2;        // 16B-chunk pairs: c in {0,1} handles 2 chunks

    // issue cp.async loads for chunk ch into stage st
    auto issue = [&](int ch, uint32_t st) {
        int k0 = ch * 32;
#pragma unroll
        for (int cc = 0; cc < 2; cc++) {
            int c = ld_c + cc;                       // 0..3
            uint32_t doff = st + (uint32_t)ld_r*PRS + c*16;
            size_t ga = (size_t)(row0 + ld_r)*DMm + k0 + c*8;
            CP_ASYNC16(sb + P_AHI + doff, Xhi + ga);
            CP_ASYNC16(sb + P_ALO + doff, Xlo + ga);
            size_t gb = (size_t)(col0 + ld_r)*DMm + k0 + c*8;
            CP_ASYNC16(sb + P_BHI + doff, WThi + gb);
            CP_ASYNC16(sb + P_BLO + doff, WTlo + gb);
        }
        CP_COMMIT();
    };

    issue(0, 0);

    int a_row = lane & 15;
    int a_kb  = (lane >> 4) * 16;
    int b_row = (lane & 7) + ((lane >> 4) << 3);
    int b_kb  = ((lane >> 3) & 1) * 16;

    for (int ch = 0; ch < 32; ch++) {
        uint32_t st = (uint32_t)(ch & 1) * P_SSTR;
        if (ch + 1 < 32) {
            issue(ch + 1, (uint32_t)((ch + 1) & 1) * P_SSTR);
            CP_WAIT1();
        } else {
            CP_WAIT0();
        }
        __syncthreads();

#pragma unroll
        for (int kk = 0; kk < 2; kk++) {
            int kbyte = kk * 32;
            uint32_t ahi[4][4], alo[4][4];
            uint32_t bhi[4][2], blo[4][2];

#pragma unroll
            for (int mt = 0; mt < 4; mt++) {
                uint32_t ad = sb + st + P_AHI
                            + (uint32_t)(warp_m*64 + mt*16 + a_row)*PRS + kbyte + a_kb;
                ldsm_x4(ahi[mt], ad);
                ldsm_x4(alo[mt], ad + (P_ALO - P_AHI));
            }
#pragma unroll
            for (int p = 0; p < 2; p++) {
                uint32_t bd = sb + st + P_BHI
                            + (uint32_t)(warp_n*32 + p*16 + b_row)*PRS + kbyte + b_kb;
                uint32_t t[4];
                ldsm_x4(t, bd);
                bhi[2*p][0] = t[0]; bhi[2*p][1] = t[1];
                bhi[2*p+1][0] = t[2]; bhi[2*p+1][1] = t[3];
                ldsm_x4(t, bd + (P_BLO - P_BHI));
                blo[2*p][0] = t[0]; blo[2*p][1] = t[1];
                blo[2*p+1][0] = t[2]; blo[2*p+1][1] = t[3];
            }

#pragma unroll
            for (int mt = 0; mt < 4; mt++)
#pragma unroll
                for (int nt = 0; nt < 4; nt++) {
                    mma16816(acc[mt][nt], ahi[mt], bhi[nt]);
                    mma16816(acc[mt][nt], alo[mt], bhi[nt]);
                    mma16816(acc[mt][nt], ahi[mt], blo[nt]);
                }
        }
        __syncthreads();
    }

    int tg = lane >> 2, t4 = lane & 3;
    __nv_bfloat16 *Yhi = nullptr, *Ylo = nullptr;
    if (mode == 0) { Yhi = g_Qhi; Ylo = g_Qlo; }
    else if (mode == 1) { Yhi = g_Khi; Ylo = g_Klo; }
    else if (mode == 2) { Yhi = g_Vhi; Ylo = g_Vlo; }

#pragma unroll
    for (int mt = 0; mt < 4; mt++) {
        int rbase = row0 + warp_m*64 + mt*16 + tg;
#pragma unroll
        for (int nt = 0; nt < 4; nt++) {
            int col = col0 + warp_n*32 + nt*8 + t4*2;
            float b0 = bias[col], b1 = bias[col + 1];
#pragma unroll
            for (int half = 0; half < 2; half++) {
                int r = rbase + half*8;
                float v0 = acc[mt][nt][half*2 + 0] + b0;
                float v1 = acc[mt][nt][half*2 + 1] + b1;
                if (mode == 3) {
                    *(float2*)(Yext + (size_t)r*DMm + col) = make_float2(v0, v1);
                } else {
                    int bi = r >> 11, s = r & (Ss - 1);
                    int h = col >> 6, d = col & 63;
                    size_t off = (((size_t)bi*Hh + h)*Ss + s)*Dd + d;
                    uint32_t hi, lo;
                    pack2(v0, v1, hi, lo);
                    *(uint32_t*)(Yhi + off) = hi;
                    *(uint32_t*)(Ylo + off) = lo;
                }
            }
        }
    }
}

// ---------------------------------------------------------------------------
// Attention smem layout.  RS = 144B row stride (ldmatrix conflict-free).
// ---------------------------------------------------------------------------
#define RS    144
#define SQHI  0
#define SQLO  18432
#define SKHI  36864
#define SKLO  46080
#define SVHI  55296
#define SVLO  64512
#define SMSK1 55296
#define SMSK2 73728
#define SUM_SMEM (SMSK1 + 8192)        // 63488
#define PV_SMEM  (SMSK2 + 8192)        // 81920

#define LOAD_TILE_64(SRC, SOFF)                                              \
    _Pragma("unroll")                                                        \
    for (int i = 0; i < 2; i++) {                                            \
        int f = tid + i*256;              /* 512 uint4 */                    \
        int row = f >> 3, c8 = (f & 7) * 8;                                  \
        *(uint4*)(sm + (SOFF) + row*RS + c8*2) =                             \
            *(const uint4*)((SRC) + (size_t)row*Dd + c8);                    \
    }

// ---------------------------------------------------------------------------
// Pass 1: rowsums of exp(QK^T/8 + mask).
// ---------------------------------------------------------------------------
__global__ __launch_bounds__(256, 2) void attn_sum_mma(const float* __restrict__ mask)
{
    extern __shared__ __align__(16) char sm[];
    uint32_t sb = smem_u32(sm);
    float* smask = (float*)(sm + SMSK1);

    int tid  = threadIdx.x;
    int lane = tid & 31, w = tid >> 5;
    int tg = lane >> 2, t4 = lane & 3;
    int qt = blockIdx.x, h = blockIdx.y, b = blockIdx.z;

    size_t hb = ((size_t)b*Hh + h)*Ss;
    const __nv_bfloat16* Qh = g_Qhi + (hb + (size_t)qt*128)*Dd;
    const __nv_bfloat16* Ql = g_Qlo + (hb + (size_t)qt*128)*Dd;
    const __nv_bfloat16* Kh = g_Khi + hb*Dd;
    const __nv_bfloat16* Kl = g_Klo + hb*Dd;

#pragma unroll
    for (int i = 0; i < 2; i++) {
        int f = tid + i*256;
        *(float4*)&smask[f*4] = *(const float4*)(mask + (size_t)b*Ss + f*4);
    }
#pragma unroll
    for (int i = 0; i < 4; i++) {
        int f = tid + i*256;
        int row = f >> 3, c8 = (f & 7) * 8;
        *(uint4*)(sm + SQHI + row*RS + c8*2) = *(const uint4*)(Qh + (size_t)row*Dd + c8);
        *(uint4*)(sm + SQLO + row*RS + c8*2) = *(const uint4*)(Ql + (size_t)row*Dd + c8);
    }
    __syncthreads();

    int a_row = lane & 15;
    int a_kb  = (lane >> 4) * 16;
    int b_row = (lane & 7) + ((lane >> 4) << 3);
    int b_kb  = ((lane >> 3) & 1) * 16;

    float rs0 = 0.f, rs1 = 0.f;

    for (int kt = 0; kt < Ss; kt += 64) {
        __syncthreads();
        LOAD_TILE_64(Kh + (size_t)kt*Dd, SKHI)
        LOAD_TILE_64(Kl + (size_t)kt*Dd, SKLO)
        __syncthreads();

#pragma unroll
        for (int nbp = 0; nbp < 2; nbp++) {
            float accS[4][4];
#pragma unroll
            for (int j = 0; j < 4; j++)
#pragma unroll
                for (int e = 0; e < 4; e++) accS[j][e] = 0.f;

#pragma unroll
            for (int ks = 0; ks < 4; ks++) {
                uint32_t qh[4], ql[4];
                uint32_t qa = sb + SQHI + (uint32_t)(w*16 + a_row)*RS + ks*32 + a_kb;
                ldsm_x4(qh, qa);
                ldsm_x4(ql, qa + (SQLO - SQHI));
#pragma unroll
                for (int nb2 = 0; nb2 < 2; nb2++) {
                    int nb = nbp*2 + nb2;
                    uint32_t th[4], tl[4];
                    uint32_t ad = sb + SKHI + (uint32_t)(nb*16 + b_row)*RS + ks*32 + b_kb;
                    ldsm_x4(th, ad);
                    ldsm_x4(tl, ad + (SKLO - SKHI));
                    int j0 = nb2*2;
                    mma16816(accS[j0],   qh, th);
                    mma16816(accS[j0],   ql, th);
                    mma16816(accS[j0],   qh, tl);
                    mma16816(accS[j0+1], qh, th+2);
                    mma16816(accS[j0+1], ql, th+2);
                    mma16816(accS[j0+1], qh, tl+2);
                }
            }

#pragma unroll
            for (int idx = 0; idx < 4; idx++) {
                int col = (nbp*4 + idx)*8 + t4*2;
                float2 mv = *(float2*)&smask[kt + col];
                float m0 = mv.x * -1e9f, m1 = mv.y * -1e9f;
                rs0 += exp_fast(fmaf(accS[idx][0], 0.125f, m0))
                     + exp_fast(fmaf(accS[idx][1], 0.125f, m1));
                rs1 += exp_fast(fmaf(accS[idx][2], 0.125f, m0))
                     + exp_fast(fmaf(accS[idx][3], 0.125f, m1));
            }
        }
    }

    rs0 += __shfl_xor_sync(0xffffffffu, rs0, 1);
    rs0 += __shfl_xor_sync(0xffffffffu, rs0, 2);
    rs1 += __shfl_xor_sync(0xffffffffu, rs1, 1);
    rs1 += __shfl_xor_sync(0xffffffffu, rs1, 2);
    if (t4 == 0) {
        size_t base = hb + (size_t)qt*128;
        g_SUM[base + w*16 + tg]     = rs0;
        g_SUM[base + w*16 + tg + 8] = rs1;
    }
}

// ---------------------------------------------------------------------------
// Pass 2: recompute QK, p = exp/rowsum, write attn once, O += P V, O -> g_CTX.
// ---------------------------------------------------------------------------
__global__ __launch_bounds__(256, 2) void attn_pv_mma(
    const float* __restrict__ mask, float* __restrict__ attn, int write_attn)
{
    extern __shared__ __align__(16) char sm[];
    uint32_t sb = smem_u32(sm);
    float* smask = (float*)(sm + SMSK2);

    int tid  = threadIdx.x;
    int lane = tid & 31, w = tid >> 5;
    int tg = lane >> 2, t4 = lane & 3;
    int qt = blockIdx.x, h = blockIdx.y, b = blockIdx.z;

    size_t hb = ((size_t)b*Hh + h)*Ss;
    const __nv_bfloat16* Qh = g_Qhi + (hb + (size_t)qt*128)*Dd;
    const __nv_bfloat16* Ql = g_Qlo + (hb + (size_t)qt*128)*Dd;
    const __nv_bfloat16* Kh = g_Khi + hb*Dd;
    const __nv_bfloat16* Kl = g_Klo + hb*Dd;
    const __nv_bfloat16* Vh = g_Vhi + hb*Dd;
    const __nv_bfloat16* Vl = g_Vlo + hb*Dd;
    float* attn_base = attn + (hb + (size_t)qt*128)*Ss;

#pragma unroll
    for (int i = 0; i < 2; i++) {
        int f = tid + i*256;
        *(float4*)&smask[f*4] = *(const float4*)(mask + (size_t)b*Ss + f*4);
    }
#pragma unroll
    for (int i = 0; i < 4; i++) {
        int f = tid + i*256;
        int row = f >> 3, c8 = (f & 7) * 8;
        *(uint4*)(sm + SQHI + row*RS + c8*2) = *(const uint4*)(Qh + (size_t)row*Dd + c8);
        *(uint4*)(sm + SQLO + row*RS + c8*2) = *(const uint4*)(Ql + (size_t)row*Dd + c8);
    }
    __syncthreads();

    int a_row = lane & 15;
    int a_kb  = (lane >> 4) * 16;
    int b_row = (lane & 7) + ((lane >> 4) << 3);
    int b_kb  = ((lane >> 3) & 1) * 16;
    int v_koff = ((lane >> 3) & 1) * 8 + (lane & 7);
    int v_noff = (lane >> 4) * 8;

    size_t base = hb + (size_t)qt*128;
    float rinv0 = 1.0f / g_SUM[base + w*16 + tg];
    float rinv1 = 1.0f / g_SUM[base + w*16 + tg + 8];
    int r0g = w*16 + tg;

    float accO[8][4];
#pragma unroll
    for (int nt = 0; nt < 8; nt++)
#pragma unroll
        for (int e = 0; e < 4; e++) accO[nt][e] = 0.f;

    for (int kt = 0; kt < Ss; kt += 64) {
        __syncthreads();
        LOAD_TILE_64(Kh + (size_t)kt*Dd, SKHI)
        LOAD_TILE_64(Kl + (size_t)kt*Dd, SKLO)
        LOAD_TILE_64(Vh + (size_t)kt*Dd, SVHI)
        LOAD_TILE_64(Vl + (size_t)kt*Dd, SVLO)
        __syncthreads();

#pragma unroll
        for (int nbp = 0; nbp < 2; nbp++) {
            float accS[4][4];
#pragma unroll
            for (int j = 0; j < 4; j++)
#pragma unroll
                for (int e = 0; e < 4; e++) accS[j][e] = 0.f;

#pragma unroll
            for (int ks = 0; ks < 4; ks++) {
                uint32_t qh[4], ql[4];
                uint32_t qa = sb + SQHI + (uint32_t)(w*16 + a_row)*RS + ks*32 + a_kb;
                ldsm_x4(qh, qa);
                ldsm_x4(ql, qa + (SQLO - SQHI));
#pragma unroll
                for (int nb2 = 0; nb2 < 2; nb2++) {
                    int nb = nbp*2 + nb2;
                    uint32_t th[4], tl[4];
                    uint32_t ad = sb + SKHI + (uint32_t)(nb*16 + b_row)*RS + ks*32 + b_kb;
                    ldsm_x4(th, ad);
                    ldsm_x4(tl, ad + (SKLO - SKHI));
                    int j0 = nb2*2;
                    mma16816(accS[j0],   qh, th);
                    mma16816(accS[j0],   ql, th);
                    mma16816(accS[j0],   qh, tl);
                    mma16816(accS[j0+1], qh, th+2);
                    mma16816(accS[j0+1], ql, th+2);
                    mma16816(accS[j0+1], qh, tl+2);
                }
            }

            uint32_t ph0[4], ph1[4], pl0[4], pl1[4];
#pragma unroll
            for (int idx = 0; idx < 4; idx++) {
                int col = (nbp*4 + idx)*8 + t4*2;
                float2 mv = *(float2*)&smask[kt + col];
                float m0 = mv.x * -1e9f, m1 = mv.y * -1e9f;
                float p0 = exp_fast(fmaf(accS[idx][0], 0.125f, m0)) * rinv0;
                float p1 = exp_fast(fmaf(accS[idx][1], 0.125f, m1)) * rinv0;
                float p2 = exp_fast(fmaf(accS[idx][2], 0.125f, m0)) * rinv1;
                float p3 = exp_fast(fmaf(accS[idx][3], 0.125f, m1)) * rinv1;
                if (write_attn) {
                    *(float2*)&attn_base[(size_t)r0g*Ss + kt + col]       = make_float2(p0, p1);
                    *(float2*)&attn_base[(size_t)(r0g + 8)*Ss + kt + col] = make_float2(p2, p3);
                }
                pack2(p0, p1, ph0[idx], pl0[idx]);
                pack2(p2, p3, ph1[idx], pl1[idx]);
            }

#pragma unroll
            for (int nb2 = 0; nb2 < 2; nb2++) {
                int ksv = nbp*2 + nb2;
                uint32_t ah[4] = {ph0[2*nb2], ph1[2*nb2], ph0[2*nb2+1], ph1[2*nb2+1]};
                uint32_t al[4] = {pl0[2*nb2], pl1[2*nb2], pl0[2*nb2+1], pl1[2*nb2+1]};
#pragma unroll
                for (int vb = 0; vb < 4; vb++) {
                    uint32_t th[4], tl[4];
                    uint32_t ad = sb + SVHI + (uint32_t)(ksv*16 + v_koff)*RS
                                + (vb*16 + v_noff)*2;
                    ldsm_x4_t(th, ad);
                    ldsm_x4_t(tl, ad + (SVLO - SVHI));
                    int nt0 = vb*2;
                    mma16816(accO[nt0],   ah, th);
                    mma16816(accO[nt0],   al, th);
                    mma16816(accO[nt0],   ah, tl);
                    mma16816(accO[nt0+1], ah, th+2);
                    mma16816(accO[nt0+1], al, th+2);
                    mma16816(accO[nt0+1], ah, tl+2);
                }
            }
        }
    }

    int q0 = qt*128 + w*16 + tg;
#pragma unroll
    for (int nt = 0; nt < 8; nt++) {
        int d = nt*8 + t4*2;
        float* c0 = g_CTX + ((size_t)b*Ss + q0)*DMm + h*64 + d;
        *(float2*)c0 = make_float2(accO[nt][0], accO[nt][1]);
        float* c1 = g_CTX + ((size_t)b*Ss + q0 + 8)*DMm + h*64 + d;
        *(float2*)c1 = make_float2(accO[nt][2], accO[nt][3]);
    }
}

// ---------------------------------------------------------------------------
// Launch
// ---------------------------------------------------------------------------
extern "C" void kernel_launch(void* const* d_in, const int* in_sizes, int n_in,
                              void* d_out, int out_size)
{
    const float* q    = (const float*)d_in[0];
    const float* k    = (const float*)d_in[1];
    const float* v    = (const float*)d_in[2];
    const float* mask = (const float*)d_in[3];
    const float* Wq   = (const float*)d_in[4];
    const float* bq   = (const float*)d_in[5];
    const float* Wk   = (const float*)d_in[6];
    const float* bk   = (const float*)d_in[7];
    const float* Wv   = (const float*)d_in[8];
    const float* bv   = (const float*)d_in[9];
    const float* Wo   = (const float*)d_in[10];
    const float* bo   = (const float*)d_in[11];

    float* out  = (float*)d_out;
    float* attn = out + (size_t)NTOK*DMm;

    long long need = (long long)NTOK*DMm + (long long)Bb*Hh*Ss*Ss;
    int write_attn = ((long long)out_size >= need) ? 1 : 0;

    cudaFuncSetAttribute(proj_mma_kernel,
                         cudaFuncAttributeMaxDynamicSharedMemorySize, PROJ_SMEM);
    cudaFuncSetAttribute(attn_sum_mma,
                         cudaFuncAttributeMaxDynamicSharedMemorySize, SUM_SMEM);
    cudaFuncSetAttribute(attn_pv_mma,
                         cudaFuncAttributeMaxDynamicSharedMemorySize, PV_SMEM);

    // prep: split q,k,v (one launch) + transpose all 4 weights (one launch)
    dim3 cgrid((NTOK*DMm)/(256*4), 3);
    convert_split_kernel<<<cgrid, 256>>>(q, k, v, 0);
    dim3 tgrid(DMm/32, DMm/32, 4);
    transW_kernel<<<tgrid, dim3(32, 8)>>>(Wq, Wk, Wv, Wo);

    // fused Q/K/V projections (one launch, grid.z = 3)
    dim3 ggrid3(DMm/128, NTOK/128, 3);
    proj_mma_kernel<<<ggrid3, 256, PROJ_SMEM>>>(bq, bk, bv, nullptr, 0);

    // attention
    dim3 agrid(Ss/128, Hh, Bb);
    attn_sum_mma<<<agrid, 256, SUM_SMEM>>>(mask);
    attn_pv_mma<<<agrid, 256, PV_SMEM>>>(mask, attn, write_attn);

    // out projection: split CTX into slot 0, then GEMM with W slot 3
    dim3 cgrid1((NTOK*DMm)/(256*4), 1);
    convert_split_kernel<<<cgrid1, 256>>>(nullptr, nullptr, nullptr, 1);
    dim3 ggrid1(DMm/128, NTOK/128, 1);
    proj_mma_kernel<<<ggrid1, 256, PROJ_SMEM>>>(bo, bo, bo, out, 3);
}

// round 9
// speedup vs baseline: 2.1492x; 1.0685x over previous
#include <cuda_runtime.h>
#include <cuda_bf16.h>
#include <cstdint>

#define DMm  1024
#define Hh   16
#define Dd   64
#define Bb   2
#define Ss   2048
#define NTOK (Bb*Ss)   // 4096

// ---------------------------------------------------------------------------
// Static device scratch
// ---------------------------------------------------------------------------
__device__ float g_CTX[(size_t)NTOK*DMm];
__device__ float g_SUM[(size_t)Bb*Hh*Ss];
// X splits: slots 0/1/2 = q/k/v (slot 0 reused for CTX before out-proj)
__device__ __nv_bfloat16 g_Xhi [(size_t)3*NTOK*DMm];
__device__ __nv_bfloat16 g_Xlo [(size_t)3*NTOK*DMm];
// W^T splits: slots 0..3 = Wq,Wk,Wv,Wo   [N][K]
__device__ __nv_bfloat16 g_WThi[(size_t)4*DMm*DMm];
__device__ __nv_bfloat16 g_WTlo[(size_t)4*DMm*DMm];
// head-split Q/K/V, bf16 hi/lo  [b][h][s][d]
__device__ __nv_bfloat16 g_Qhi[(size_t)Bb*Hh*Ss*Dd];
__device__ __nv_bfloat16 g_Qlo[(size_t)Bb*Hh*Ss*Dd];
__device__ __nv_bfloat16 g_Khi[(size_t)Bb*Hh*Ss*Dd];
__device__ __nv_bfloat16 g_Klo[(size_t)Bb*Hh*Ss*Dd];
__device__ __nv_bfloat16 g_Vhi[(size_t)Bb*Hh*Ss*Dd];
__device__ __nv_bfloat16 g_Vlo[(size_t)Bb*Hh*Ss*Dd];

// ---------------------------------------------------------------------------
// Helpers (base ISA sm_80+, valid on compute_103)
// ---------------------------------------------------------------------------
__device__ __forceinline__ uint32_t smem_u32(const void* p) {
    uint32_t a;
    asm("{ .reg .u64 t; cvta.to.shared.u64 t, %1; cvt.u32.u64 %0, t; }"
        : "=r"(a) : "l"(p));
    return a;
}

__device__ __forceinline__ void ldsm_x4(uint32_t* r, uint32_t addr) {
    asm volatile("ldmatrix.sync.aligned.m8n8.x4.shared.b16 {%0,%1,%2,%3}, [%4];"
        : "=r"(r[0]), "=r"(r[1]), "=r"(r[2]), "=r"(r[3]) : "r"(addr));
}

__device__ __forceinline__ void ldsm_x4_t(uint32_t* r, uint32_t addr) {
    asm volatile("ldmatrix.sync.aligned.m8n8.x4.trans.shared.b16 {%0,%1,%2,%3}, [%4];"
        : "=r"(r[0]), "=r"(r[1]), "=r"(r[2]), "=r"(r[3]) : "r"(addr));
}

__device__ __forceinline__ void mma16816(float* c, const uint32_t* a, const uint32_t* b) {
    asm volatile(
        "mma.sync.aligned.m16n8k16.row.col.f32.bf16.bf16.f32 "
        "{%0,%1,%2,%3}, {%4,%5,%6,%7}, {%8,%9}, {%0,%1,%2,%3};"
        : "+f"(c[0]), "+f"(c[1]), "+f"(c[2]), "+f"(c[3])
        : "r"(a[0]), "r"(a[1]), "r"(a[2]), "r"(a[3]), "r"(b[0]), "r"(b[1]));
}

#define CP_ASYNC16(dst, src) \
    asm volatile("cp.async.cg.shared.global [%0], [%1], 16;" \
        :: "r"(dst), "l"(src))
#define CP_COMMIT() asm volatile("cp.async.commit_group;")
#define CP_WAIT1()  asm volatile("cp.async.wait_group 1;")
#define CP_WAIT0()  asm volatile("cp.async.wait_group 0;")

// FFMA-pipe exp: 2^(x*log2e), deg-6 poly on [-0.5,0.5], rel err ~1e-6
__device__ __forceinline__ float exp_fast(float x) {
    float t = x * 1.4426950408889634f;
    t = fminf(fmaxf(t, -126.f), 126.f);
    float fi = rintf(t);
    float f  = t - fi;
    int   ei = (int)fi;
    float p = 1.5403530e-4f;
    p = fmaf(p, f, 1.33335581e-3f);
    p = fmaf(p, f, 9.61812911e-3f);
    p = fmaf(p, f, 5.55041087e-2f);
    p = fmaf(p, f, 2.40226507e-1f);
    p = fmaf(p, f, 6.93147181e-1f);
    p = fmaf(p, f, 1.0f);
    return __int_as_float(__float_as_int(p) + (ei << 23));
}

__device__ __forceinline__ ushort bfu(__nv_bfloat16 h) {
    return __bfloat16_as_ushort(h);
}

__device__ __forceinline__ void split4(float4 v, uint2& hi, uint2& lo) {
    __nv_bfloat16 h0 = __float2bfloat16_rn(v.x);
    __nv_bfloat16 h1 = __float2bfloat16_rn(v.y);
    __nv_bfloat16 h2 = __float2bfloat16_rn(v.z);
    __nv_bfloat16 h3 = __float2bfloat16_rn(v.w);
    hi.x = (uint32_t)bfu(h0) | ((uint32_t)bfu(h1) << 16);
    hi.y = (uint32_t)bfu(h2) | ((uint32_t)bfu(h3) << 16);
    __nv_bfloat16 l0 = __float2bfloat16_rn(v.x - __bfloat162float(h0));
    __nv_bfloat16 l1 = __float2bfloat16_rn(v.y - __bfloat162float(h1));
    __nv_bfloat16 l2 = __float2bfloat16_rn(v.z - __bfloat162float(h2));
    __nv_bfloat16 l3 = __float2bfloat16_rn(v.w - __bfloat162float(h3));
    lo.x = (uint32_t)bfu(l0) | ((uint32_t)bfu(l1) << 16);
    lo.y = (uint32_t)bfu(l2) | ((uint32_t)bfu(l3) << 16);
}

__device__ __forceinline__ void pack2(float a, float b, uint32_t& hi, uint32_t& lo) {
    __nv_bfloat16 ha = __float2bfloat16_rn(a);
    __nv_bfloat16 hb = __float2bfloat16_rn(b);
    hi = (uint32_t)bfu(ha) | ((uint32_t)bfu(hb) << 16);
    __nv_bfloat16 la = __float2bfloat16_rn(a - __bfloat162float(ha));
    __nv_bfloat16 lb = __float2bfloat16_rn(b - __bfloat162float(hb));
    lo = (uint32_t)bfu(la) | ((uint32_t)bfu(lb) << 16);
}

// ---------------------------------------------------------------------------
// fp32 -> bf16 hi/lo split.  grid.y selects input (q/k/v); use_ctx reads CTX.
// ---------------------------------------------------------------------------
__global__ __launch_bounds__(256) void convert_split_kernel(
    const float* __restrict__ xq, const float* __restrict__ xk,
    const float* __restrict__ xv, int use_ctx)
{
    int z = blockIdx.y;
    const float* X = use_ctx ? g_CTX : (z == 0 ? xq : (z == 1 ? xk : xv));
    size_t slot = (size_t)z * NTOK * DMm;
    size_t i = ((size_t)blockIdx.x * 256 + threadIdx.x) * 4;
    float4 v = *(const float4*)(X + i);
    uint2 hi, lo;
    split4(v, hi, lo);
    *(uint2*)(g_Xhi + slot + i) = hi;
    *(uint2*)(g_Xlo + slot + i) = lo;
}

// ---------------------------------------------------------------------------
// W [K][N] fp32 -> WT [N][K] bf16 hi/lo.  grid.z selects weight slot.
// ---------------------------------------------------------------------------
__global__ __launch_bounds__(256) void transW_kernel(
    const float* __restrict__ Wq, const float* __restrict__ Wk,
    const float* __restrict__ Wv, const float* __restrict__ Wo)
{
    __shared__ float t[32][33];
    int z = blockIdx.z;
    const float* W = (z == 0) ? Wq : (z == 1) ? Wk : (z == 2) ? Wv : Wo;
    size_t slot = (size_t)z * DMm * DMm;
    int nx = blockIdx.x * 32, ky = blockIdx.y * 32;
    int txx = threadIdx.x, tyy = threadIdx.y;   // block (32, 8)
#pragma unroll
    for (int j = 0; j < 4; j++)
        t[tyy + j*8][txx] = W[(size_t)(ky + tyy + j*8)*DMm + nx + txx];
    __syncthreads();
#pragma unroll
    for (int j = 0; j < 4; j++) {
        float val = t[txx][tyy + j*8];
        __nv_bfloat16 h = __float2bfloat16_rn(val);
        size_t o = slot + (size_t)(nx + tyy + j*8)*DMm + ky + txx;
        g_WThi[o] = h;
        g_WTlo[o] = __float2bfloat16_rn(val - __bfloat162float(h));
    }
}

// ---------------------------------------------------------------------------
// HMMA projection GEMM, cp.async double-buffered.  bf16x3 split.
// grid.z + base_mode selects mode: 0/1/2 -> Q/K/V head-split; 3 -> flat out.
// ---------------------------------------------------------------------------
#define PRS    80                    // smem row stride bytes (40 bf16)
#define P_AHI  0
#define P_ALO  10240
#define P_BHI  20480
#define P_BLO  30720
#define P_SSTR 40960                 // stage stride
#define PROJ_SMEM (2*P_SSTR)         // 81920

__global__ __launch_bounds__(256, 2) void proj_mma_kernel(
    const float* __restrict__ bq, const float* __restrict__ bk,
    const float* __restrict__ bv, float* __restrict__ Yext, int base_mode)
{
    extern __shared__ __align__(16) char psm[];
    uint32_t sb = smem_u32(psm);

    int mode = base_mode + blockIdx.z;
    const float* bias = (blockIdx.z == 0) ? bq : (blockIdx.z == 1) ? bk : bv;

    const __nv_bfloat16* Xhi = g_Xhi + (size_t)(mode == 3 ? 0 : mode) * NTOK * DMm;
    const __nv_bfloat16* Xlo = g_Xlo + (size_t)(mode == 3 ? 0 : mode) * NTOK * DMm;
    const __nv_bfloat16* WThi = g_WThi + (size_t)mode * DMm * DMm;
    const __nv_bfloat16* WTlo = g_WTlo + (size_t)mode * DMm * DMm;

    int tid  = threadIdx.x;
    int lane = tid & 31, wid = tid >> 5;
    int warp_m = wid & 1, warp_n = wid >> 1;
    int row0 = blockIdx.y * 128;
    int col0 = blockIdx.x * 128;

    float acc[4][4][4];
#pragma unroll
    for (int mt = 0; mt < 4; mt++)
#pragma unroll
        for (int nt = 0; nt < 4; nt++)
#pragma unroll
            for (int e = 0; e < 4; e++) acc[mt][nt][e] = 0.f;

    int ld_r = tid >> 1;             // 0..127
    int ld_c = (tid & 1) * 2;        // 16B-chunk pairs

    auto issue = [&](int ch, uint32_t st) {
        int k0 = ch * 32;
#pragma unroll
        for (int cc = 0; cc < 2; cc++) {
            int c = ld_c + cc;
            uint32_t doff = st + (uint32_t)ld_r*PRS + c*16;
            size_t ga = (size_t)(row0 + ld_r)*DMm + k0 + c*8;
            CP_ASYNC16(sb + P_AHI + doff, Xhi + ga);
            CP_ASYNC16(sb + P_ALO + doff, Xlo + ga);
            size_t gb = (size_t)(col0 + ld_r)*DMm + k0 + c*8;
            CP_ASYNC16(sb + P_BHI + doff, WThi + gb);
            CP_ASYNC16(sb + P_BLO + doff, WTlo + gb);
        }
        CP_COMMIT();
    };

    issue(0, 0);

    int a_row = lane & 15;
    int a_kb  = (lane >> 4) * 16;
    int b_row = (lane & 7) + ((lane >> 4) << 3);
    int b_kb  = ((lane >> 3) & 1) * 16;

    for (int ch = 0; ch < 32; ch++) {
        uint32_t st = (uint32_t)(ch & 1) * P_SSTR;
        if (ch + 1 < 32) {
            issue(ch + 1, (uint32_t)((ch + 1) & 1) * P_SSTR);
            CP_WAIT1();
        } else {
            CP_WAIT0();
        }
        __syncthreads();

#pragma unroll
        for (int kk = 0; kk < 2; kk++) {
            int kbyte = kk * 32;
            uint32_t ahi[4][4], alo[4][4];
            uint32_t bhi[4][2], blo[4][2];

#pragma unroll
            for (int mt = 0; mt < 4; mt++) {
                uint32_t ad = sb + st + P_AHI
                            + (uint32_t)(warp_m*64 + mt*16 + a_row)*PRS + kbyte + a_kb;
                ldsm_x4(ahi[mt], ad);
                ldsm_x4(alo[mt], ad + (P_ALO - P_AHI));
            }
#pragma unroll
            for (int p = 0; p < 2; p++) {
                uint32_t bd = sb + st + P_BHI
                            + (uint32_t)(warp_n*32 + p*16 + b_row)*PRS + kbyte + b_kb;
                uint32_t t[4];
                ldsm_x4(t, bd);
                bhi[2*p][0] = t[0]; bhi[2*p][1] = t[1];
                bhi[2*p+1][0] = t[2]; bhi[2*p+1][1] = t[3];
                ldsm_x4(t, bd + (P_BLO - P_BHI));
                blo[2*p][0] = t[0]; blo[2*p][1] = t[1];
                blo[2*p+1][0] = t[2]; blo[2*p+1][1] = t[3];
            }

#pragma unroll
            for (int mt = 0; mt < 4; mt++)
#pragma unroll
                for (int nt = 0; nt < 4; nt++) {
                    mma16816(acc[mt][nt], ahi[mt], bhi[nt]);
                    mma16816(acc[mt][nt], alo[mt], bhi[nt]);
                    mma16816(acc[mt][nt], ahi[mt], blo[nt]);
                }
        }
        __syncthreads();
    }

    int tg = lane >> 2, t4 = lane & 3;
    __nv_bfloat16 *Yhi = nullptr, *Ylo = nullptr;
    if (mode == 0) { Yhi = g_Qhi; Ylo = g_Qlo; }
    else if (mode == 1) { Yhi = g_Khi; Ylo = g_Klo; }
    else if (mode == 2) { Yhi = g_Vhi; Ylo = g_Vlo; }

#pragma unroll
    for (int mt = 0; mt < 4; mt++) {
        int rbase = row0 + warp_m*64 + mt*16 + tg;
#pragma unroll
        for (int nt = 0; nt < 4; nt++) {
            int col = col0 + warp_n*32 + nt*8 + t4*2;
            float b0 = bias[col], b1 = bias[col + 1];
#pragma unroll
            for (int half = 0; half < 2; half++) {
                int r = rbase + half*8;
                float v0 = acc[mt][nt][half*2 + 0] + b0;
                float v1 = acc[mt][nt][half*2 + 1] + b1;
                if (mode == 3) {
                    *(float2*)(Yext + (size_t)r*DMm + col) = make_float2(v0, v1);
                } else {
                    int bi = r >> 11, s = r & (Ss - 1);
                    int h = col >> 6, d = col & 63;
                    size_t off = (((size_t)bi*Hh + h)*Ss + s)*Dd + d;
                    uint32_t hi, lo;
                    pack2(v0, v1, hi, lo);
                    *(uint32_t*)(Yhi + off) = hi;
                    *(uint32_t*)(Ylo + off) = lo;
                }
            }
        }
    }
}

// ---------------------------------------------------------------------------
// Attention smem layout.  RS = 144B row stride (ldmatrix conflict-free).
// ---------------------------------------------------------------------------
#define RS    144
#define SQHI  0
#define SQLO  18432
#define SKHI  36864
#define SKLO  46080
#define SVHI  55296
#define SVLO  64512
#define SMSK1 55296
#define SMSK2 73728
#define SUM_SMEM (SMSK1 + 8192)        // 63488
#define PV_SMEM  (SMSK2 + 8192)        // 81920

#define LOAD_TILE_64(SRC, SOFF)                                              \
    _Pragma("unroll")                                                        \
    for (int i = 0; i < 2; i++) {                                            \
        int f = tid + i*256;              /* 512 uint4 */                    \
        int row = f >> 3, c8 = (f & 7) * 8;                                  \
        *(uint4*)(sm + (SOFF) + row*RS + c8*2) =                             \
            *(const uint4*)((SRC) + (size_t)row*Dd + c8);                    \
    }

// ---------------------------------------------------------------------------
// Pass 1: rowsums of exp(QK^T/8 + mask).  3 CTAs/SM.
// ---------------------------------------------------------------------------
__global__ __launch_bounds__(256, 3) void attn_sum_mma(const float* __restrict__ mask)
{
    extern __shared__ __align__(16) char sm[];
    uint32_t sb = smem_u32(sm);
    float* smask = (float*)(sm + SMSK1);

    int tid  = threadIdx.x;
    int lane = tid & 31, w = tid >> 5;
    int tg = lane >> 2, t4 = lane & 3;
    int qt = blockIdx.x, h = blockIdx.y, b = blockIdx.z;

    size_t hb = ((size_t)b*Hh + h)*Ss;
    const __nv_bfloat16* Qh = g_Qhi + (hb + (size_t)qt*128)*Dd;
    const __nv_bfloat16* Ql = g_Qlo + (hb + (size_t)qt*128)*Dd;
    const __nv_bfloat16* Kh = g_Khi + hb*Dd;
    const __nv_bfloat16* Kl = g_Klo + hb*Dd;

#pragma unroll
    for (int i = 0; i < 2; i++) {
        int f = tid + i*256;
        *(float4*)&smask[f*4] = *(const float4*)(mask + (size_t)b*Ss + f*4);
    }
#pragma unroll
    for (int i = 0; i < 4; i++) {
        int f = tid + i*256;
        int row = f >> 3, c8 = (f & 7) * 8;
        *(uint4*)(sm + SQHI + row*RS + c8*2) = *(const uint4*)(Qh + (size_t)row*Dd + c8);
        *(uint4*)(sm + SQLO + row*RS + c8*2) = *(const uint4*)(Ql + (size_t)row*Dd + c8);
    }
    __syncthreads();

    int a_row = lane & 15;
    int a_kb  = (lane >> 4) * 16;
    int b_row = (lane & 7) + ((lane >> 4) << 3);
    int b_kb  = ((lane >> 3) & 1) * 16;

    float rs0 = 0.f, rs1 = 0.f;

    for (int kt = 0; kt < Ss; kt += 64) {
        __syncthreads();
        LOAD_TILE_64(Kh + (size_t)kt*Dd, SKHI)
        LOAD_TILE_64(Kl + (size_t)kt*Dd, SKLO)
        __syncthreads();

#pragma unroll
        for (int nbp = 0; nbp < 2; nbp++) {
            float accS[4][4];
#pragma unroll
            for (int j = 0; j < 4; j++)
#pragma unroll
                for (int e = 0; e < 4; e++) accS[j][e] = 0.f;

#pragma unroll
            for (int ks = 0; ks < 4; ks++) {
                uint32_t qh[4], ql[4];
                uint32_t qa = sb + SQHI + (uint32_t)(w*16 + a_row)*RS + ks*32 + a_kb;
                ldsm_x4(qh, qa);
                ldsm_x4(ql, qa + (SQLO - SQHI));
#pragma unroll
                for (int nb2 = 0; nb2 < 2; nb2++) {
                    int nb = nbp*2 + nb2;
                    uint32_t th[4], tl[4];
                    uint32_t ad = sb + SKHI + (uint32_t)(nb*16 + b_row)*RS + ks*32 + b_kb;
                    ldsm_x4(th, ad);
                    ldsm_x4(tl, ad + (SKLO - SKHI));
                    int j0 = nb2*2;
                    mma16816(accS[j0],   qh, th);
                    mma16816(accS[j0],   ql, th);
                    mma16816(accS[j0],   qh, tl);
                    mma16816(accS[j0+1], qh, th+2);
                    mma16816(accS[j0+1], ql, th+2);
                    mma16816(accS[j0+1], qh, tl+2);
                }
            }

#pragma unroll
            for (int idx = 0; idx < 4; idx++) {
                int col = (nbp*4 + idx)*8 + t4*2;
                float2 mv = *(float2*)&smask[kt + col];
                float m0 = mv.x * -1e9f, m1 = mv.y * -1e9f;
                rs0 += exp_fast(fmaf(accS[idx][0], 0.125f, m0))
                     + exp_fast(fmaf(accS[idx][1], 0.125f, m1));
                rs1 += exp_fast(fmaf(accS[idx][2], 0.125f, m0))
                     + exp_fast(fmaf(accS[idx][3], 0.125f, m1));
            }
        }
    }

    rs0 += __shfl_xor_sync(0xffffffffu, rs0, 1);
    rs0 += __shfl_xor_sync(0xffffffffu, rs0, 2);
    rs1 += __shfl_xor_sync(0xffffffffu, rs1, 1);
    rs1 += __shfl_xor_sync(0xffffffffu, rs1, 2);
    if (t4 == 0) {
        size_t base = hb + (size_t)qt*128;
        g_SUM[base + w*16 + tg]     = rs0;
        g_SUM[base + w*16 + tg + 8] = rs1;
    }
}

// ---------------------------------------------------------------------------
// Pass 2: recompute QK, p = exp/rowsum, write attn once, O += P V, O -> g_CTX.
// ---------------------------------------------------------------------------
__global__ __launch_bounds__(256, 2) void attn_pv_mma(
    const float* __restrict__ mask, float* __restrict__ attn, int write_attn)
{
    extern __shared__ __align__(16) char sm[];
    uint32_t sb = smem_u32(sm);
    float* smask = (float*)(sm + SMSK2);

    int tid  = threadIdx.x;
    int lane = tid & 31, w = tid >> 5;
    int tg = lane >> 2, t4 = lane & 3;
    int qt = blockIdx.x, h = blockIdx.y, b = blockIdx.z;

    size_t hb = ((size_t)b*Hh + h)*Ss;
    const __nv_bfloat16* Qh = g_Qhi + (hb + (size_t)qt*128)*Dd;
    const __nv_bfloat16* Ql = g_Qlo + (hb + (size_t)qt*128)*Dd;
    const __nv_bfloat16* Kh = g_Khi + hb*Dd;
    const __nv_bfloat16* Kl = g_Klo + hb*Dd;
    const __nv_bfloat16* Vh = g_Vhi + hb*Dd;
    const __nv_bfloat16* Vl = g_Vlo + hb*Dd;
    float* attn_base = attn + (hb + (size_t)qt*128)*Ss;

#pragma unroll
    for (int i = 0; i < 2; i++) {
        int f = tid + i*256;
        *(float4*)&smask[f*4] = *(const float4*)(mask + (size_t)b*Ss + f*4);
    }
#pragma unroll
    for (int i = 0; i < 4; i++) {
        int f = tid + i*256;
        int row = f >> 3, c8 = (f & 7) * 8;
        *(uint4*)(sm + SQHI + row*RS + c8*2) = *(const uint4*)(Qh + (size_t)row*Dd + c8);
        *(uint4*)(sm + SQLO + row*RS + c8*2) = *(const uint4*)(Ql + (size_t)row*Dd + c8);
    }
    __syncthreads();

    int a_row = lane & 15;
    int a_kb  = (lane >> 4) * 16;
    int b_row = (lane & 7) + ((lane >> 4) << 3);
    int b_kb  = ((lane >> 3) & 1) * 16;
    int v_koff = ((lane >> 3) & 1) * 8 + (lane & 7);
    int v_noff = (lane >> 4) * 8;

    size_t base = hb + (size_t)qt*128;
    float rinv0 = 1.0f / g_SUM[base + w*16 + tg];
    float rinv1 = 1.0f / g_SUM[base + w*16 + tg + 8];
    int r0g = w*16 + tg;

    float accO[8][4];
#pragma unroll
    for (int nt = 0; nt < 8; nt++)
#pragma unroll
        for (int e = 0; e < 4; e++) accO[nt][e] = 0.f;

    for (int kt = 0; kt < Ss; kt += 64) {
        __syncthreads();
        LOAD_TILE_64(Kh + (size_t)kt*Dd, SKHI)
        LOAD_TILE_64(Kl + (size_t)kt*Dd, SKLO)
        LOAD_TILE_64(Vh + (size_t)kt*Dd, SVHI)
        LOAD_TILE_64(Vl + (size_t)kt*Dd, SVLO)
        __syncthreads();

#pragma unroll
        for (int nbp = 0; nbp < 2; nbp++) {
            float accS[4][4];
#pragma unroll
            for (int j = 0; j < 4; j++)
#pragma unroll
                for (int e = 0; e < 4; e++) accS[j][e] = 0.f;

#pragma unroll
            for (int ks = 0; ks < 4; ks++) {
                uint32_t qh[4], ql[4];
                uint32_t qa = sb + SQHI + (uint32_t)(w*16 + a_row)*RS + ks*32 + a_kb;
                ldsm_x4(qh, qa);
                ldsm_x4(ql, qa + (SQLO - SQHI));
#pragma unroll
                for (int nb2 = 0; nb2 < 2; nb2++) {
                    int nb = nbp*2 + nb2;
                    uint32_t th[4], tl[4];
                    uint32_t ad = sb + SKHI + (uint32_t)(nb*16 + b_row)*RS + ks*32 + b_kb;
                    ldsm_x4(th, ad);
                    ldsm_x4(tl, ad + (SKLO - SKHI));
                    int j0 = nb2*2;
                    mma16816(accS[j0],   qh, th);
                    mma16816(accS[j0],   ql, th);
                    mma16816(accS[j0],   qh, tl);
                    mma16816(accS[j0+1], qh, th+2);
                    mma16816(accS[j0+1], ql, th+2);
                    mma16816(accS[j0+1], qh, tl+2);
                }
            }

            uint32_t ph0[4], ph1[4], pl0[4], pl1[4];
#pragma unroll
            for (int idx = 0; idx < 4; idx++) {
                int col = (nbp*4 + idx)*8 + t4*2;
                float2 mv = *(float2*)&smask[kt + col];
                float m0 = mv.x * -1e9f, m1 = mv.y * -1e9f;
                float p0 = exp_fast(fmaf(accS[idx][0], 0.125f, m0)) * rinv0;
                float p1 = exp_fast(fmaf(accS[idx][1], 0.125f, m1)) * rinv0;
                float p2 = exp_fast(fmaf(accS[idx][2], 0.125f, m0)) * rinv1;
                float p3 = exp_fast(fmaf(accS[idx][3], 0.125f, m1)) * rinv1;
                if (write_attn) {
                    *(float2*)&attn_base[(size_t)r0g*Ss + kt + col]       = make_float2(p0, p1);
                    *(float2*)&attn_base[(size_t)(r0g + 8)*Ss + kt + col] = make_float2(p2, p3);
                }
                pack2(p0, p1, ph0[idx], pl0[idx]);
                pack2(p2, p3, ph1[idx], pl1[idx]);
            }

#pragma unroll
            for (int nb2 = 0; nb2 < 2; nb2++) {
                int ksv = nbp*2 + nb2;
                uint32_t ah[4] = {ph0[2*nb2], ph1[2*nb2], ph0[2*nb2+1], ph1[2*nb2+1]};
                uint32_t al[4] = {pl0[2*nb2], pl1[2*nb2], pl0[2*nb2+1], pl1[2*nb2+1]};
#pragma unroll
                for (int vb = 0; vb < 4; vb++) {
                    uint32_t th[4], tl[4];
                    uint32_t ad = sb + SVHI + (uint32_t)(ksv*16 + v_koff)*RS
                                + (vb*16 + v_noff)*2;
                    ldsm_x4_t(th, ad);
                    ldsm_x4_t(tl, ad + (SVLO - SVHI));
                    int nt0 = vb*2;
                    mma16816(accO[nt0],   ah, th);
                    mma16816(accO[nt0],   al, th);
                    mma16816(accO[nt0],   ah, tl);
                    mma16816(accO[nt0+1], ah, th+2);
                    mma16816(accO[nt0+1], al, th+2);
                    mma16816(accO[nt0+1], ah, tl+2);
                }
            }
        }
    }

    int q0 = qt*128 + w*16 + tg;
#pragma unroll
    for (int nt = 0; nt < 8; nt++) {
        int d = nt*8 + t4*2;
        float* c0 = g_CTX + ((size_t)b*Ss + q0)*DMm + h*64 + d;
        *(float2*)c0 = make_float2(accO[nt][0], accO[nt][1]);
        float* c1 = g_CTX + ((size_t)b*Ss + q0 + 8)*DMm + h*64 + d;
        *(float2*)c1 = make_float2(accO[nt][2], accO[nt][3]);
    }
}

// ---------------------------------------------------------------------------
// Launch
// ---------------------------------------------------------------------------
extern "C" void kernel_launch(void* const* d_in, const int* in_sizes, int n_in,
                              void* d_out, int out_size)
{
    const float* q    = (const float*)d_in[0];
    const float* k    = (const float*)d_in[1];
    const float* v    = (const float*)d_in[2];
    const float* mask = (const float*)d_in[3];
    const float* Wq   = (const float*)d_in[4];
    const float* bq   = (const float*)d_in[5];
    const float* Wk   = (const float*)d_in[6];
    const float* bk   = (const float*)d_in[7];
    const float* Wv   = (const float*)d_in[8];
    const float* bv   = (const float*)d_in[9];
    const float* Wo   = (const float*)d_in[10];
    const float* bo   = (const float*)d_in[11];

    float* out  = (float*)d_out;
    float* attn = out + (size_t)NTOK*DMm;

    long long need = (long long)NTOK*DMm + (long long)Bb*Hh*Ss*Ss;
    int write_attn = ((long long)out_size >= need) ? 1 : 0;

    cudaFuncSetAttribute(proj_mma_kernel,
                         cudaFuncAttributeMaxDynamicSharedMemorySize, PROJ_SMEM);
    cudaFuncSetAttribute(attn_sum_mma,
                         cudaFuncAttributeMaxDynamicSharedMemorySize, SUM_SMEM);
    cudaFuncSetAttribute(attn_pv_mma,
                         cudaFuncAttributeMaxDynamicSharedMemorySize, PV_SMEM);

    dim3 cgrid((NTOK*DMm)/(256*4), 3);
    convert_split_kernel<<<cgrid, 256>>>(q, k, v, 0);
    dim3 tgrid(DMm/32, DMm/32, 4);
    transW_kernel<<<tgrid, dim3(32, 8)>>>(Wq, Wk, Wv, Wo);

    dim3 ggrid3(DMm/128, NTOK/128, 3);
    proj_mma_kernel<<<ggrid3, 256, PROJ_SMEM>>>(bq, bk, bv, nullptr, 0);

    dim3 agrid(Ss/128, Hh, Bb);
    attn_sum_mma<<<agrid, 256, SUM_SMEM>>>(mask);
    attn_pv_mma<<<agrid, 256, PV_SMEM>>>(mask, attn, write_attn);

    dim3 cgrid1((NTOK*DMm)/(256*4), 1);
    convert_split_kernel<<<cgrid1, 256>>>(nullptr, nullptr, nullptr, 1);
    dim3 ggrid1(DMm/128, NTOK/128, 1);
    proj_mma_kernel<<<ggrid1, 256, PROJ_SMEM>>>(bo, bo, bo, out, 3);
}

// round 11
// speedup vs baseline: 2.3077x; 1.0738x over previous
#include <cuda_runtime.h>
#include <cuda_bf16.h>
#include <cstdint>

#define DMm  1024
#define Hh   16
#define Dd   64
#define Bb   2
#define Ss   2048
#define NTOK (Bb*Ss)   // 4096

// ---------------------------------------------------------------------------
// Static device scratch
// ---------------------------------------------------------------------------
__device__ float g_CTX[(size_t)NTOK*DMm];
__device__ float g_SUM[(size_t)Bb*Hh*Ss];
__device__ __nv_bfloat16 g_Xhi [(size_t)3*NTOK*DMm];
__device__ __nv_bfloat16 g_Xlo [(size_t)3*NTOK*DMm];
__device__ __nv_bfloat16 g_WThi[(size_t)4*DMm*DMm];
__device__ __nv_bfloat16 g_WTlo[(size_t)4*DMm*DMm];
__device__ __nv_bfloat16 g_Qhi[(size_t)Bb*Hh*Ss*Dd];
__device__ __nv_bfloat16 g_Qlo[(size_t)Bb*Hh*Ss*Dd];
__device__ __nv_bfloat16 g_Khi[(size_t)Bb*Hh*Ss*Dd];
__device__ __nv_bfloat16 g_Klo[(size_t)Bb*Hh*Ss*Dd];
__device__ __nv_bfloat16 g_Vhi[(size_t)Bb*Hh*Ss*Dd];
__device__ __nv_bfloat16 g_Vlo[(size_t)Bb*Hh*Ss*Dd];

// ---------------------------------------------------------------------------
// Helpers (base ISA sm_80+, valid on compute_103)
// ---------------------------------------------------------------------------
__device__ __forceinline__ uint32_t smem_u32(const void* p) {
    uint32_t a;
    asm("{ .reg .u64 t; cvta.to.shared.u64 t, %1; cvt.u32.u64 %0, t; }"
        : "=r"(a) : "l"(p));
    return a;
}

__device__ __forceinline__ void ldsm_x4(uint32_t* r, uint32_t addr) {
    asm volatile("ldmatrix.sync.aligned.m8n8.x4.shared.b16 {%0,%1,%2,%3}, [%4];"
        : "=r"(r[0]), "=r"(r[1]), "=r"(r[2]), "=r"(r[3]) : "r"(addr));
}

__device__ __forceinline__ void ldsm_x4_t(uint32_t* r, uint32_t addr) {
    asm volatile("ldmatrix.sync.aligned.m8n8.x4.trans.shared.b16 {%0,%1,%2,%3}, [%4];"
        : "=r"(r[0]), "=r"(r[1]), "=r"(r[2]), "=r"(r[3]) : "r"(addr));
}

__device__ __forceinline__ void mma16816(float* c, const uint32_t* a, const uint32_t* b) {
    asm volatile(
        "mma.sync.aligned.m16n8k16.row.col.f32.bf16.bf16.f32 "
        "{%0,%1,%2,%3}, {%4,%5,%6,%7}, {%8,%9}, {%0,%1,%2,%3};"
        : "+f"(c[0]), "+f"(c[1]), "+f"(c[2]), "+f"(c[3])
        : "r"(a[0]), "r"(a[1]), "r"(a[2]), "r"(a[3]), "r"(b[0]), "r"(b[1]));
}

#define CP_ASYNC16(dst, src) \
    asm volatile("cp.async.cg.shared.global [%0], [%1], 16;" \
        :: "r"(dst), "l"(src))
#define CP_COMMIT() asm volatile("cp.async.commit_group;")
#define CP_WAIT1()  asm volatile("cp.async.wait_group 1;")
#define CP_WAIT0()  asm volatile("cp.async.wait_group 0;")

// FFMA-pipe exp: 2^(x*log2e), deg-6 poly on [-0.5,0.5], rel err ~1e-6
__device__ __forceinline__ float exp_fast(float x) {
    float t = x * 1.4426950408889634f;
    t = fminf(fmaxf(t, -126.f), 126.f);
    float fi = rintf(t);
    float f  = t - fi;
    int   ei = (int)fi;
    float p = 1.5403530e-4f;
    p = fmaf(p, f, 1.33335581e-3f);
    p = fmaf(p, f, 9.61812911e-3f);
    p = fmaf(p, f, 5.55041087e-2f);
    p = fmaf(p, f, 2.40226507e-1f);
    p = fmaf(p, f, 6.93147181e-1f);
    p = fmaf(p, f, 1.0f);
    return __int_as_float(__float_as_int(p) + (ei << 23));
}

__device__ __forceinline__ ushort bfu(__nv_bfloat16 h) {
    return __bfloat16_as_ushort(h);
}

__device__ __forceinline__ void split4(float4 v, uint2& hi, uint2& lo) {
    __nv_bfloat16 h0 = __float2bfloat16_rn(v.x);
    __nv_bfloat16 h1 = __float2bfloat16_rn(v.y);
    __nv_bfloat16 h2 = __float2bfloat16_rn(v.z);
    __nv_bfloat16 h3 = __float2bfloat16_rn(v.w);
    hi.x = (uint32_t)bfu(h0) | ((uint32_t)bfu(h1) << 16);
    hi.y = (uint32_t)bfu(h2) | ((uint32_t)bfu(h3) << 16);
    __nv_bfloat16 l0 = __float2bfloat16_rn(v.x - __bfloat162float(h0));
    __nv_bfloat16 l1 = __float2bfloat16_rn(v.y - __bfloat162float(h1));
    __nv_bfloat16 l2 = __float2bfloat16_rn(v.z - __bfloat162float(h2));
    __nv_bfloat16 l3 = __float2bfloat16_rn(v.w - __bfloat162float(h3));
    lo.x = (uint32_t)bfu(l0) | ((uint32_t)bfu(l1) << 16);
    lo.y = (uint32_t)bfu(l2) | ((uint32_t)bfu(l3) << 16);
}

__device__ __forceinline__ void pack2(float a, float b, uint32_t& hi, uint32_t& lo) {
    __nv_bfloat16 ha = __float2bfloat16_rn(a);
    __nv_bfloat16 hb = __float2bfloat16_rn(b);
    hi = (uint32_t)bfu(ha) | ((uint32_t)bfu(hb) << 16);
    __nv_bfloat16 la = __float2bfloat16_rn(a - __bfloat162float(ha));
    __nv_bfloat16 lb = __float2bfloat16_rn(b - __bfloat162float(hb));
    lo = (uint32_t)bfu(la) | ((uint32_t)bfu(lb) << 16);
}

// ---------------------------------------------------------------------------
// fp32 -> bf16 hi/lo split.  grid.y selects input (q/k/v); use_ctx reads CTX.
// ---------------------------------------------------------------------------
__global__ __launch_bounds__(256) void convert_split_kernel(
    const float* __restrict__ xq, const float* __restrict__ xk,
    const float* __restrict__ xv, int use_ctx)
{
    int z = blockIdx.y;
    const float* X = use_ctx ? g_CTX : (z == 0 ? xq : (z == 1 ? xk : xv));
    size_t slot = (size_t)z * NTOK * DMm;
    size_t i = ((size_t)blockIdx.x * 256 + threadIdx.x) * 4;
    float4 v = *(const float4*)(X + i);
    uint2 hi, lo;
    split4(v, hi, lo);
    *(uint2*)(g_Xhi + slot + i) = hi;
    *(uint2*)(g_Xlo + slot + i) = lo;
}

// ---------------------------------------------------------------------------
// W [K][N] fp32 -> WT [N][K] bf16 hi/lo.  grid.z selects weight slot.
// ---------------------------------------------------------------------------
__global__ __launch_bounds__(256) void transW_kernel(
    const float* __restrict__ Wq, const float* __restrict__ Wk,
    const float* __restrict__ Wv, const float* __restrict__ Wo)
{
    __shared__ float t[32][33];
    int z = blockIdx.z;
    const float* W = (z == 0) ? Wq : (z == 1) ? Wk : (z == 2) ? Wv : Wo;
    size_t slot = (size_t)z * DMm * DMm;
    int nx = blockIdx.x * 32, ky = blockIdx.y * 32;
    int txx = threadIdx.x, tyy = threadIdx.y;   // block (32, 8)
#pragma unroll
    for (int j = 0; j < 4; j++)
        t[tyy + j*8][txx] = W[(size_t)(ky + tyy + j*8)*DMm + nx + txx];
    __syncthreads();
#pragma unroll
    for (int j = 0; j < 4; j++) {
        float val = t[txx][tyy + j*8];
        __nv_bfloat16 h = __float2bfloat16_rn(val);
        size_t o = slot + (size_t)(nx + tyy + j*8)*DMm + ky + txx;
        g_WThi[o] = h;
        g_WTlo[o] = __float2bfloat16_rn(val - __bfloat162float(h));
    }
}

// ---------------------------------------------------------------------------
// HMMA projection GEMM, cp.async double-buffered.  bf16x3 split.
// ---------------------------------------------------------------------------
#define PRS    80
#define P_AHI  0
#define P_ALO  10240
#define P_BHI  20480
#define P_BLO  30720
#define P_SSTR 40960
#define PROJ_SMEM (2*P_SSTR)         // 81920

__global__ __launch_bounds__(256, 2) void proj_mma_kernel(
    const float* __restrict__ bq, const float* __restrict__ bk,
    const float* __restrict__ bv, float* __restrict__ Yext, int base_mode)
{
    extern __shared__ __align__(16) char psm[];
    uint32_t sb = smem_u32(psm);

    int mode = base_mode + blockIdx.z;
    const float* bias = (blockIdx.z == 0) ? bq : (blockIdx.z == 1) ? bk : bv;

    const __nv_bfloat16* Xhi = g_Xhi + (size_t)(mode == 3 ? 0 : mode) * NTOK * DMm;
    const __nv_bfloat16* Xlo = g_Xlo + (size_t)(mode == 3 ? 0 : mode) * NTOK * DMm;
    const __nv_bfloat16* WThi = g_WThi + (size_t)mode * DMm * DMm;
    const __nv_bfloat16* WTlo = g_WTlo + (size_t)mode * DMm * DMm;

    int tid  = threadIdx.x;
    int lane = tid & 31, wid = tid >> 5;
    int warp_m = wid & 1, warp_n = wid >> 1;
    int row0 = blockIdx.y * 128;
    int col0 = blockIdx.x * 128;

    float acc[4][4][4];
#pragma unroll
    for (int mt = 0; mt < 4; mt++)
#pragma unroll
        for (int nt = 0; nt < 4; nt++)
#pragma unroll
            for (int e = 0; e < 4; e++) acc[mt][nt][e] = 0.f;

    int ld_r = tid >> 1;
    int ld_c = (tid & 1) * 2;

    auto issue = [&](int ch, uint32_t st) {
        int k0 = ch * 32;
#pragma unroll
        for (int cc = 0; cc < 2; cc++) {
            int c = ld_c + cc;
            uint32_t doff = st + (uint32_t)ld_r*PRS + c*16;
            size_t ga = (size_t)(row0 + ld_r)*DMm + k0 + c*8;
            CP_ASYNC16(sb + P_AHI + doff, Xhi + ga);
            CP_ASYNC16(sb + P_ALO + doff, Xlo + ga);
            size_t gb = (size_t)(col0 + ld_r)*DMm + k0 + c*8;
            CP_ASYNC16(sb + P_BHI + doff, WThi + gb);
            CP_ASYNC16(sb + P_BLO + doff, WTlo + gb);
        }
        CP_COMMIT();
    };

    issue(0, 0);

    int a_row = lane & 15;
    int a_kb  = (lane >> 4) * 16;
    int b_row = (lane & 7) + ((lane >> 4) << 3);
    int b_kb  = ((lane >> 3) & 1) * 16;

    for (int ch = 0; ch < 32; ch++) {
        uint32_t st = (uint32_t)(ch & 1) * P_SSTR;
        if (ch + 1 < 32) {
            issue(ch + 1, (uint32_t)((ch + 1) & 1) * P_SSTR);
            CP_WAIT1();
        } else {
            CP_WAIT0();
        }
        __syncthreads();

#pragma unroll
        for (int kk = 0; kk < 2; kk++) {
            int kbyte = kk * 32;
            uint32_t ahi[4][4], alo[4][4];
            uint32_t bhi[4][2], blo[4][2];

#pragma unroll
            for (int mt = 0; mt < 4; mt++) {
                uint32_t ad = sb + st + P_AHI
                            + (uint32_t)(warp_m*64 + mt*16 + a_row)*PRS + kbyte + a_kb;
                ldsm_x4(ahi[mt], ad);
                ldsm_x4(alo[mt], ad + (P_ALO - P_AHI));
            }
#pragma unroll
            for (int p = 0; p < 2; p++) {
                uint32_t bd = sb + st + P_BHI
                            + (uint32_t)(warp_n*32 + p*16 + b_row)*PRS + kbyte + b_kb;
                uint32_t t[4];
                ldsm_x4(t, bd);
                bhi[2*p][0] = t[0]; bhi[2*p][1] = t[1];
                bhi[2*p+1][0] = t[2]; bhi[2*p+1][1] = t[3];
                ldsm_x4(t, bd + (P_BLO - P_BHI));
                blo[2*p][0] = t[0]; blo[2*p][1] = t[1];
                blo[2*p+1][0] = t[2]; blo[2*p+1][1] = t[3];
            }

#pragma unroll
            for (int mt = 0; mt < 4; mt++)
#pragma unroll
                for (int nt = 0; nt < 4; nt++) {
                    mma16816(acc[mt][nt], ahi[mt], bhi[nt]);
                    mma16816(acc[mt][nt], alo[mt], bhi[nt]);
                    mma16816(acc[mt][nt], ahi[mt], blo[nt]);
                }
        }
        __syncthreads();
    }

    int tg = lane >> 2, t4 = lane & 3;
    __nv_bfloat16 *Yhi = nullptr, *Ylo = nullptr;
    if (mode == 0) { Yhi = g_Qhi; Ylo = g_Qlo; }
    else if (mode == 1) { Yhi = g_Khi; Ylo = g_Klo; }
    else if (mode == 2) { Yhi = g_Vhi; Ylo = g_Vlo; }

#pragma unroll
    for (int mt = 0; mt < 4; mt++) {
        int rbase = row0 + warp_m*64 + mt*16 + tg;
#pragma unroll
        for (int nt = 0; nt < 4; nt++) {
            int col = col0 + warp_n*32 + nt*8 + t4*2;
            float b0 = bias[col], b1 = bias[col + 1];
#pragma unroll
            for (int half = 0; half < 2; half++) {
                int r = rbase + half*8;
                float v0 = acc[mt][nt][half*2 + 0] + b0;
                float v1 = acc[mt][nt][half*2 + 1] + b1;
                if (mode == 3) {
                    *(float2*)(Yext + (size_t)r*DMm + col) = make_float2(v0, v1);
                } else {
                    int bi = r >> 11, s = r & (Ss - 1);
                    int h = col >> 6, d = col & 63;
                    size_t off = (((size_t)bi*Hh + h)*Ss + s)*Dd + d;
                    uint32_t hi, lo;
                    pack2(v0, v1, hi, lo);
                    *(uint32_t*)(Yhi + off) = hi;
                    *(uint32_t*)(Ylo + off) = lo;
                }
            }
        }
    }
}

// ---------------------------------------------------------------------------
// Attention smem layouts.  RS = 144B row stride (ldmatrix conflict-free).
// ---------------------------------------------------------------------------
#define RS    144
// pass 1 (hi-only): Qhi + Khi + mask
#define S1QHI 0
#define S1KHI 18432
#define S1MSK 27648
#define SUM_SMEM (S1MSK + 8192)        // 35840
// pass 2: Qhi/Qlo + Khi/Klo + Vhi/Vlo + mask
#define SQHI  0
#define SQLO  18432
#define SKHI  36864
#define SKLO  46080
#define SVHI  55296
#define SVLO  64512
#define SMSK2 73728
#define PV_SMEM  (SMSK2 + 8192)        // 81920

// 64-row tile (512 uint4), element-indexed: row stride Dd=64 bf16
#define LOAD_TILE_64(SRC, SOFF)                                              \
    _Pragma("unroll")                                                        \
    for (int i = 0; i < 2; i++) {                                            \
        int f = tid + i*256;              /* 512 uint4 */                    \
        int row = f >> 3, c8 = (f & 7) * 8;                                  \
        *(uint4*)(sm + (SOFF) + row*RS + c8*2) =                             \
            *(const uint4*)((SRC) + (size_t)row*Dd + c8);                    \
    }

// 128-row tile (1024 uint4), same pattern
#define LOAD_TILE_128(SRC, SOFF)                                             \
    _Pragma("unroll")                                                        \
    for (int i = 0; i < 4; i++) {                                            \
        int f = tid + i*256;              /* 1024 uint4 */                   \
        int row = f >> 3, c8 = (f & 7) * 8;                                  \
        *(uint4*)(sm + (SOFF) + row*RS + c8*2) =                             \
            *(const uint4*)((SRC) + (size_t)row*Dd + c8);                    \
    }

// ---------------------------------------------------------------------------
// Pass 1: rowsums of exp(QK^T/8 + mask), HI-ONLY QK (1 MMA per product).
// Per-logit delta ~3.5e-3 averages to ~8e-5 on the 2048-key denominator;
// pass 2 keeps full bf16x3 for the normalized attn values and O.
// ---------------------------------------------------------------------------
__global__ __launch_bounds__(256, 3) void attn_sum_mma(const float* __restrict__ mask)
{
    extern __shared__ __align__(16) char sm[];
    uint32_t sb = smem_u32(sm);
    float* smask = (float*)(sm + S1MSK);

    int tid  = threadIdx.x;
    int lane = tid & 31, w = tid >> 5;
    int tg = lane >> 2, t4 = lane & 3;
    int qt = blockIdx.x, h = blockIdx.y, b = blockIdx.z;

    size_t hb = ((size_t)b*Hh + h)*Ss;
    const __nv_bfloat16* Qh = g_Qhi + (hb + (size_t)qt*128)*Dd;
    const __nv_bfloat16* Kh = g_Khi + hb*Dd;

#pragma unroll
    for (int i = 0; i < 2; i++) {
        int f = tid + i*256;
        *(float4*)&smask[f*4] = *(const float4*)(mask + (size_t)b*Ss + f*4);
    }
    LOAD_TILE_128(Qh, S1QHI)
    __syncthreads();

    int a_row = lane & 15;
    int a_kb  = (lane >> 4) * 16;
    int b_row = (lane & 7) + ((lane >> 4) << 3);
    int b_kb  = ((lane >> 3) & 1) * 16;

    float rs0 = 0.f, rs1 = 0.f;

    for (int kt = 0; kt < Ss; kt += 64) {
        __syncthreads();
        LOAD_TILE_64(Kh + (size_t)kt*Dd, S1KHI)
        __syncthreads();

#pragma unroll
        for (int nbp = 0; nbp < 2; nbp++) {
            float accS[4][4];
#pragma unroll
            for (int j = 0; j < 4; j++)
#pragma unroll
                for (int e = 0; e < 4; e++) accS[j][e] = 0.f;

#pragma unroll
            for (int ks = 0; ks < 4; ks++) {
                uint32_t qh[4];
                uint32_t qa = sb + S1QHI + (uint32_t)(w*16 + a_row)*RS + ks*32 + a_kb;
                ldsm_x4(qh, qa);
#pragma unroll
                for (int nb2 = 0; nb2 < 2; nb2++) {
                    int nb = nbp*2 + nb2;
                    uint32_t th[4];
                    uint32_t ad = sb + S1KHI + (uint32_t)(nb*16 + b_row)*RS + ks*32 + b_kb;
                    ldsm_x4(th, ad);
                    int j0 = nb2*2;
                    mma16816(accS[j0],   qh, th);
                    mma16816(accS[j0+1], qh, th+2);
                }
            }

#pragma unroll
            for (int idx = 0; idx < 4; idx++) {
                int col = (nbp*4 + idx)*8 + t4*2;
                float2 mv = *(float2*)&smask[kt + col];
                float m0 = mv.x * -1e9f, m1 = mv.y * -1e9f;
                rs0 += exp_fast(fmaf(accS[idx][0], 0.125f, m0))
                     + exp_fast(fmaf(accS[idx][1], 0.125f, m1));
                rs1 += exp_fast(fmaf(accS[idx][2], 0.125f, m0))
                     + exp_fast(fmaf(accS[idx][3], 0.125f, m1));
            }
        }
    }

    rs0 += __shfl_xor_sync(0xffffffffu, rs0, 1);
    rs0 += __shfl_xor_sync(0xffffffffu, rs0, 2);
    rs1 += __shfl_xor_sync(0xffffffffu, rs1, 1);
    rs1 += __shfl_xor_sync(0xffffffffu, rs1, 2);
    if (t4 == 0) {
        size_t base = hb + (size_t)qt*128;
        g_SUM[base + w*16 + tg]     = rs0;
        g_SUM[base + w*16 + tg + 8] = rs1;
    }
}

// ---------------------------------------------------------------------------
// Pass 2: recompute QK (bf16x3), p = exp/rowsum, write attn once,
// O += P V (bf16x3), O -> g_CTX.
// ---------------------------------------------------------------------------
__global__ __launch_bounds__(256, 2) void attn_pv_mma(
    const float* __restrict__ mask, float* __restrict__ attn, int write_attn)
{
    extern __shared__ __align__(16) char sm[];
    uint32_t sb = smem_u32(sm);
    float* smask = (float*)(sm + SMSK2);

    int tid  = threadIdx.x;
    int lane = tid & 31, w = tid >> 5;
    int tg = lane >> 2, t4 = lane & 3;
    int qt = blockIdx.x, h = blockIdx.y, b = blockIdx.z;

    size_t hb = ((size_t)b*Hh + h)*Ss;
    const __nv_bfloat16* Qh = g_Qhi + (hb + (size_t)qt*128)*Dd;
    const __nv_bfloat16* Ql = g_Qlo + (hb + (size_t)qt*128)*Dd;
    const __nv_bfloat16* Kh = g_Khi + hb*Dd;
    const __nv_bfloat16* Kl = g_Klo + hb*Dd;
    const __nv_bfloat16* Vh = g_Vhi + hb*Dd;
    const __nv_bfloat16* Vl = g_Vlo + hb*Dd;
    float* attn_base = attn + (hb + (size_t)qt*128)*Ss;

#pragma unroll
    for (int i = 0; i < 2; i++) {
        int f = tid + i*256;
        *(float4*)&smask[f*4] = *(const float4*)(mask + (size_t)b*Ss + f*4);
    }
    LOAD_TILE_128(Qh, SQHI)
    LOAD_TILE_128(Ql, SQLO)
    __syncthreads();

    int a_row = lane & 15;
    int a_kb  = (lane >> 4) * 16;
    int b_row = (lane & 7) + ((lane >> 4) << 3);
    int b_kb  = ((lane >> 3) & 1) * 16;
    int v_koff = ((lane >> 3) & 1) * 8 + (lane & 7);
    int v_noff = (lane >> 4) * 8;

    size_t base = hb + (size_t)qt*128;
    float rinv0 = 1.0f / g_SUM[base + w*16 + tg];
    float rinv1 = 1.0f / g_SUM[base + w*16 + tg + 8];
    int r0g = w*16 + tg;

    float accO[8][4];
#pragma unroll
    for (int nt = 0; nt < 8; nt++)
#pragma unroll
        for (int e = 0; e < 4; e++) accO[nt][e] = 0.f;

    for (int kt = 0; kt < Ss; kt += 64) {
        __syncthreads();
        LOAD_TILE_64(Kh + (size_t)kt*Dd, SKHI)
        LOAD_TILE_64(Kl + (size_t)kt*Dd, SKLO)
        LOAD_TILE_64(Vh + (size_t)kt*Dd, SVHI)
        LOAD_TILE_64(Vl + (size_t)kt*Dd, SVLO)
        __syncthreads();

#pragma unroll
        for (int nbp = 0; nbp < 2; nbp++) {
            float accS[4][4];
#pragma unroll
            for (int j = 0; j < 4; j++)
#pragma unroll
                for (int e = 0; e < 4; e++) accS[j][e] = 0.f;

#pragma unroll
            for (int ks = 0; ks < 4; ks++) {
                uint32_t qh[4], ql[4];
                uint32_t qa = sb + SQHI + (uint32_t)(w*16 + a_row)*RS + ks*32 + a_kb;
                ldsm_x4(qh, qa);
                ldsm_x4(ql, qa + (SQLO - SQHI));
#pragma unroll
                for (int nb2 = 0; nb2 < 2; nb2++) {
                    int nb = nbp*2 + nb2;
                    uint32_t th[4], tl[4];
                    uint32_t ad = sb + SKHI + (uint32_t)(nb*16 + b_row)*RS + ks*32 + b_kb;
                    ldsm_x4(th, ad);
                    ldsm_x4(tl, ad + (SKLO - SKHI));
                    int j0 = nb2*2;
                    mma16816(accS[j0],   qh, th);
                    mma16816(accS[j0],   ql, th);
                    mma16816(accS[j0],   qh, tl);
                    mma16816(accS[j0+1], qh, th+2);
                    mma16816(accS[j0+1], ql, th+2);
                    mma16816(accS[j0+1], qh, tl+2);
                }
            }

            uint32_t ph0[4], ph1[4], pl0[4], pl1[4];
#pragma unroll
            for (int idx = 0; idx < 4; idx++) {
                int col = (nbp*4 + idx)*8 + t4*2;
                float2 mv = *(float2*)&smask[kt + col];
                float m0 = mv.x * -1e9f, m1 = mv.y * -1e9f;
                float p0 = exp_fast(fmaf(accS[idx][0], 0.125f, m0)) * rinv0;
                float p1 = exp_fast(fmaf(accS[idx][1], 0.125f, m1)) * rinv0;
                float p2 = exp_fast(fmaf(accS[idx][2], 0.125f, m0)) * rinv1;
                float p3 = exp_fast(fmaf(accS[idx][3], 0.125f, m1)) * rinv1;
                if (write_attn) {
                    *(float2*)&attn_base[(size_t)r0g*Ss + kt + col]       = make_float2(p0, p1);
                    *(float2*)&attn_base[(size_t)(r0g + 8)*Ss + kt + col] = make_float2(p2, p3);
                }
                pack2(p0, p1, ph0[idx], pl0[idx]);
                pack2(p2, p3, ph1[idx], pl1[idx]);
            }

#pragma unroll
            for (int nb2 = 0; nb2 < 2; nb2++) {
                int ksv = nbp*2 + nb2;
                uint32_t ah[4] = {ph0[2*nb2], ph1[2*nb2], ph0[2*nb2+1], ph1[2*nb2+1]};
                uint32_t al[4] = {pl0[2*nb2], pl1[2*nb2], pl0[2*nb2+1], pl1[2*nb2+1]};
#pragma unroll
                for (int vb = 0; vb < 4; vb++) {
                    uint32_t th[4], tl[4];
                    uint32_t ad = sb + SVHI + (uint32_t)(ksv*16 + v_koff)*RS
                                + (vb*16 + v_noff)*2;
                    ldsm_x4_t(th, ad);
                    ldsm_x4_t(tl, ad + (SVLO - SVHI));
                    int nt0 = vb*2;
                    mma16816(accO[nt0],   ah, th);
                    mma16816(accO[nt0],   al, th);
                    mma16816(accO[nt0],   ah, tl);
                    mma16816(accO[nt0+1], ah, th+2);
                    mma16816(accO[nt0+1], al, th+2);
                    mma16816(accO[nt0+1], ah, tl+2);
                }
            }
        }
    }

    int q0 = qt*128 + w*16 + tg;
#pragma unroll
    for (int nt = 0; nt < 8; nt++) {
        int d = nt*8 + t4*2;
        float* c0 = g_CTX + ((size_t)b*Ss + q0)*DMm + h*64 + d;
        *(float2*)c0 = make_float2(accO[nt][0], accO[nt][1]);
        float* c1 = g_CTX + ((size_t)b*Ss + q0 + 8)*DMm + h*64 + d;
        *(float2*)c1 = make_float2(accO[nt][2], accO[nt][3]);
    }
}

// ---------------------------------------------------------------------------
// Launch
// ---------------------------------------------------------------------------
extern "C" void kernel_launch(void* const* d_in, const int* in_sizes, int n_in,
                              void* d_out, int out_size)
{
    const float* q    = (const float*)d_in[0];
    const float* k    = (const float*)d_in[1];
    const float* v    = (const float*)d_in[2];
    const float* mask = (const float*)d_in[3];
    const float* Wq   = (const float*)d_in[4];
    const float* bq   = (const float*)d_in[5];
    const float* Wk   = (const float*)d_in[6];
    const float* bk   = (const float*)d_in[7];
    const float* Wv   = (const float*)d_in[8];
    const float* bv   = (const float*)d_in[9];
    const float* Wo   = (const float*)d_in[10];
    const float* bo   = (const float*)d_in[11];

    float* out  = (float*)d_out;
    float* attn = out + (size_t)NTOK*DMm;

    long long need = (long long)NTOK*DMm + (long long)Bb*Hh*Ss*Ss;
    int write_attn = ((long long)out_size >= need) ? 1 : 0;

    cudaFuncSetAttribute(proj_mma_kernel,
                         cudaFuncAttributeMaxDynamicSharedMemorySize, PROJ_SMEM);
    cudaFuncSetAttribute(attn_sum_mma,
                         cudaFuncAttributeMaxDynamicSharedMemorySize, SUM_SMEM);
    cudaFuncSetAttribute(attn_pv_mma,
                         cudaFuncAttributeMaxDynamicSharedMemorySize, PV_SMEM);

    dim3 cgrid((NTOK*DMm)/(256*4), 3);
    convert_split_kernel<<<cgrid, 256>>>(q, k, v, 0);
    dim3 tgrid(DMm/32, DMm/32, 4);
    transW_kernel<<<tgrid, dim3(32, 8)>>>(Wq, Wk, Wv, Wo);

    dim3 ggrid3(DMm/128, NTOK/128, 3);
    proj_mma_kernel<<<ggrid3, 256, PROJ_SMEM>>>(bq, bk, bv, nullptr, 0);

    dim3 agrid(Ss/128, Hh, Bb);
    attn_sum_mma<<<agrid, 256, SUM_SMEM>>>(mask);
    attn_pv_mma<<<agrid, 256, PV_SMEM>>>(mask, attn, write_attn);

    dim3 cgrid1((NTOK*DMm)/(256*4), 1);
    convert_split_kernel<<<cgrid1, 256>>>(nullptr, nullptr, nullptr, 1);
    dim3 ggrid1(DMm/128, NTOK/128, 1);
    proj_mma_kernel<<<ggrid1, 256, PROJ_SMEM>>>(bo, bo, bo, out, 3);
}

// round 12
// speedup vs baseline: 2.3503x; 1.0185x over previous
#include <cuda_runtime.h>
#include <cuda_bf16.h>
#include <cstdint>

#define DMm  1024
#define Hh   16
#define Dd   64
#define Bb   2
#define Ss   2048
#define NTOK (Bb*Ss)   // 4096

// ---------------------------------------------------------------------------
// Static device scratch
// ---------------------------------------------------------------------------
__device__ float g_CTX[(size_t)NTOK*DMm];
__device__ float g_SUM[(size_t)Bb*Hh*Ss];
__device__ __nv_bfloat16 g_Xhi [(size_t)3*NTOK*DMm];
__device__ __nv_bfloat16 g_Xlo [(size_t)3*NTOK*DMm];
__device__ __nv_bfloat16 g_WThi[(size_t)4*DMm*DMm];
__device__ __nv_bfloat16 g_WTlo[(size_t)4*DMm*DMm];
__device__ __nv_bfloat16 g_Qhi[(size_t)Bb*Hh*Ss*Dd];
__device__ __nv_bfloat16 g_Qlo[(size_t)Bb*Hh*Ss*Dd];
__device__ __nv_bfloat16 g_Khi[(size_t)Bb*Hh*Ss*Dd];
__device__ __nv_bfloat16 g_Klo[(size_t)Bb*Hh*Ss*Dd];
__device__ __nv_bfloat16 g_Vhi[(size_t)Bb*Hh*Ss*Dd];
__device__ __nv_bfloat16 g_Vlo[(size_t)Bb*Hh*Ss*Dd];

// ---------------------------------------------------------------------------
// Helpers (base ISA sm_80+, valid on compute_103)
// ---------------------------------------------------------------------------
__device__ __forceinline__ uint32_t smem_u32(const void* p) {
    uint32_t a;
    asm("{ .reg .u64 t; cvta.to.shared.u64 t, %1; cvt.u32.u64 %0, t; }"
        : "=r"(a) : "l"(p));
    return a;
}

__device__ __forceinline__ void ldsm_x4(uint32_t* r, uint32_t addr) {
    asm volatile("ldmatrix.sync.aligned.m8n8.x4.shared.b16 {%0,%1,%2,%3}, [%4];"
        : "=r"(r[0]), "=r"(r[1]), "=r"(r[2]), "=r"(r[3]) : "r"(addr));
}

__device__ __forceinline__ void ldsm_x4_t(uint32_t* r, uint32_t addr) {
    asm volatile("ldmatrix.sync.aligned.m8n8.x4.trans.shared.b16 {%0,%1,%2,%3}, [%4];"
        : "=r"(r[0]), "=r"(r[1]), "=r"(r[2]), "=r"(r[3]) : "r"(addr));
}

__device__ __forceinline__ void mma16816(float* c, const uint32_t* a, const uint32_t* b) {
    asm volatile(
        "mma.sync.aligned.m16n8k16.row.col.f32.bf16.bf16.f32 "
        "{%0,%1,%2,%3}, {%4,%5,%6,%7}, {%8,%9}, {%0,%1,%2,%3};"
        : "+f"(c[0]), "+f"(c[1]), "+f"(c[2]), "+f"(c[3])
        : "r"(a[0]), "r"(a[1]), "r"(a[2]), "r"(a[3]), "r"(b[0]), "r"(b[1]));
}

#define CP_ASYNC16(dst, src) \
    asm volatile("cp.async.cg.shared.global [%0], [%1], 16;" \
        :: "r"(dst), "l"(src))
#define CP_COMMIT() asm volatile("cp.async.commit_group;")
#define CP_WAIT0()  asm volatile("cp.async.wait_group 0;")

// FFMA-pipe exp: 2^(x*log2e), deg-6 poly on [-0.5,0.5], rel err ~1e-6
__device__ __forceinline__ float exp_fast(float x) {
    float t = x * 1.4426950408889634f;
    t = fminf(fmaxf(t, -126.f), 126.f);
    float fi = rintf(t);
    float f  = t - fi;
    int   ei = (int)fi;
    float p = 1.5403530e-4f;
    p = fmaf(p, f, 1.33335581e-3f);
    p = fmaf(p, f, 9.61812911e-3f);
    p = fmaf(p, f, 5.55041087e-2f);
    p = fmaf(p, f, 2.40226507e-1f);
    p = fmaf(p, f, 6.93147181e-1f);
    p = fmaf(p, f, 1.0f);
    return __int_as_float(__float_as_int(p) + (ei << 23));
}

__device__ __forceinline__ ushort bfu(__nv_bfloat16 h) {
    return __bfloat16_as_ushort(h);
}

__device__ __forceinline__ void split4(float4 v, uint2& hi, uint2& lo) {
    __nv_bfloat16 h0 = __float2bfloat16_rn(v.x);
    __nv_bfloat16 h1 = __float2bfloat16_rn(v.y);
    __nv_bfloat16 h2 = __float2bfloat16_rn(v.z);
    __nv_bfloat16 h3 = __float2bfloat16_rn(v.w);
    hi.x = (uint32_t)bfu(h0) | ((uint32_t)bfu(h1) << 16);
    hi.y = (uint32_t)bfu(h2) | ((uint32_t)bfu(h3) << 16);
    __nv_bfloat16 l0 = __float2bfloat16_rn(v.x - __bfloat162float(h0));
    __nv_bfloat16 l1 = __float2bfloat16_rn(v.y - __bfloat162float(h1));
    __nv_bfloat16 l2 = __float2bfloat16_rn(v.z - __bfloat162float(h2));
    __nv_bfloat16 l3 = __float2bfloat16_rn(v.w - __bfloat162float(h3));
    lo.x = (uint32_t)bfu(l0) | ((uint32_t)bfu(l1) << 16);
    lo.y = (uint32_t)bfu(l2) | ((uint32_t)bfu(l3) << 16);
}

__device__ __forceinline__ void pack2(float a, float b, uint32_t& hi, uint32_t& lo) {
    __nv_bfloat16 ha = __float2bfloat16_rn(a);
    __nv_bfloat16 hb = __float2bfloat16_rn(b);
    hi = (uint32_t)bfu(ha) | ((uint32_t)bfu(hb) << 16);
    __nv_bfloat16 la = __float2bfloat16_rn(a - __bfloat162float(ha));
    __nv_bfloat16 lb = __float2bfloat16_rn(b - __bfloat162float(hb));
    lo = (uint32_t)bfu(la) | ((uint32_t)bfu(lb) << 16);
}

// ---------------------------------------------------------------------------
// fp32 -> bf16 hi/lo split.  grid.y selects input (q/k/v); use_ctx reads CTX.
// ---------------------------------------------------------------------------
__global__ __launch_bounds__(256) void convert_split_kernel(
    const float* __restrict__ xq, const float* __restrict__ xk,
    const float* __restrict__ xv, int use_ctx)
{
    int z = blockIdx.y;
    const float* X = use_ctx ? g_CTX : (z == 0 ? xq : (z == 1 ? xk : xv));
    size_t slot = (size_t)z * NTOK * DMm;
    size_t i = ((size_t)blockIdx.x * 256 + threadIdx.x) * 4;
    float4 v = *(const float4*)(X + i);
    uint2 hi, lo;
    split4(v, hi, lo);
    *(uint2*)(g_Xhi + slot + i) = hi;
    *(uint2*)(g_Xlo + slot + i) = lo;
}

// ---------------------------------------------------------------------------
// W [K][N] fp32 -> WT [N][K] bf16 hi/lo.  grid.z selects weight slot.
// ---------------------------------------------------------------------------
__global__ __launch_bounds__(256) void transW_kernel(
    const float* __restrict__ Wq, const float* __restrict__ Wk,
    const float* __restrict__ Wv, const float* __restrict__ Wo)
{
    __shared__ float t[32][33];
    int z = blockIdx.z;
    const float* W = (z == 0) ? Wq : (z == 1) ? Wk : (z == 2) ? Wv : Wo;
    size_t slot = (size_t)z * DMm * DMm;
    int nx = blockIdx.x * 32, ky = blockIdx.y * 32;
    int txx = threadIdx.x, tyy = threadIdx.y;   // block (32, 8)
#pragma unroll
    for (int j = 0; j < 4; j++)
        t[tyy + j*8][txx] = W[(size_t)(ky + tyy + j*8)*DMm + nx + txx];
    __syncthreads();
#pragma unroll
    for (int j = 0; j < 4; j++) {
        float val = t[txx][tyy + j*8];
        __nv_bfloat16 h = __float2bfloat16_rn(val);
        size_t o = slot + (size_t)(nx + tyy + j*8)*DMm + ky + txx;
        g_WThi[o] = h;
        g_WTlo[o] = __float2bfloat16_rn(val - __bfloat162float(h));
    }
}

// ---------------------------------------------------------------------------
// HMMA projection GEMM, cp.async double-buffered (race-free order).
// ---------------------------------------------------------------------------
#define PRS    80
#define P_AHI  0
#define P_ALO  10240
#define P_BHI  20480
#define P_BLO  30720
#define P_SSTR 40960
#define PROJ_SMEM (2*P_SSTR)         // 81920

__global__ __launch_bounds__(256, 2) void proj_mma_kernel(
    const float* __restrict__ bq, const float* __restrict__ bk,
    const float* __restrict__ bv, float* __restrict__ Yext, int base_mode)
{
    extern __shared__ __align__(16) char psm[];
    uint32_t sb = smem_u32(psm);

    int mode = base_mode + blockIdx.z;
    const float* bias = (blockIdx.z == 0) ? bq : (blockIdx.z == 1) ? bk : bv;

    const __nv_bfloat16* Xhi = g_Xhi + (size_t)(mode == 3 ? 0 : mode) * NTOK * DMm;
    const __nv_bfloat16* Xlo = g_Xlo + (size_t)(mode == 3 ? 0 : mode) * NTOK * DMm;
    const __nv_bfloat16* WThi = g_WThi + (size_t)mode * DMm * DMm;
    const __nv_bfloat16* WTlo = g_WTlo + (size_t)mode * DMm * DMm;

    int tid  = threadIdx.x;
    int lane = tid & 31, wid = tid >> 5;
    int warp_m = wid & 1, warp_n = wid >> 1;
    int row0 = blockIdx.y * 128;
    int col0 = blockIdx.x * 128;

    float acc[4][4][4];
#pragma unroll
    for (int mt = 0; mt < 4; mt++)
#pragma unroll
        for (int nt = 0; nt < 4; nt++)
#pragma unroll
            for (int e = 0; e < 4; e++) acc[mt][nt][e] = 0.f;

    int ld_r = tid >> 1;
    int ld_c = (tid & 1) * 2;

    auto issue = [&](int ch, uint32_t st) {
        int k0 = ch * 32;
#pragma unroll
        for (int cc = 0; cc < 2; cc++) {
            int c = ld_c + cc;
            uint32_t doff = st + (uint32_t)ld_r*PRS + c*16;
            size_t ga = (size_t)(row0 + ld_r)*DMm + k0 + c*8;
            CP_ASYNC16(sb + P_AHI + doff, Xhi + ga);
            CP_ASYNC16(sb + P_ALO + doff, Xlo + ga);
            size_t gb = (size_t)(col0 + ld_r)*DMm + k0 + c*8;
            CP_ASYNC16(sb + P_BHI + doff, WThi + gb);
            CP_ASYNC16(sb + P_BLO + doff, WTlo + gb);
        }
        CP_COMMIT();
    };

    issue(0, 0);

    int a_row = lane & 15;
    int a_kb  = (lane >> 4) * 16;
    int b_row = (lane & 7) + ((lane >> 4) << 3);
    int b_kb  = ((lane >> 3) & 1) * 16;

    for (int ch = 0; ch < 32; ch++) {
        uint32_t st = (uint32_t)(ch & 1) * P_SSTR;
        CP_WAIT0();
        __syncthreads();
        if (ch + 1 < 32)
            issue(ch + 1, (uint32_t)((ch + 1) & 1) * P_SSTR);

#pragma unroll
        for (int kk = 0; kk < 2; kk++) {
            int kbyte = kk * 32;
            uint32_t ahi[4][4], alo[4][4];
            uint32_t bhi[4][2], blo[4][2];

#pragma unroll
            for (int mt = 0; mt < 4; mt++) {
                uint32_t ad = sb + st + P_AHI
                            + (uint32_t)(warp_m*64 + mt*16 + a_row)*PRS + kbyte + a_kb;
                ldsm_x4(ahi[mt], ad);
                ldsm_x4(alo[mt], ad + (P_ALO - P_AHI));
            }
#pragma unroll
            for (int p = 0; p < 2; p++) {
                uint32_t bd = sb + st + P_BHI
                            + (uint32_t)(warp_n*32 + p*16 + b_row)*PRS + kbyte + b_kb;
                uint32_t t[4];
                ldsm_x4(t, bd);
                bhi[2*p][0] = t[0]; bhi[2*p][1] = t[1];
                bhi[2*p+1][0] = t[2]; bhi[2*p+1][1] = t[3];
                ldsm_x4(t, bd + (P_BLO - P_BHI));
                blo[2*p][0] = t[0]; blo[2*p][1] = t[1];
                blo[2*p+1][0] = t[2]; blo[2*p+1][1] = t[3];
            }

#pragma unroll
            for (int mt = 0; mt < 4; mt++)
#pragma unroll
                for (int nt = 0; nt < 4; nt++) {
                    mma16816(acc[mt][nt], ahi[mt], bhi[nt]);
                    mma16816(acc[mt][nt], alo[mt], bhi[nt]);
                    mma16816(acc[mt][nt], ahi[mt], blo[nt]);
                }
        }
        __syncthreads();
    }

    int tg = lane >> 2, t4 = lane & 3;
    __nv_bfloat16 *Yhi = nullptr, *Ylo = nullptr;
    if (mode == 0) { Yhi = g_Qhi; Ylo = g_Qlo; }
    else if (mode == 1) { Yhi = g_Khi; Ylo = g_Klo; }
    else if (mode == 2) { Yhi = g_Vhi; Ylo = g_Vlo; }

#pragma unroll
    for (int mt = 0; mt < 4; mt++) {
        int rbase = row0 + warp_m*64 + mt*16 + tg;
#pragma unroll
        for (int nt = 0; nt < 4; nt++) {
            int col = col0 + warp_n*32 + nt*8 + t4*2;
            float b0 = bias[col], b1 = bias[col + 1];
#pragma unroll
            for (int half = 0; half < 2; half++) {
                int r = rbase + half*8;
                float v0 = acc[mt][nt][half*2 + 0] + b0;
                float v1 = acc[mt][nt][half*2 + 1] + b1;
                if (mode == 3) {
                    *(float2*)(Yext + (size_t)r*DMm + col) = make_float2(v0, v1);
                } else {
                    int bi = r >> 11, s = r & (Ss - 1);
                    int h = col >> 6, d = col & 63;
                    size_t off = (((size_t)bi*Hh + h)*Ss + s)*Dd + d;
                    uint32_t hi, lo;
                    pack2(v0, v1, hi, lo);
                    *(uint32_t*)(Yhi + off) = hi;
                    *(uint32_t*)(Ylo + off) = lo;
                }
            }
        }
    }
}

// ---------------------------------------------------------------------------
// Attention smem layouts.  RS = 144B row stride (ldmatrix conflict-free).
// ---------------------------------------------------------------------------
#define RS    144
// pass 1: Qhi (18432) + 2 K stages (9216 each) + mask (8192)
#define S1QHI   0
#define S1KSTG  18432
#define S1KSTR  9216
#define S1MSK   36864
#define SUM_SMEM (S1MSK + 8192)        // 45056
// pass 2: Qhi/Qlo (36864) + 2 KV stages (36864 each); mask via __ldg
#define SQHI    0
#define SQLO    18432
#define S2STG   36864
#define S2STR   36864
#define S2KHI   0
#define S2KLO   9216
#define S2VHI   18432
#define S2VLO   27648
#define PV_SMEM (S2STG + 2*S2STR)      // 110592

// 128-row Q tile (1024 uint4)
#define LOAD_TILE_128(SRC, SOFF)                                             \
    _Pragma("unroll")                                                        \
    for (int i = 0; i < 4; i++) {                                            \
        int f = tid + i*256;                                                 \
        int row = f >> 3, c8 = (f & 7) * 8;                                  \
        *(uint4*)(sm + (SOFF) + row*RS + c8*2) =                             \
            *(const uint4*)((SRC) + (size_t)row*Dd + c8);                    \
    }

// ---------------------------------------------------------------------------
// Pass 1: rowsums of exp(QK^T/8 + mask), HI-ONLY QK, cp.async K pipeline.
// ---------------------------------------------------------------------------
__global__ __launch_bounds__(256, 3) void attn_sum_mma(const float* __restrict__ mask)
{
    extern __shared__ __align__(16) char sm[];
    uint32_t sb = smem_u32(sm);
    float* smask = (float*)(sm + S1MSK);

    int tid  = threadIdx.x;
    int lane = tid & 31, w = tid >> 5;
    int tg = lane >> 2, t4 = lane & 3;
    int qt = blockIdx.x, h = blockIdx.y, b = blockIdx.z;

    size_t hb = ((size_t)b*Hh + h)*Ss;
    const __nv_bfloat16* Qh = g_Qhi + (hb + (size_t)qt*128)*Dd;
    const __nv_bfloat16* Kh = g_Khi + hb*Dd;

#pragma unroll
    for (int i = 0; i < 2; i++) {
        int f = tid + i*256;
        *(float4*)&smask[f*4] = *(const float4*)(mask + (size_t)b*Ss + f*4);
    }
    LOAD_TILE_128(Qh, S1QHI)

    int ld_row = tid >> 3, ld_c8 = (tid & 7) * 8;   // K-tile cp.async: 2/thread
    auto issue_k = [&](int kt, uint32_t stg) {
#pragma unroll
        for (int i = 0; i < 2; i++) {
            int row = ld_row + i*32;
            uint32_t doff = stg + (uint32_t)row*RS + ld_c8*2;
            CP_ASYNC16(sb + doff, Kh + (size_t)(kt + row)*Dd + ld_c8);
        }
        CP_COMMIT();
    };

    issue_k(0, S1KSTG);
    __syncthreads();    // Q + mask visible

    int a_row = lane & 15;
    int a_kb  = (lane >> 4) * 16;
    int b_row = (lane & 7) + ((lane >> 4) << 3);
    int b_kb  = ((lane >> 3) & 1) * 16;

    float rs0 = 0.f, rs1 = 0.f;

    for (int kt = 0; kt < Ss; kt += 64) {
        uint32_t stg = S1KSTG + (uint32_t)((kt >> 6) & 1) * S1KSTR;
        CP_WAIT0();
        __syncthreads();
        if (kt + 64 < Ss)
            issue_k(kt + 64, S1KSTG + (uint32_t)(((kt >> 6) + 1) & 1) * S1KSTR);

#pragma unroll
        for (int nbp = 0; nbp < 2; nbp++) {
            float accS[4][4];
#pragma unroll
            for (int j = 0; j < 4; j++)
#pragma unroll
                for (int e = 0; e < 4; e++) accS[j][e] = 0.f;

#pragma unroll
            for (int ks = 0; ks < 4; ks++) {
                uint32_t qh[4];
                uint32_t qa = sb + S1QHI + (uint32_t)(w*16 + a_row)*RS + ks*32 + a_kb;
                ldsm_x4(qh, qa);
#pragma unroll
                for (int nb2 = 0; nb2 < 2; nb2++) {
                    int nb = nbp*2 + nb2;
                    uint32_t th[4];
                    uint32_t ad = sb + stg + (uint32_t)(nb*16 + b_row)*RS + ks*32 + b_kb;
                    ldsm_x4(th, ad);
                    int j0 = nb2*2;
                    mma16816(accS[j0],   qh, th);
                    mma16816(accS[j0+1], qh, th+2);
                }
            }

#pragma unroll
            for (int idx = 0; idx < 4; idx++) {
                int col = (nbp*4 + idx)*8 + t4*2;
                float2 mv = *(float2*)&smask[kt + col];
                float m0 = mv.x * -1e9f, m1 = mv.y * -1e9f;
                rs0 += exp_fast(fmaf(accS[idx][0], 0.125f, m0))
                     + exp_fast(fmaf(accS[idx][1], 0.125f, m1));
                rs1 += exp_fast(fmaf(accS[idx][2], 0.125f, m0))
                     + exp_fast(fmaf(accS[idx][3], 0.125f, m1));
            }
        }
        __syncthreads();    // all reads of stage done before it is refilled
    }

    rs0 += __shfl_xor_sync(0xffffffffu, rs0, 1);
    rs0 += __shfl_xor_sync(0xffffffffu, rs0, 2);
    rs1 += __shfl_xor_sync(0xffffffffu, rs1, 1);
    rs1 += __shfl_xor_sync(0xffffffffu, rs1, 2);
    if (t4 == 0) {
        size_t base = hb + (size_t)qt*128;
        g_SUM[base + w*16 + tg]     = rs0;
        g_SUM[base + w*16 + tg + 8] = rs1;
    }
}

// ---------------------------------------------------------------------------
// Pass 2: recompute QK (bf16x3), p = exp/rowsum, write attn once,
// O += P V (bf16x3).  cp.async K/V pipeline; mask via __ldg.
// ---------------------------------------------------------------------------
__global__ __launch_bounds__(256, 2) void attn_pv_mma(
    const float* __restrict__ mask, float* __restrict__ attn, int write_attn)
{
    extern __shared__ __align__(16) char sm[];
    uint32_t sb = smem_u32(sm);

    int tid  = threadIdx.x;
    int lane = tid & 31, w = tid >> 5;
    int tg = lane >> 2, t4 = lane & 3;
    int qt = blockIdx.x, h = blockIdx.y, b = blockIdx.z;

    size_t hb = ((size_t)b*Hh + h)*Ss;
    const __nv_bfloat16* Qh = g_Qhi + (hb + (size_t)qt*128)*Dd;
    const __nv_bfloat16* Ql = g_Qlo + (hb + (size_t)qt*128)*Dd;
    const __nv_bfloat16* Kh = g_Khi + hb*Dd;
    const __nv_bfloat16* Kl = g_Klo + hb*Dd;
    const __nv_bfloat16* Vh = g_Vhi + hb*Dd;
    const __nv_bfloat16* Vl = g_Vlo + hb*Dd;
    const float* maskb = mask + (size_t)b*Ss;
    float* attn_base = attn + (hb + (size_t)qt*128)*Ss;

    LOAD_TILE_128(Qh, SQHI)
    LOAD_TILE_128(Ql, SQLO)

    int ld_row = tid >> 3, ld_c8 = (tid & 7) * 8;
    auto issue_kv = [&](int kt, uint32_t stg) {
#pragma unroll
        for (int i = 0; i < 2; i++) {
            int row = ld_row + i*32;
            uint32_t doff = stg + (uint32_t)row*RS + ld_c8*2;
            size_t ga = (size_t)(kt + row)*Dd + ld_c8;
            CP_ASYNC16(sb + doff + S2KHI, Kh + ga);
            CP_ASYNC16(sb + doff + S2KLO, Kl + ga);
            CP_ASYNC16(sb + doff + S2VHI, Vh + ga);
            CP_ASYNC16(sb + doff + S2VLO, Vl + ga);
        }
        CP_COMMIT();
    };

    issue_kv(0, S2STG);
    __syncthreads();    // Q visible

    int a_row = lane & 15;
    int a_kb  = (lane >> 4) * 16;
    int b_row = (lane & 7) + ((lane >> 4) << 3);
    int b_kb  = ((lane >> 3) & 1) * 16;
    int v_koff = ((lane >> 3) & 1) * 8 + (lane & 7);
    int v_noff = (lane >> 4) * 8;

    size_t base = hb + (size_t)qt*128;
    float rinv0 = 1.0f / g_SUM[base + w*16 + tg];
    float rinv1 = 1.0f / g_SUM[base + w*16 + tg + 8];
    int r0g = w*16 + tg;

    float accO[8][4];
#pragma unroll
    for (int nt = 0; nt < 8; nt++)
#pragma unroll
        for (int e = 0; e < 4; e++) accO[nt][e] = 0.f;

    for (int kt = 0; kt < Ss; kt += 64) {
        uint32_t stg = S2STG + (uint32_t)((kt >> 6) & 1) * S2STR;
        CP_WAIT0();
        __syncthreads();
        if (kt + 64 < Ss)
            issue_kv(kt + 64, S2STG + (uint32_t)(((kt >> 6) + 1) & 1) * S2STR);

#pragma unroll
        for (int nbp = 0; nbp < 2; nbp++) {
            float accS[4][4];
#pragma unroll
            for (int j = 0; j < 4; j++)
#pragma unroll
                for (int e = 0; e < 4; e++) accS[j][e] = 0.f;

#pragma unroll
            for (int ks = 0; ks < 4; ks++) {
                uint32_t qh[4], ql[4];
                uint32_t qa = sb + SQHI + (uint32_t)(w*16 + a_row)*RS + ks*32 + a_kb;
                ldsm_x4(qh, qa);
                ldsm_x4(ql, qa + (SQLO - SQHI));
#pragma unroll
                for (int nb2 = 0; nb2 < 2; nb2++) {
                    int nb = nbp*2 + nb2;
                    uint32_t th[4], tl[4];
                    uint32_t ad = sb + stg + S2KHI + (uint32_t)(nb*16 + b_row)*RS + ks*32 + b_kb;
                    ldsm_x4(th, ad);
                    ldsm_x4(tl, ad + (S2KLO - S2KHI));
                    int j0 = nb2*2;
                    mma16816(accS[j0],   qh, th);
                    mma16816(accS[j0],   ql, th);
                    mma16816(accS[j0],   qh, tl);
                    mma16816(accS[j0+1], qh, th+2);
                    mma16816(accS[j0+1], ql, th+2);
                    mma16816(accS[j0+1], qh, tl+2);
                }
            }

            uint32_t ph0[4], ph1[4], pl0[4], pl1[4];
#pragma unroll
            for (int idx = 0; idx < 4; idx++) {
                int col = (nbp*4 + idx)*8 + t4*2;
                float2 mv = __ldg((const float2*)(maskb + kt + col));
                float m0 = mv.x * -1e9f, m1 = mv.y * -1e9f;
                float p0 = exp_fast(fmaf(accS[idx][0], 0.125f, m0)) * rinv0;
                float p1 = exp_fast(fmaf(accS[idx][1], 0.125f, m1)) * rinv0;
                float p2 = exp_fast(fmaf(accS[idx][2], 0.125f, m0)) * rinv1;
                float p3 = exp_fast(fmaf(accS[idx][3], 0.125f, m1)) * rinv1;
                if (write_attn) {
                    *(float2*)&attn_base[(size_t)r0g*Ss + kt + col]       = make_float2(p0, p1);
                    *(float2*)&attn_base[(size_t)(r0g + 8)*Ss + kt + col] = make_float2(p2, p3);
                }
                pack2(p0, p1, ph0[idx], pl0[idx]);
                pack2(p2, p3, ph1[idx], pl1[idx]);
            }

#pragma unroll
            for (int nb2 = 0; nb2 < 2; nb2++) {
                int ksv = nbp*2 + nb2;
                uint32_t ah[4] = {ph0[2*nb2], ph1[2*nb2], ph0[2*nb2+1], ph1[2*nb2+1]};
                uint32_t al[4] = {pl0[2*nb2], pl1[2*nb2], pl0[2*nb2+1], pl1[2*nb2+1]};
#pragma unroll
                for (int vb = 0; vb < 4; vb++) {
                    uint32_t th[4], tl[4];
                    uint32_t ad = sb + stg + S2VHI + (uint32_t)(ksv*16 + v_koff)*RS
                                + (vb*16 + v_noff)*2;
                    ldsm_x4_t(th, ad);
                    ldsm_x4_t(tl, ad + (S2VLO - S2VHI));
                    int nt0 = vb*2;
                    mma16816(accO[nt0],   ah, th);
                    mma16816(accO[nt0],   al, th);
                    mma16816(accO[nt0],   ah, tl);
                    mma16816(accO[nt0+1], ah, th+2);
                    mma16816(accO[nt0+1], al, th+2);
                    mma16816(accO[nt0+1], ah, tl+2);
                }
            }
        }
        __syncthreads();    // all reads of this stage done before refill
    }

    int q0 = qt*128 + w*16 + tg;
#pragma unroll
    for (int nt = 0; nt < 8; nt++) {
        int d = nt*8 + t4*2;
        float* c0 = g_CTX + ((size_t)b*Ss + q0)*DMm + h*64 + d;
        *(float2*)c0 = make_float2(accO[nt][0], accO[nt][1]);
        float* c1 = g_CTX + ((size_t)b*Ss + q0 + 8)*DMm + h*64 + d;
        *(float2*)c1 = make_float2(accO[nt][2], accO[nt][3]);
    }
}

// ---------------------------------------------------------------------------
// Launch
// ---------------------------------------------------------------------------
extern "C" void kernel_launch(void* const* d_in, const int* in_sizes, int n_in,
                              void* d_out, int out_size)
{
    const float* q    = (const float*)d_in[0];
    const float* k    = (const float*)d_in[1];
    const float* v    = (const float*)d_in[2];
    const float* mask = (const float*)d_in[3];
    const float* Wq   = (const float*)d_in[4];
    const float* bq   = (const float*)d_in[5];
    const float* Wk   = (const float*)d_in[6];
    const float* bk   = (const float*)d_in[7];
    const float* Wv   = (const float*)d_in[8];
    const float* bv   = (const float*)d_in[9];
    const float* Wo   = (const float*)d_in[10];
    const float* bo   = (const float*)d_in[11];

    float* out  = (float*)d_out;
    float* attn = out + (size_t)NTOK*DMm;

    long long need = (long long)NTOK*DMm + (long long)Bb*Hh*Ss*Ss;
    int write_attn = ((long long)out_size >= need) ? 1 : 0;

    cudaFuncSetAttribute(proj_mma_kernel,
                         cudaFuncAttributeMaxDynamicSharedMemorySize, PROJ_SMEM);
    cudaFuncSetAttribute(attn_sum_mma,
                         cudaFuncAttributeMaxDynamicSharedMemorySize, SUM_SMEM);
    cudaFuncSetAttribute(attn_pv_mma,
                         cudaFuncAttributeMaxDynamicSharedMemorySize, PV_SMEM);

    dim3 cgrid((NTOK*DMm)/(256*4), 3);
    convert_split_kernel<<<cgrid, 256>>>(q, k, v, 0);
    dim3 tgrid(DMm/32, DMm/32, 4);
    transW_kernel<<<tgrid, dim3(32, 8)>>>(Wq, Wk, Wv, Wo);

    dim3 ggrid3(DMm/128, NTOK/128, 3);
    proj_mma_kernel<<<ggrid3, 256, PROJ_SMEM>>>(bq, bk, bv, nullptr, 0);

    dim3 agrid(Ss/128, Hh, Bb);
    attn_sum_mma<<<agrid, 256, SUM_SMEM>>>(mask);
    attn_pv_mma<<<agrid, 256, PV_SMEM>>>(mask, attn, write_attn);

    dim3 cgrid1((NTOK*DMm)/(256*4), 1);
    convert_split_kernel<<<cgrid1, 256>>>(nullptr, nullptr, nullptr, 1);
    dim3 ggrid1(DMm/128, NTOK/128, 1);
    proj_mma_kernel<<<ggrid1, 256, PROJ_SMEM>>>(bo, bo, bo, out, 3);
}

// round 13
// speedup vs baseline: 2.6357x; 1.1214x over previous
#include <cuda_runtime.h>
#include <cuda_bf16.h>
#include <cstdint>

#define DMm  1024
#define Hh   16
#define Dd   64
#define Bb   2
#define Ss   2048
#define NTOK (Bb*Ss)   // 4096

// exp(x) = 2^(x*log2e); fold the 1/8 logit scale: 0.125*log2e
#define EXSCALE  0.1803368801111601f
#define MASKMUL  (-1.4426950408889634e9f)

// ---------------------------------------------------------------------------
// Static device scratch
// ---------------------------------------------------------------------------
__device__ float g_CTX[(size_t)NTOK*DMm];
__device__ float g_SUM[(size_t)Bb*Hh*Ss];
__device__ __nv_bfloat16 g_Xhi [(size_t)3*NTOK*DMm];
__device__ __nv_bfloat16 g_Xlo [(size_t)3*NTOK*DMm];
__device__ __nv_bfloat16 g_WThi[(size_t)4*DMm*DMm];
__device__ __nv_bfloat16 g_WTlo[(size_t)4*DMm*DMm];
__device__ __nv_bfloat16 g_Qhi[(size_t)Bb*Hh*Ss*Dd];
__device__ __nv_bfloat16 g_Qlo[(size_t)Bb*Hh*Ss*Dd];
__device__ __nv_bfloat16 g_Khi[(size_t)Bb*Hh*Ss*Dd];
__device__ __nv_bfloat16 g_Klo[(size_t)Bb*Hh*Ss*Dd];
__device__ __nv_bfloat16 g_Vhi[(size_t)Bb*Hh*Ss*Dd];
__device__ __nv_bfloat16 g_Vlo[(size_t)Bb*Hh*Ss*Dd];

// ---------------------------------------------------------------------------
// Helpers (base ISA sm_80+, valid on compute_103)
// ---------------------------------------------------------------------------
__device__ __forceinline__ uint32_t smem_u32(const void* p) {
    uint32_t a;
    asm("{ .reg .u64 t; cvta.to.shared.u64 t, %1; cvt.u32.u64 %0, t; }"
        : "=r"(a) : "l"(p));
    return a;
}

__device__ __forceinline__ void ldsm_x4(uint32_t* r, uint32_t addr) {
    asm volatile("ldmatrix.sync.aligned.m8n8.x4.shared.b16 {%0,%1,%2,%3}, [%4];"
        : "=r"(r[0]), "=r"(r[1]), "=r"(r[2]), "=r"(r[3]) : "r"(addr));
}

__device__ __forceinline__ void ldsm_x4_t(uint32_t* r, uint32_t addr) {
    asm volatile("ldmatrix.sync.aligned.m8n8.x4.trans.shared.b16 {%0,%1,%2,%3}, [%4];"
        : "=r"(r[0]), "=r"(r[1]), "=r"(r[2]), "=r"(r[3]) : "r"(addr));
}

__device__ __forceinline__ void mma16816(float* c, const uint32_t* a, const uint32_t* b) {
    asm volatile(
        "mma.sync.aligned.m16n8k16.row.col.f32.bf16.bf16.f32 "
        "{%0,%1,%2,%3}, {%4,%5,%6,%7}, {%8,%9}, {%0,%1,%2,%3};"
        : "+f"(c[0]), "+f"(c[1]), "+f"(c[2]), "+f"(c[3])
        : "r"(a[0]), "r"(a[1]), "r"(a[2]), "r"(a[3]), "r"(b[0]), "r"(b[1]));
}

#define CP_ASYNC16(dst, src) \
    asm volatile("cp.async.cg.shared.global [%0], [%1], 16;" \
        :: "r"(dst), "l"(src))
#define CP_COMMIT() asm volatile("cp.async.commit_group;")
#define CP_WAIT0()  asm volatile("cp.async.wait_group 0;")

// hardware exp2 (MUFU.EX2): 1 instruction, rel err ~2^-22
__device__ __forceinline__ float ex2f(float x) {
    float r;
    asm("ex2.approx.f32 %0, %1;" : "=f"(r) : "f"(x));
    return r;
}

__device__ __forceinline__ ushort bfu(__nv_bfloat16 h) {
    return __bfloat16_as_ushort(h);
}

__device__ __forceinline__ void split4(float4 v, uint2& hi, uint2& lo) {
    __nv_bfloat16 h0 = __float2bfloat16_rn(v.x);
    __nv_bfloat16 h1 = __float2bfloat16_rn(v.y);
    __nv_bfloat16 h2 = __float2bfloat16_rn(v.z);
    __nv_bfloat16 h3 = __float2bfloat16_rn(v.w);
    hi.x = (uint32_t)bfu(h0) | ((uint32_t)bfu(h1) << 16);
    hi.y = (uint32_t)bfu(h2) | ((uint32_t)bfu(h3) << 16);
    __nv_bfloat16 l0 = __float2bfloat16_rn(v.x - __bfloat162float(h0));
    __nv_bfloat16 l1 = __float2bfloat16_rn(v.y - __bfloat162float(h1));
    __nv_bfloat16 l2 = __float2bfloat16_rn(v.z - __bfloat162float(h2));
    __nv_bfloat16 l3 = __float2bfloat16_rn(v.w - __bfloat162float(h3));
    lo.x = (uint32_t)bfu(l0) | ((uint32_t)bfu(l1) << 16);
    lo.y = (uint32_t)bfu(l2) | ((uint32_t)bfu(l3) << 16);
}

// fast bf16 hi/lo pack of (a,b): lo16 = a, hi16 = b.  6 instructions.
__device__ __forceinline__ void pack2(float a, float b, uint32_t& hi, uint32_t& lo) {
    uint32_t u;
    asm("cvt.rn.bf16x2.f32 %0, %1, %2;" : "=r"(u) : "f"(b), "f"(a));
    float af = __uint_as_float(u << 16);
    float bf = __uint_as_float(u & 0xffff0000u);
    hi = u;
    float ra = a - af, rb = b - bf;
    asm("cvt.rn.bf16x2.f32 %0, %1, %2;" : "=r"(lo) : "f"(rb), "f"(ra));
}

// ---------------------------------------------------------------------------
// fp32 -> bf16 hi/lo split.  grid.y selects input (q/k/v); use_ctx reads CTX.
// ---------------------------------------------------------------------------
__global__ __launch_bounds__(256) void convert_split_kernel(
    const float* __restrict__ xq, const float* __restrict__ xk,
    const float* __restrict__ xv, int use_ctx)
{
    int z = blockIdx.y;
    const float* X = use_ctx ? g_CTX : (z == 0 ? xq : (z == 1 ? xk : xv));
    size_t slot = (size_t)z * NTOK * DMm;
    size_t i = ((size_t)blockIdx.x * 256 + threadIdx.x) * 4;
    float4 v = *(const float4*)(X + i);
    uint2 hi, lo;
    split4(v, hi, lo);
    *(uint2*)(g_Xhi + slot + i) = hi;
    *(uint2*)(g_Xlo + slot + i) = lo;
}

// ---------------------------------------------------------------------------
// W [K][N] fp32 -> WT [N][K] bf16 hi/lo.  grid.z selects weight slot.
// ---------------------------------------------------------------------------
__global__ __launch_bounds__(256) void transW_kernel(
    const float* __restrict__ Wq, const float* __restrict__ Wk,
    const float* __restrict__ Wv, const float* __restrict__ Wo)
{
    __shared__ float t[32][33];
    int z = blockIdx.z;
    const float* W = (z == 0) ? Wq : (z == 1) ? Wk : (z == 2) ? Wv : Wo;
    size_t slot = (size_t)z * DMm * DMm;
    int nx = blockIdx.x * 32, ky = blockIdx.y * 32;
    int txx = threadIdx.x, tyy = threadIdx.y;   // block (32, 8)
#pragma unroll
    for (int j = 0; j < 4; j++)
        t[tyy + j*8][txx] = W[(size_t)(ky + tyy + j*8)*DMm + nx + txx];
    __syncthreads();
#pragma unroll
    for (int j = 0; j < 4; j++) {
        float val = t[txx][tyy + j*8];
        __nv_bfloat16 h = __float2bfloat16_rn(val);
        size_t o = slot + (size_t)(nx + tyy + j*8)*DMm + ky + txx;
        g_WThi[o] = h;
        g_WTlo[o] = __float2bfloat16_rn(val - __bfloat162float(h));
    }
}

// ---------------------------------------------------------------------------
// HMMA projection GEMM, cp.async double-buffered (race-free order).
// ---------------------------------------------------------------------------
#define PRS    80
#define P_AHI  0
#define P_ALO  10240
#define P_BHI  20480
#define P_BLO  30720
#define P_SSTR 40960
#define PROJ_SMEM (2*P_SSTR)         // 81920

__global__ __launch_bounds__(256, 2) void proj_mma_kernel(
    const float* __restrict__ bq, const float* __restrict__ bk,
    const float* __restrict__ bv, float* __restrict__ Yext, int base_mode)
{
    extern __shared__ __align__(16) char psm[];
    uint32_t sb = smem_u32(psm);

    int mode = base_mode + blockIdx.z;
    const float* bias = (blockIdx.z == 0) ? bq : (blockIdx.z == 1) ? bk : bv;

    const __nv_bfloat16* Xhi = g_Xhi + (size_t)(mode == 3 ? 0 : mode) * NTOK * DMm;
    const __nv_bfloat16* Xlo = g_Xlo + (size_t)(mode == 3 ? 0 : mode) * NTOK * DMm;
    const __nv_bfloat16* WThi = g_WThi + (size_t)mode * DMm * DMm;
    const __nv_bfloat16* WTlo = g_WTlo + (size_t)mode * DMm * DMm;

    int tid  = threadIdx.x;
    int lane = tid & 31, wid = tid >> 5;
    int warp_m = wid & 1, warp_n = wid >> 1;
    int row0 = blockIdx.y * 128;
    int col0 = blockIdx.x * 128;

    float acc[4][4][4];
#pragma unroll
    for (int mt = 0; mt < 4; mt++)
#pragma unroll
        for (int nt = 0; nt < 4; nt++)
#pragma unroll
            for (int e = 0; e < 4; e++) acc[mt][nt][e] = 0.f;

    int ld_r = tid >> 1;
    int ld_c = (tid & 1) * 2;

    auto issue = [&](int ch, uint32_t st) {
        int k0 = ch * 32;
#pragma unroll
        for (int cc = 0; cc < 2; cc++) {
            int c = ld_c + cc;
            uint32_t doff = st + (uint32_t)ld_r*PRS + c*16;
            size_t ga = (size_t)(row0 + ld_r)*DMm + k0 + c*8;
            CP_ASYNC16(sb + P_AHI + doff, Xhi + ga);
            CP_ASYNC16(sb + P_ALO + doff, Xlo + ga);
            size_t gb = (size_t)(col0 + ld_r)*DMm + k0 + c*8;
            CP_ASYNC16(sb + P_BHI + doff, WThi + gb);
            CP_ASYNC16(sb + P_BLO + doff, WTlo + gb);
        }
        CP_COMMIT();
    };

    issue(0, 0);

    int a_row = lane & 15;
    int a_kb  = (lane >> 4) * 16;
    int b_row = (lane & 7) + ((lane >> 4) << 3);
    int b_kb  = ((lane >> 3) & 1) * 16;

    for (int ch = 0; ch < 32; ch++) {
        uint32_t st = (uint32_t)(ch & 1) * P_SSTR;
        CP_WAIT0();
        __syncthreads();
        if (ch + 1 < 32)
            issue(ch + 1, (uint32_t)((ch + 1) & 1) * P_SSTR);

#pragma unroll
        for (int kk = 0; kk < 2; kk++) {
            int kbyte = kk * 32;
            uint32_t ahi[4][4], alo[4][4];
            uint32_t bhi[4][2], blo[4][2];

#pragma unroll
            for (int mt = 0; mt < 4; mt++) {
                uint32_t ad = sb + st + P_AHI
                            + (uint32_t)(warp_m*64 + mt*16 + a_row)*PRS + kbyte + a_kb;
                ldsm_x4(ahi[mt], ad);
                ldsm_x4(alo[mt], ad + (P_ALO - P_AHI));
            }
#pragma unroll
            for (int p = 0; p < 2; p++) {
                uint32_t bd = sb + st + P_BHI
                            + (uint32_t)(warp_n*32 + p*16 + b_row)*PRS + kbyte + b_kb;
                uint32_t t[4];
                ldsm_x4(t, bd);
                bhi[2*p][0] = t[0]; bhi[2*p][1] = t[1];
                bhi[2*p+1][0] = t[2]; bhi[2*p+1][1] = t[3];
                ldsm_x4(t, bd + (P_BLO - P_BHI));
                blo[2*p][0] = t[0]; blo[2*p][1] = t[1];
                blo[2*p+1][0] = t[2]; blo[2*p+1][1] = t[3];
            }

#pragma unroll
            for (int mt = 0; mt < 4; mt++)
#pragma unroll
                for (int nt = 0; nt < 4; nt++) {
                    mma16816(acc[mt][nt], ahi[mt], bhi[nt]);
                    mma16816(acc[mt][nt], alo[mt], bhi[nt]);
                    mma16816(acc[mt][nt], ahi[mt], blo[nt]);
                }
        }
        __syncthreads();
    }

    int tg = lane >> 2, t4 = lane & 3;
    __nv_bfloat16 *Yhi = nullptr, *Ylo = nullptr;
    if (mode == 0) { Yhi = g_Qhi; Ylo = g_Qlo; }
    else if (mode == 1) { Yhi = g_Khi; Ylo = g_Klo; }
    else if (mode == 2) { Yhi = g_Vhi; Ylo = g_Vlo; }

#pragma unroll
    for (int mt = 0; mt < 4; mt++) {
        int rbase = row0 + warp_m*64 + mt*16 + tg;
#pragma unroll
        for (int nt = 0; nt < 4; nt++) {
            int col = col0 + warp_n*32 + nt*8 + t4*2;
            float b0 = bias[col], b1 = bias[col + 1];
#pragma unroll
            for (int half = 0; half < 2; half++) {
                int r = rbase + half*8;
                float v0 = acc[mt][nt][half*2 + 0] + b0;
                float v1 = acc[mt][nt][half*2 + 1] + b1;
                if (mode == 3) {
                    *(float2*)(Yext + (size_t)r*DMm + col) = make_float2(v0, v1);
                } else {
                    int bi = r >> 11, s = r & (Ss - 1);
                    int h = col >> 6, d = col & 63;
                    size_t off = (((size_t)bi*Hh + h)*Ss + s)*Dd + d;
                    uint32_t hi, lo;
                    pack2(v0, v1, hi, lo);
                    *(uint32_t*)(Yhi + off) = hi;
                    *(uint32_t*)(Ylo + off) = lo;
                }
            }
        }
    }
}

// ---------------------------------------------------------------------------
// Attention smem layouts.  RS = 144B row stride (ldmatrix conflict-free).
// ---------------------------------------------------------------------------
#define RS    144
#define S1QHI   0
#define S1KSTG  18432
#define S1KSTR  9216
#define S1MSK   36864
#define SUM_SMEM (S1MSK + 8192)        // 45056
#define SQHI    0
#define SQLO    18432
#define S2STG   36864
#define S2STR   36864
#define S2KHI   0
#define S2KLO   9216
#define S2VHI   18432
#define S2VLO   27648
#define PV_SMEM (S2STG + 2*S2STR)      // 110592

#define LOAD_TILE_128(SRC, SOFF)                                             \
    _Pragma("unroll")                                                        \
    for (int i = 0; i < 4; i++) {                                            \
        int f = tid + i*256;                                                 \
        int row = f >> 3, c8 = (f & 7) * 8;                                  \
        *(uint4*)(sm + (SOFF) + row*RS + c8*2) =                             \
            *(const uint4*)((SRC) + (size_t)row*Dd + c8);                    \
    }

// ---------------------------------------------------------------------------
// Pass 1: rowsums of exp(QK^T/8 + mask), HI-ONLY QK, cp.async K pipeline.
// ---------------------------------------------------------------------------
__global__ __launch_bounds__(256, 3) void attn_sum_mma(const float* __restrict__ mask)
{
    extern __shared__ __align__(16) char sm[];
    uint32_t sb = smem_u32(sm);
    float* smask = (float*)(sm + S1MSK);

    int tid  = threadIdx.x;
    int lane = tid & 31, w = tid >> 5;
    int tg = lane >> 2, t4 = lane & 3;
    int qt = blockIdx.x, h = blockIdx.y, b = blockIdx.z;

    size_t hb = ((size_t)b*Hh + h)*Ss;
    const __nv_bfloat16* Qh = g_Qhi + (hb + (size_t)qt*128)*Dd;
    const __nv_bfloat16* Kh = g_Khi + hb*Dd;

#pragma unroll
    for (int i = 0; i < 2; i++) {
        int f = tid + i*256;
        *(float4*)&smask[f*4] = *(const float4*)(mask + (size_t)b*Ss + f*4);
    }
    LOAD_TILE_128(Qh, S1QHI)

    int ld_row = tid >> 3, ld_c8 = (tid & 7) * 8;
    auto issue_k = [&](int kt, uint32_t stg) {
#pragma unroll
        for (int i = 0; i < 2; i++) {
            int row = ld_row + i*32;
            uint32_t doff = stg + (uint32_t)row*RS + ld_c8*2;
            CP_ASYNC16(sb + doff, Kh + (size_t)(kt + row)*Dd + ld_c8);
        }
        CP_COMMIT();
    };

    issue_k(0, S1KSTG);
    __syncthreads();

    int a_row = lane & 15;
    int a_kb  = (lane >> 4) * 16;
    int b_row = (lane & 7) + ((lane >> 4) << 3);
    int b_kb  = ((lane >> 3) & 1) * 16;

    float rs0 = 0.f, rs1 = 0.f;

    for (int kt = 0; kt < Ss; kt += 64) {
        uint32_t stg = S1KSTG + (uint32_t)((kt >> 6) & 1) * S1KSTR;
        CP_WAIT0();
        __syncthreads();
        if (kt + 64 < Ss)
            issue_k(kt + 64, S1KSTG + (uint32_t)(((kt >> 6) + 1) & 1) * S1KSTR);

#pragma unroll
        for (int nbp = 0; nbp < 2; nbp++) {
            float accS[4][4];
#pragma unroll
            for (int j = 0; j < 4; j++)
#pragma unroll
                for (int e = 0; e < 4; e++) accS[j][e] = 0.f;

#pragma unroll
            for (int ks = 0; ks < 4; ks++) {
                uint32_t qh[4];
                uint32_t qa = sb + S1QHI + (uint32_t)(w*16 + a_row)*RS + ks*32 + a_kb;
                ldsm_x4(qh, qa);
#pragma unroll
                for (int nb2 = 0; nb2 < 2; nb2++) {
                    int nb = nbp*2 + nb2;
                    uint32_t th[4];
                    uint32_t ad = sb + stg + (uint32_t)(nb*16 + b_row)*RS + ks*32 + b_kb;
                    ldsm_x4(th, ad);
                    int j0 = nb2*2;
                    mma16816(accS[j0],   qh, th);
                    mma16816(accS[j0+1], qh, th+2);
                }
            }

#pragma unroll
            for (int idx = 0; idx < 4; idx++) {
                int col = (nbp*4 + idx)*8 + t4*2;
                float2 mv = *(float2*)&smask[kt + col];
                float m0 = mv.x * MASKMUL, m1 = mv.y * MASKMUL;
                rs0 += ex2f(fmaf(accS[idx][0], EXSCALE, m0))
                     + ex2f(fmaf(accS[idx][1], EXSCALE, m1));
                rs1 += ex2f(fmaf(accS[idx][2], EXSCALE, m0))
                     + ex2f(fmaf(accS[idx][3], EXSCALE, m1));
            }
        }
        __syncthreads();
    }

    rs0 += __shfl_xor_sync(0xffffffffu, rs0, 1);
    rs0 += __shfl_xor_sync(0xffffffffu, rs0, 2);
    rs1 += __shfl_xor_sync(0xffffffffu, rs1, 1);
    rs1 += __shfl_xor_sync(0xffffffffu, rs1, 2);
    if (t4 == 0) {
        size_t base = hb + (size_t)qt*128;
        g_SUM[base + w*16 + tg]     = rs0;
        g_SUM[base + w*16 + tg + 8] = rs1;
    }
}

// ---------------------------------------------------------------------------
// Pass 2: recompute QK (bf16x3), p = exp/rowsum, write attn once,
// O += P V (bf16x3).  cp.async K/V pipeline; mask via __ldg.
// ---------------------------------------------------------------------------
__global__ __launch_bounds__(256, 2) void attn_pv_mma(
    const float* __restrict__ mask, float* __restrict__ attn, int write_attn)
{
    extern __shared__ __align__(16) char sm[];
    uint32_t sb = smem_u32(sm);

    int tid  = threadIdx.x;
    int lane = tid & 31, w = tid >> 5;
    int tg = lane >> 2, t4 = lane & 3;
    int qt = blockIdx.x, h = blockIdx.y, b = blockIdx.z;

    size_t hb = ((size_t)b*Hh + h)*Ss;
    const __nv_bfloat16* Qh = g_Qhi + (hb + (size_t)qt*128)*Dd;
    const __nv_bfloat16* Ql = g_Qlo + (hb + (size_t)qt*128)*Dd;
    const __nv_bfloat16* Kh = g_Khi + hb*Dd;
    const __nv_bfloat16* Kl = g_Klo + hb*Dd;
    const __nv_bfloat16* Vh = g_Vhi + hb*Dd;
    const __nv_bfloat16* Vl = g_Vlo + hb*Dd;
    const float* maskb = mask + (size_t)b*Ss;
    float* attn_base = attn + (hb + (size_t)qt*128)*Ss;

    LOAD_TILE_128(Qh, SQHI)
    LOAD_TILE_128(Ql, SQLO)

    int ld_row = tid >> 3, ld_c8 = (tid & 7) * 8;
    auto issue_kv = [&](int kt, uint32_t stg) {
#pragma unroll
        for (int i = 0; i < 2; i++) {
            int row = ld_row + i*32;
            uint32_t doff = stg + (uint32_t)row*RS + ld_c8*2;
            size_t ga = (size_t)(kt + row)*Dd + ld_c8;
            CP_ASYNC16(sb + doff + S2KHI, Kh + ga);
            CP_ASYNC16(sb + doff + S2KLO, Kl + ga);
            CP_ASYNC16(sb + doff + S2VHI, Vh + ga);
            CP_ASYNC16(sb + doff + S2VLO, Vl + ga);
        }
        CP_COMMIT();
    };

    issue_kv(0, S2STG);
    __syncthreads();

    int a_row = lane & 15;
    int a_kb  = (lane >> 4) * 16;
    int b_row = (lane & 7) + ((lane >> 4) << 3);
    int b_kb  = ((lane >> 3) & 1) * 16;
    int v_koff = ((lane >> 3) & 1) * 8 + (lane & 7);
    int v_noff = (lane >> 4) * 8;

    size_t base = hb + (size_t)qt*128;
    float rinv0 = 1.0f / g_SUM[base + w*16 + tg];
    float rinv1 = 1.0f / g_SUM[base + w*16 + tg + 8];
    int r0g = w*16 + tg;

    float accO[8][4];
#pragma unroll
    for (int nt = 0; nt < 8; nt++)
#pragma unroll
        for (int e = 0; e < 4; e++) accO[nt][e] = 0.f;

    for (int kt = 0; kt < Ss; kt += 64) {
        uint32_t stg = S2STG + (uint32_t)((kt >> 6) & 1) * S2STR;
        CP_WAIT0();
        __syncthreads();
        if (kt + 64 < Ss)
            issue_kv(kt + 64, S2STG + (uint32_t)(((kt >> 6) + 1) & 1) * S2STR);

#pragma unroll
        for (int nbp = 0; nbp < 2; nbp++) {
            float accS[4][4];
#pragma unroll
            for (int j = 0; j < 4; j++)
#pragma unroll
                for (int e = 0; e < 4; e++) accS[j][e] = 0.f;

#pragma unroll
            for (int ks = 0; ks < 4; ks++) {
                uint32_t qh[4], ql[4];
                uint32_t qa = sb + SQHI + (uint32_t)(w*16 + a_row)*RS + ks*32 + a_kb;
                ldsm_x4(qh, qa);
                ldsm_x4(ql, qa + (SQLO - SQHI));
#pragma unroll
                for (int nb2 = 0; nb2 < 2; nb2++) {
                    int nb = nbp*2 + nb2;
                    uint32_t th[4], tl[4];
                    uint32_t ad = sb + stg + S2KHI + (uint32_t)(nb*16 + b_row)*RS + ks*32 + b_kb;
                    ldsm_x4(th, ad);
                    ldsm_x4(tl, ad + (S2KLO - S2KHI));
                    int j0 = nb2*2;
                    mma16816(accS[j0],   qh, th);
                    mma16816(accS[j0],   ql, th);
                    mma16816(accS[j0],   qh, tl);
                    mma16816(accS[j0+1], qh, th+2);
                    mma16816(accS[j0+1], ql, th+2);
                    mma16816(accS[j0+1], qh, tl+2);
                }
            }

            uint32_t ph0[4], ph1[4], pl0[4], pl1[4];
#pragma unroll
            for (int idx = 0; idx < 4; idx++) {
                int col = (nbp*4 + idx)*8 + t4*2;
                float2 mv = __ldg((const float2*)(maskb + kt + col));
                float m0 = mv.x * MASKMUL, m1 = mv.y * MASKMUL;
                float p0 = ex2f(fmaf(accS[idx][0], EXSCALE, m0)) * rinv0;
                float p1 = ex2f(fmaf(accS[idx][1], EXSCALE, m1)) * rinv0;
                float p2 = ex2f(fmaf(accS[idx][2], EXSCALE, m0)) * rinv1;
                float p3 = ex2f(fmaf(accS[idx][3], EXSCALE, m1)) * rinv1;
                if (write_attn) {
                    *(float2*)&attn_base[(size_t)r0g*Ss + kt + col]       = make_float2(p0, p1);
                    *(float2*)&attn_base[(size_t)(r0g + 8)*Ss + kt + col] = make_float2(p2, p3);
                }
                pack2(p0, p1, ph0[idx], pl0[idx]);
                pack2(p2, p3, ph1[idx], pl1[idx]);
            }

#pragma unroll
            for (int nb2 = 0; nb2 < 2; nb2++) {
                int ksv = nbp*2 + nb2;
                uint32_t ah[4] = {ph0[2*nb2], ph1[2*nb2], ph0[2*nb2+1], ph1[2*nb2+1]};
                uint32_t al[4] = {pl0[2*nb2], pl1[2*nb2], pl0[2*nb2+1], pl1[2*nb2+1]};
#pragma unroll
                for (int vb = 0; vb < 4; vb++) {
                    uint32_t th[4], tl[4];
                    uint32_t ad = sb + stg + S2VHI + (uint32_t)(ksv*16 + v_koff)*RS
                                + (vb*16 + v_noff)*2;
                    ldsm_x4_t(th, ad);
                    ldsm_x4_t(tl, ad + (S2VLO - S2VHI));
                    int nt0 = vb*2;
                    mma16816(accO[nt0],   ah, th);
                    mma16816(accO[nt0],   al, th);
                    mma16816(accO[nt0],   ah, tl);
                    mma16816(accO[nt0+1], ah, th+2);
                    mma16816(accO[nt0+1], al, th+2);
                    mma16816(accO[nt0+1], ah, tl+2);
                }
            }
        }
        __syncthreads();
    }

    int q0 = qt*128 + w*16 + tg;
#pragma unroll
    for (int nt = 0; nt < 8; nt++) {
        int d = nt*8 + t4*2;
        float* c0 = g_CTX + ((size_t)b*Ss + q0)*DMm + h*64 + d;
        *(float2*)c0 = make_float2(accO[nt][0], accO[nt][1]);
        float* c1 = g_CTX + ((size_t)b*Ss + q0 + 8)*DMm + h*64 + d;
        *(float2*)c1 = make_float2(accO[nt][2], accO[nt][3]);
    }
}

// ---------------------------------------------------------------------------
// Launch
// ---------------------------------------------------------------------------
extern "C" void kernel_launch(void* const* d_in, const int* in_sizes, int n_in,
                              void* d_out, int out_size)
{
    const float* q    = (const float*)d_in[0];
    const float* k    = (const float*)d_in[1];
    const float* v    = (const float*)d_in[2];
    const float* mask = (const float*)d_in[3];
    const float* Wq   = (const float*)d_in[4];
    const float* bq   = (const float*)d_in[5];
    const float* Wk   = (const float*)d_in[6];
    const float* bk   = (const float*)d_in[7];
    const float* Wv   = (const float*)d_in[8];
    const float* bv   = (const float*)d_in[9];
    const float* Wo   = (const float*)d_in[10];
    const float* bo   = (const float*)d_in[11];

    float* out  = (float*)d_out;
    float* attn = out + (size_t)NTOK*DMm;

    long long need = (long long)NTOK*DMm + (long long)Bb*Hh*Ss*Ss;
    int write_attn = ((long long)out_size >= need) ? 1 : 0;

    cudaFuncSetAttribute(proj_mma_kernel,
                         cudaFuncAttributeMaxDynamicSharedMemorySize, PROJ_SMEM);
    cudaFuncSetAttribute(attn_sum_mma,
                         cudaFuncAttributeMaxDynamicSharedMemorySize, SUM_SMEM);
    cudaFuncSetAttribute(attn_pv_mma,
                         cudaFuncAttributeMaxDynamicSharedMemorySize, PV_SMEM);

    dim3 cgrid((NTOK*DMm)/(256*4), 3);
    convert_split_kernel<<<cgrid, 256>>>(q, k, v, 0);
    dim3 tgrid(DMm/32, DMm/32, 4);
    transW_kernel<<<tgrid, dim3(32, 8)>>>(Wq, Wk, Wv, Wo);

    dim3 ggrid3(DMm/128, NTOK/128, 3);
    proj_mma_kernel<<<ggrid3, 256, PROJ_SMEM>>>(bq, bk, bv, nullptr, 0);

    dim3 agrid(Ss/128, Hh, Bb);
    attn_sum_mma<<<agrid, 256, SUM_SMEM>>>(mask);
    attn_pv_mma<<<agrid, 256, PV_SMEM>>>(mask, attn, write_attn);

    dim3 cgrid1((NTOK*DMm)/(256*4), 1);
    convert_split_kernel<<<cgrid1, 256>>>(nullptr, nullptr, nullptr, 1);
    dim3 ggrid1(DMm/128, NTOK/128, 1);
    proj_mma_kernel<<<ggrid1, 256, PROJ_SMEM>>>(bo, bo, bo, out, 3);
}

// round 14
// speedup vs baseline: 2.7413x; 1.0401x over previous
#include <cuda_runtime.h>
#include <cuda_bf16.h>
#include <cstdint>

#define DMm  1024
#define Hh   16
#define Dd   64
#define Bb   2
#define Ss   2048
#define NTOK (Bb*Ss)   // 4096

// exp(x) = 2^(x*log2e); fold the 1/8 logit scale: 0.125*log2e
#define EXSCALE  0.1803368801111601f
#define MASKMUL  (-1.4426950408889634e9f)

// ---------------------------------------------------------------------------
// Static device scratch
// ---------------------------------------------------------------------------
__device__ float g_CTX[(size_t)NTOK*DMm];
__device__ float g_SUM[(size_t)Bb*Hh*Ss];
__device__ __nv_bfloat16 g_Xhi [(size_t)3*NTOK*DMm];
__device__ __nv_bfloat16 g_Xlo [(size_t)3*NTOK*DMm];
__device__ __nv_bfloat16 g_WThi[(size_t)4*DMm*DMm];
__device__ __nv_bfloat16 g_WTlo[(size_t)4*DMm*DMm];
__device__ __nv_bfloat16 g_Qhi[(size_t)Bb*Hh*Ss*Dd];
__device__ __nv_bfloat16 g_Qlo[(size_t)Bb*Hh*Ss*Dd];
__device__ __nv_bfloat16 g_Khi[(size_t)Bb*Hh*Ss*Dd];
__device__ __nv_bfloat16 g_Klo[(size_t)Bb*Hh*Ss*Dd];
__device__ __nv_bfloat16 g_Vhi[(size_t)Bb*Hh*Ss*Dd];
__device__ __nv_bfloat16 g_Vlo[(size_t)Bb*Hh*Ss*Dd];

// ---------------------------------------------------------------------------
// Helpers (base ISA sm_80+, valid on compute_103)
// ---------------------------------------------------------------------------
__device__ __forceinline__ uint32_t smem_u32(const void* p) {
    uint32_t a;
    asm("{ .reg .u64 t; cvta.to.shared.u64 t, %1; cvt.u32.u64 %0, t; }"
        : "=r"(a) : "l"(p));
    return a;
}

__device__ __forceinline__ void ldsm_x4(uint32_t* r, uint32_t addr) {
    asm volatile("ldmatrix.sync.aligned.m8n8.x4.shared.b16 {%0,%1,%2,%3}, [%4];"
        : "=r"(r[0]), "=r"(r[1]), "=r"(r[2]), "=r"(r[3]) : "r"(addr));
}

__device__ __forceinline__ void ldsm_x4_t(uint32_t* r, uint32_t addr) {
    asm volatile("ldmatrix.sync.aligned.m8n8.x4.trans.shared.b16 {%0,%1,%2,%3}, [%4];"
        : "=r"(r[0]), "=r"(r[1]), "=r"(r[2]), "=r"(r[3]) : "r"(addr));
}

__device__ __forceinline__ void mma16816(float* c, const uint32_t* a, const uint32_t* b) {
    asm volatile(
        "mma.sync.aligned.m16n8k16.row.col.f32.bf16.bf16.f32 "
        "{%0,%1,%2,%3}, {%4,%5,%6,%7}, {%8,%9}, {%0,%1,%2,%3};"
        : "+f"(c[0]), "+f"(c[1]), "+f"(c[2]), "+f"(c[3])
        : "r"(a[0]), "r"(a[1]), "r"(a[2]), "r"(a[3]), "r"(b[0]), "r"(b[1]));
}

#define CP_ASYNC16(dst, src) \
    asm volatile("cp.async.cg.shared.global [%0], [%1], 16;" \
        :: "r"(dst), "l"(src))
#define CP_COMMIT() asm volatile("cp.async.commit_group;")
#define CP_WAIT0()  asm volatile("cp.async.wait_group 0;")

// hardware exp2 (MUFU.EX2): 1 instruction, rel err ~2^-22
__device__ __forceinline__ float ex2f(float x) {
    float r;
    asm("ex2.approx.f32 %0, %1;" : "=f"(r) : "f"(x));
    return r;
}

__device__ __forceinline__ ushort bfu(__nv_bfloat16 h) {
    return __bfloat16_as_ushort(h);
}

__device__ __forceinline__ void split4(float4 v, uint2& hi, uint2& lo) {
    __nv_bfloat16 h0 = __float2bfloat16_rn(v.x);
    __nv_bfloat16 h1 = __float2bfloat16_rn(v.y);
    __nv_bfloat16 h2 = __float2bfloat16_rn(v.z);
    __nv_bfloat16 h3 = __float2bfloat16_rn(v.w);
    hi.x = (uint32_t)bfu(h0) | ((uint32_t)bfu(h1) << 16);
    hi.y = (uint32_t)bfu(h2) | ((uint32_t)bfu(h3) << 16);
    __nv_bfloat16 l0 = __float2bfloat16_rn(v.x - __bfloat162float(h0));
    __nv_bfloat16 l1 = __float2bfloat16_rn(v.y - __bfloat162float(h1));
    __nv_bfloat16 l2 = __float2bfloat16_rn(v.z - __bfloat162float(h2));
    __nv_bfloat16 l3 = __float2bfloat16_rn(v.w - __bfloat162float(h3));
    lo.x = (uint32_t)bfu(l0) | ((uint32_t)bfu(l1) << 16);
    lo.y = (uint32_t)bfu(l2) | ((uint32_t)bfu(l3) << 16);
}

// fast bf16 hi/lo pack of (a,b): lo16 = a, hi16 = b.
__device__ __forceinline__ void pack2(float a, float b, uint32_t& hi, uint32_t& lo) {
    uint32_t u;
    asm("cvt.rn.bf16x2.f32 %0, %1, %2;" : "=r"(u) : "f"(b), "f"(a));
    float af = __uint_as_float(u << 16);
    float bf = __uint_as_float(u & 0xffff0000u);
    hi = u;
    float ra = a - af, rb = b - bf;
    asm("cvt.rn.bf16x2.f32 %0, %1, %2;" : "=r"(lo) : "f"(rb), "f"(ra));
}

// ---------------------------------------------------------------------------
// fp32 -> bf16 hi/lo split.  grid.y selects input (q/k/v); use_ctx reads CTX.
// ---------------------------------------------------------------------------
__global__ __launch_bounds__(256) void convert_split_kernel(
    const float* __restrict__ xq, const float* __restrict__ xk,
    const float* __restrict__ xv, int use_ctx)
{
    int z = blockIdx.y;
    const float* X = use_ctx ? g_CTX : (z == 0 ? xq : (z == 1 ? xk : xv));
    size_t slot = (size_t)z * NTOK * DMm;
    size_t i = ((size_t)blockIdx.x * 256 + threadIdx.x) * 4;
    float4 v = *(const float4*)(X + i);
    uint2 hi, lo;
    split4(v, hi, lo);
    *(uint2*)(g_Xhi + slot + i) = hi;
    *(uint2*)(g_Xlo + slot + i) = lo;
}

// ---------------------------------------------------------------------------
// W [K][N] fp32 -> WT [N][K] bf16 hi/lo.  grid.z selects weight slot.
// ---------------------------------------------------------------------------
__global__ __launch_bounds__(256) void transW_kernel(
    const float* __restrict__ Wq, const float* __restrict__ Wk,
    const float* __restrict__ Wv, const float* __restrict__ Wo)
{
    __shared__ float t[32][33];
    int z = blockIdx.z;
    const float* W = (z == 0) ? Wq : (z == 1) ? Wk : (z == 2) ? Wv : Wo;
    size_t slot = (size_t)z * DMm * DMm;
    int nx = blockIdx.x * 32, ky = blockIdx.y * 32;
    int txx = threadIdx.x, tyy = threadIdx.y;   // block (32, 8)
#pragma unroll
    for (int j = 0; j < 4; j++)
        t[tyy + j*8][txx] = W[(size_t)(ky + tyy + j*8)*DMm + nx + txx];
    __syncthreads();
#pragma unroll
    for (int j = 0; j < 4; j++) {
        float val = t[txx][tyy + j*8];
        __nv_bfloat16 h = __float2bfloat16_rn(val);
        size_t o = slot + (size_t)(nx + tyy + j*8)*DMm + ky + txx;
        g_WThi[o] = h;
        g_WTlo[o] = __float2bfloat16_rn(val - __bfloat162float(h));
    }
}

// ---------------------------------------------------------------------------
// HMMA projection GEMM, cp.async double-buffered (race-free order).
// ---------------------------------------------------------------------------
#define PRS    80
#define P_AHI  0
#define P_ALO  10240
#define P_BHI  20480
#define P_BLO  30720
#define P_SSTR 40960
#define PROJ_SMEM (2*P_SSTR)         // 81920

__global__ __launch_bounds__(256, 2) void proj_mma_kernel(
    const float* __restrict__ bq, const float* __restrict__ bk,
    const float* __restrict__ bv, float* __restrict__ Yext, int base_mode)
{
    extern __shared__ __align__(16) char psm[];
    uint32_t sb = smem_u32(psm);

    int mode = base_mode + blockIdx.z;
    const float* bias = (blockIdx.z == 0) ? bq : (blockIdx.z == 1) ? bk : bv;

    const __nv_bfloat16* Xhi = g_Xhi + (size_t)(mode == 3 ? 0 : mode) * NTOK * DMm;
    const __nv_bfloat16* Xlo = g_Xlo + (size_t)(mode == 3 ? 0 : mode) * NTOK * DMm;
    const __nv_bfloat16* WThi = g_WThi + (size_t)mode * DMm * DMm;
    const __nv_bfloat16* WTlo = g_WTlo + (size_t)mode * DMm * DMm;

    int tid  = threadIdx.x;
    int lane = tid & 31, wid = tid >> 5;
    int warp_m = wid & 1, warp_n = wid >> 1;
    int row0 = blockIdx.y * 128;
    int col0 = blockIdx.x * 128;

    float acc[4][4][4];
#pragma unroll
    for (int mt = 0; mt < 4; mt++)
#pragma unroll
        for (int nt = 0; nt < 4; nt++)
#pragma unroll
            for (int e = 0; e < 4; e++) acc[mt][nt][e] = 0.f;

    int ld_r = tid >> 1;
    int ld_c = (tid & 1) * 2;

    auto issue = [&](int ch, uint32_t st) {
        int k0 = ch * 32;
#pragma unroll
        for (int cc = 0; cc < 2; cc++) {
            int c = ld_c + cc;
            uint32_t doff = st + (uint32_t)ld_r*PRS + c*16;
            size_t ga = (size_t)(row0 + ld_r)*DMm + k0 + c*8;
            CP_ASYNC16(sb + P_AHI + doff, Xhi + ga);
            CP_ASYNC16(sb + P_ALO + doff, Xlo + ga);
            size_t gb = (size_t)(col0 + ld_r)*DMm + k0 + c*8;
            CP_ASYNC16(sb + P_BHI + doff, WThi + gb);
            CP_ASYNC16(sb + P_BLO + doff, WTlo + gb);
        }
        CP_COMMIT();
    };

    issue(0, 0);

    int a_row = lane & 15;
    int a_kb  = (lane >> 4) * 16;
    int b_row = (lane & 7) + ((lane >> 4) << 3);
    int b_kb  = ((lane >> 3) & 1) * 16;

    for (int ch = 0; ch < 32; ch++) {
        uint32_t st = (uint32_t)(ch & 1) * P_SSTR;
        CP_WAIT0();
        __syncthreads();
        if (ch + 1 < 32)
            issue(ch + 1, (uint32_t)((ch + 1) & 1) * P_SSTR);

#pragma unroll
        for (int kk = 0; kk < 2; kk++) {
            int kbyte = kk * 32;
            uint32_t ahi[4][4], alo[4][4];
            uint32_t bhi[4][2], blo[4][2];

#pragma unroll
            for (int mt = 0; mt < 4; mt++) {
                uint32_t ad = sb + st + P_AHI
                            + (uint32_t)(warp_m*64 + mt*16 + a_row)*PRS + kbyte + a_kb;
                ldsm_x4(ahi[mt], ad);
                ldsm_x4(alo[mt], ad + (P_ALO - P_AHI));
            }
#pragma unroll
            for (int p = 0; p < 2; p++) {
                uint32_t bd = sb + st + P_BHI
                            + (uint32_t)(warp_n*32 + p*16 + b_row)*PRS + kbyte + b_kb;
                uint32_t t[4];
                ldsm_x4(t, bd);
                bhi[2*p][0] = t[0]; bhi[2*p][1] = t[1];
                bhi[2*p+1][0] = t[2]; bhi[2*p+1][1] = t[3];
                ldsm_x4(t, bd + (P_BLO - P_BHI));
                blo[2*p][0] = t[0]; blo[2*p][1] = t[1];
                blo[2*p+1][0] = t[2]; blo[2*p+1][1] = t[3];
            }

#pragma unroll
            for (int mt = 0; mt < 4; mt++)
#pragma unroll
                for (int nt = 0; nt < 4; nt++) {
                    mma16816(acc[mt][nt], ahi[mt], bhi[nt]);
                    mma16816(acc[mt][nt], alo[mt], bhi[nt]);
                    mma16816(acc[mt][nt], ahi[mt], blo[nt]);
                }
        }
        __syncthreads();
    }

    int tg = lane >> 2, t4 = lane & 3;
    __nv_bfloat16 *Yhi = nullptr, *Ylo = nullptr;
    if (mode == 0) { Yhi = g_Qhi; Ylo = g_Qlo; }
    else if (mode == 1) { Yhi = g_Khi; Ylo = g_Klo; }
    else if (mode == 2) { Yhi = g_Vhi; Ylo = g_Vlo; }

#pragma unroll
    for (int mt = 0; mt < 4; mt++) {
        int rbase = row0 + warp_m*64 + mt*16 + tg;
#pragma unroll
        for (int nt = 0; nt < 4; nt++) {
            int col = col0 + warp_n*32 + nt*8 + t4*2;
            float b0 = bias[col], b1 = bias[col + 1];
#pragma unroll
            for (int half = 0; half < 2; half++) {
                int r = rbase + half*8;
                float v0 = acc[mt][nt][half*2 + 0] + b0;
                float v1 = acc[mt][nt][half*2 + 1] + b1;
                if (mode == 3) {
                    *(float2*)(Yext + (size_t)r*DMm + col) = make_float2(v0, v1);
                } else {
                    int bi = r >> 11, s = r & (Ss - 1);
                    int h = col >> 6, d = col & 63;
                    size_t off = (((size_t)bi*Hh + h)*Ss + s)*Dd + d;
                    uint32_t hi, lo;
                    pack2(v0, v1, hi, lo);
                    *(uint32_t*)(Yhi + off) = hi;
                    *(uint32_t*)(Ylo + off) = lo;
                }
            }
        }
    }
}

// ---------------------------------------------------------------------------
// Attention smem layouts.  RS = 144B row stride (ldmatrix conflict-free).
// ---------------------------------------------------------------------------
#define RS    144
#define S1QHI   0
#define S1KSTG  18432
#define S1KSTR  9216
#define S1MSK   36864
#define SUM_SMEM (S1MSK + 8192)        // 45056
// pass 2: Qhi/Qlo + 2 stages of (Khi,Vhi,Vlo) + fp32 P staging tile
#define SQHI    0
#define SQLO    18432
#define S2STG   36864
#define S2STR   27648
#define S2KHI   0
#define S2VHI   9216
#define S2VLO   18432
#define S2PS    92160                  // Ps[128][36] fp32 = 18432 B
#define PV_SMEM (S2PS + 18432)         // 110592

#define LOAD_TILE_128(SRC, SOFF)                                             \
    _Pragma("unroll")                                                        \
    for (int i = 0; i < 4; i++) {                                            \
        int f = tid + i*256;                                                 \
        int row = f >> 3, c8 = (f & 7) * 8;                                  \
        *(uint4*)(sm + (SOFF) + row*RS + c8*2) =                             \
            *(const uint4*)((SRC) + (size_t)row*Dd + c8);                    \
    }

// ---------------------------------------------------------------------------
// Pass 1: rowsums of exp(QK^T/8 + mask), HI-ONLY QK, cp.async K pipeline.
// ---------------------------------------------------------------------------
__global__ __launch_bounds__(256, 3) void attn_sum_mma(const float* __restrict__ mask)
{
    extern __shared__ __align__(16) char sm[];
    uint32_t sb = smem_u32(sm);
    float* smask = (float*)(sm + S1MSK);

    int tid  = threadIdx.x;
    int lane = tid & 31, w = tid >> 5;
    int tg = lane >> 2, t4 = lane & 3;
    int qt = blockIdx.x, h = blockIdx.y, b = blockIdx.z;

    size_t hb = ((size_t)b*Hh + h)*Ss;
    const __nv_bfloat16* Qh = g_Qhi + (hb + (size_t)qt*128)*Dd;
    const __nv_bfloat16* Kh = g_Khi + hb*Dd;

#pragma unroll
    for (int i = 0; i < 2; i++) {
        int f = tid + i*256;
        *(float4*)&smask[f*4] = *(const float4*)(mask + (size_t)b*Ss + f*4);
    }
    LOAD_TILE_128(Qh, S1QHI)

    int ld_row = tid >> 3, ld_c8 = (tid & 7) * 8;
    auto issue_k = [&](int kt, uint32_t stg) {
#pragma unroll
        for (int i = 0; i < 2; i++) {
            int row = ld_row + i*32;
            uint32_t doff = stg + (uint32_t)row*RS + ld_c8*2;
            CP_ASYNC16(sb + doff, Kh + (size_t)(kt + row)*Dd + ld_c8);
        }
        CP_COMMIT();
    };

    issue_k(0, S1KSTG);
    __syncthreads();

    int a_row = lane & 15;
    int a_kb  = (lane >> 4) * 16;
    int b_row = (lane & 7) + ((lane >> 4) << 3);
    int b_kb  = ((lane >> 3) & 1) * 16;

    float rs0 = 0.f, rs1 = 0.f;

    for (int kt = 0; kt < Ss; kt += 64) {
        uint32_t stg = S1KSTG + (uint32_t)((kt >> 6) & 1) * S1KSTR;
        CP_WAIT0();
        __syncthreads();
        if (kt + 64 < Ss)
            issue_k(kt + 64, S1KSTG + (uint32_t)(((kt >> 6) + 1) & 1) * S1KSTR);

#pragma unroll
        for (int nbp = 0; nbp < 2; nbp++) {
            float accS[4][4];
#pragma unroll
            for (int j = 0; j < 4; j++)
#pragma unroll
                for (int e = 0; e < 4; e++) accS[j][e] = 0.f;

#pragma unroll
            for (int ks = 0; ks < 4; ks++) {
                uint32_t qh[4];
                uint32_t qa = sb + S1QHI + (uint32_t)(w*16 + a_row)*RS + ks*32 + a_kb;
                ldsm_x4(qh, qa);
#pragma unroll
                for (int nb2 = 0; nb2 < 2; nb2++) {
                    int nb = nbp*2 + nb2;
                    uint32_t th[4];
                    uint32_t ad = sb + stg + (uint32_t)(nb*16 + b_row)*RS + ks*32 + b_kb;
                    ldsm_x4(th, ad);
                    int j0 = nb2*2;
                    mma16816(accS[j0],   qh, th);
                    mma16816(accS[j0+1], qh, th+2);
                }
            }

#pragma unroll
            for (int idx = 0; idx < 4; idx++) {
                int col = (nbp*4 + idx)*8 + t4*2;
                float2 mv = *(float2*)&smask[kt + col];
                float m0 = mv.x * MASKMUL, m1 = mv.y * MASKMUL;
                rs0 += ex2f(fmaf(accS[idx][0], EXSCALE, m0))
                     + ex2f(fmaf(accS[idx][1], EXSCALE, m1));
                rs1 += ex2f(fmaf(accS[idx][2], EXSCALE, m0))
                     + ex2f(fmaf(accS[idx][3], EXSCALE, m1));
            }
        }
        __syncthreads();
    }

    rs0 += __shfl_xor_sync(0xffffffffu, rs0, 1);
    rs0 += __shfl_xor_sync(0xffffffffu, rs0, 2);
    rs1 += __shfl_xor_sync(0xffffffffu, rs1, 1);
    rs1 += __shfl_xor_sync(0xffffffffu, rs1, 2);
    if (t4 == 0) {
        size_t base = hb + (size_t)qt*128;
        g_SUM[base + w*16 + tg]     = rs0;
        g_SUM[base + w*16 + tg + 8] = rs1;
    }
}

// ---------------------------------------------------------------------------
// Pass 2: QK (qh*kh + ql*kh, K-lo dropped), p = exp/rowsum, attn written
// via smem-staged coalesced rows, O += P V (bf16x3).  cp.async K/V pipeline.
// ---------------------------------------------------------------------------
__global__ __launch_bounds__(256, 2) void attn_pv_mma(
    const float* __restrict__ mask, float* __restrict__ attn, int write_attn)
{
    extern __shared__ __align__(16) char sm[];
    uint32_t sb = smem_u32(sm);
    float* Ps = (float*)(sm + S2PS);

    int tid  = threadIdx.x;
    int lane = tid & 31, w = tid >> 5;
    int tg = lane >> 2, t4 = lane & 3;
    int qt = blockIdx.x, h = blockIdx.y, b = blockIdx.z;

    size_t hb = ((size_t)b*Hh + h)*Ss;
    const __nv_bfloat16* Qh = g_Qhi + (hb + (size_t)qt*128)*Dd;
    const __nv_bfloat16* Ql = g_Qlo + (hb + (size_t)qt*128)*Dd;
    const __nv_bfloat16* Kh = g_Khi + hb*Dd;
    const __nv_bfloat16* Vh = g_Vhi + hb*Dd;
    const __nv_bfloat16* Vl = g_Vlo + hb*Dd;
    const float* maskb = mask + (size_t)b*Ss;
    float* attn_base = attn + (hb + (size_t)qt*128)*Ss;

    LOAD_TILE_128(Qh, SQHI)
    LOAD_TILE_128(Ql, SQLO)

    int ld_row = tid >> 3, ld_c8 = (tid & 7) * 8;
    auto issue_kv = [&](int kt, uint32_t stg) {
#pragma unroll
        for (int i = 0; i < 2; i++) {
            int row = ld_row + i*32;
            uint32_t doff = stg + (uint32_t)row*RS + ld_c8*2;
            size_t ga = (size_t)(kt + row)*Dd + ld_c8;
            CP_ASYNC16(sb + doff + S2KHI, Kh + ga);
            CP_ASYNC16(sb + doff + S2VHI, Vh + ga);
            CP_ASYNC16(sb + doff + S2VLO, Vl + ga);
        }
        CP_COMMIT();
    };

    issue_kv(0, S2STG);
    __syncthreads();

    int a_row = lane & 15;
    int a_kb  = (lane >> 4) * 16;
    int b_row = (lane & 7) + ((lane >> 4) << 3);
    int b_kb  = ((lane >> 3) & 1) * 16;
    int v_koff = ((lane >> 3) & 1) * 8 + (lane & 7);
    int v_noff = (lane >> 4) * 8;

    size_t base = hb + (size_t)qt*128;
    float rinv0 = 1.0f / g_SUM[base + w*16 + tg];
    float rinv1 = 1.0f / g_SUM[base + w*16 + tg + 8];
    int r0g = w*16 + tg;

    float accO[8][4];
#pragma unroll
    for (int nt = 0; nt < 8; nt++)
#pragma unroll
        for (int e = 0; e < 4; e++) accO[nt][e] = 0.f;

    for (int kt = 0; kt < Ss; kt += 64) {
        uint32_t stg = S2STG + (uint32_t)((kt >> 6) & 1) * S2STR;
        CP_WAIT0();
        __syncthreads();
        if (kt + 64 < Ss)
            issue_kv(kt + 64, S2STG + (uint32_t)(((kt >> 6) + 1) & 1) * S2STR);

#pragma unroll
        for (int nbp = 0; nbp < 2; nbp++) {
            // ---- QK (K-lo dropped): q = qh + ql against kh ----
            float accS[4][4];
#pragma unroll
            for (int j = 0; j < 4; j++)
#pragma unroll
                for (int e = 0; e < 4; e++) accS[j][e] = 0.f;

#pragma unroll
            for (int ks = 0; ks < 4; ks++) {
                uint32_t qh[4], ql[4];
                uint32_t qa = sb + SQHI + (uint32_t)(w*16 + a_row)*RS + ks*32 + a_kb;
                ldsm_x4(qh, qa);
                ldsm_x4(ql, qa + (SQLO - SQHI));
#pragma unroll
                for (int nb2 = 0; nb2 < 2; nb2++) {
                    int nb = nbp*2 + nb2;
                    uint32_t th[4];
                    uint32_t ad = sb + stg + S2KHI + (uint32_t)(nb*16 + b_row)*RS + ks*32 + b_kb;
                    ldsm_x4(th, ad);
                    int j0 = nb2*2;
                    mma16816(accS[j0],   qh, th);
                    mma16816(accS[j0],   ql, th);
                    mma16816(accS[j0+1], qh, th+2);
                    mma16816(accS[j0+1], ql, th+2);
                }
            }

            // ---- exp, normalize, stage P in smem, pack for PV ----
            uint32_t ph0[4], ph1[4], pl0[4], pl1[4];
#pragma unroll
            for (int idx = 0; idx < 4; idx++) {
                int lc  = idx*8 + t4*2;           // 0..30 within 32-col block
                int col = nbp*32 + lc;
                float2 mv = __ldg((const float2*)(maskb + kt + col));
                float m0 = mv.x * MASKMUL, m1 = mv.y * MASKMUL;
                float p0 = ex2f(fmaf(accS[idx][0], EXSCALE, m0)) * rinv0;
                float p1 = ex2f(fmaf(accS[idx][1], EXSCALE, m1)) * rinv0;
                float p2 = ex2f(fmaf(accS[idx][2], EXSCALE, m0)) * rinv1;
                float p3 = ex2f(fmaf(accS[idx][3], EXSCALE, m1)) * rinv1;
                if (write_attn) {
                    *(float2*)&Ps[(size_t)r0g*36 + lc]       = make_float2(p0, p1);
                    *(float2*)&Ps[(size_t)(r0g + 8)*36 + lc] = make_float2(p2, p3);
                }
                pack2(p0, p1, ph0[idx], pl0[idx]);
                pack2(p2, p3, ph1[idx], pl1[idx]);
            }

            if (write_attn) {
                __syncthreads();                   // Ps complete
                // coalesced store: 8 lanes cover one 32-col row (128B)
#pragma unroll
                for (int i = 0; i < 4; i++) {
                    int row = (tid >> 3) + i*32;
                    int c4  = (tid & 7) * 4;
                    float4 v = *(float4*)&Ps[(size_t)row*36 + c4];
                    *(float4*)&attn_base[(size_t)row*Ss + kt + nbp*32 + c4] = v;
                }
            }

            // ---- PV (bf16x3) ----
#pragma unroll
            for (int nb2 = 0; nb2 < 2; nb2++) {
                int ksv = nbp*2 + nb2;
                uint32_t ah[4] = {ph0[2*nb2], ph1[2*nb2], ph0[2*nb2+1], ph1[2*nb2+1]};
                uint32_t al[4] = {pl0[2*nb2], pl1[2*nb2], pl0[2*nb2+1], pl1[2*nb2+1]};
#pragma unroll
                for (int vb = 0; vb < 4; vb++) {
                    uint32_t th[4], tl[4];
                    uint32_t ad = sb + stg + S2VHI + (uint32_t)(ksv*16 + v_koff)*RS
                                + (vb*16 + v_noff)*2;
                    ldsm_x4_t(th, ad);
                    ldsm_x4_t(tl, ad + (S2VLO - S2VHI));
                    int nt0 = vb*2;
                    mma16816(accO[nt0],   ah, th);
                    mma16816(accO[nt0],   al, th);
                    mma16816(accO[nt0],   ah, tl);
                    mma16816(accO[nt0+1], ah, th+2);
                    mma16816(accO[nt0+1], al, th+2);
                    mma16816(accO[nt0+1], ah, tl+2);
                }
            }
            if (write_attn)
                __syncthreads();                   // Ps reads done before next STS
        }
        __syncthreads();                           // stage reads done before refill
    }

    int q0 = qt*128 + w*16 + tg;
#pragma unroll
    for (int nt = 0; nt < 8; nt++) {
        int d = nt*8 + t4*2;
        float* c0 = g_CTX + ((size_t)b*Ss + q0)*DMm + h*64 + d;
        *(float2*)c0 = make_float2(accO[nt][0], accO[nt][1]);
        float* c1 = g_CTX + ((size_t)b*Ss + q0 + 8)*DMm + h*64 + d;
        *(float2*)c1 = make_float2(accO[nt][2], accO[nt][3]);
    }
}

// ---------------------------------------------------------------------------
// Launch
// ---------------------------------------------------------------------------
extern "C" void kernel_launch(void* const* d_in, const int* in_sizes, int n_in,
                              void* d_out, int out_size)
{
    const float* q    = (const float*)d_in[0];
    const float* k    = (const float*)d_in[1];
    const float* v    = (const float*)d_in[2];
    const float* mask = (const float*)d_in[3];
    const float* Wq   = (const float*)d_in[4];
    const float* bq   = (const float*)d_in[5];
    const float* Wk   = (const float*)d_in[6];
    const float* bk   = (const float*)d_in[7];
    const float* Wv   = (const float*)d_in[8];
    const float* bv   = (const float*)d_in[9];
    const float* Wo   = (const float*)d_in[10];
    const float* bo   = (const float*)d_in[11];

    float* out  = (float*)d_out;
    float* attn = out + (size_t)NTOK*DMm;

    long long need = (long long)NTOK*DMm + (long long)Bb*Hh*Ss*Ss;
    int write_attn = ((long long)out_size >= need) ? 1 : 0;

    cudaFuncSetAttribute(proj_mma_kernel,
                         cudaFuncAttributeMaxDynamicSharedMemorySize, PROJ_SMEM);
    cudaFuncSetAttribute(attn_sum_mma,
                         cudaFuncAttributeMaxDynamicSharedMemorySize, SUM_SMEM);
    cudaFuncSetAttribute(attn_pv_mma,
                         cudaFuncAttributeMaxDynamicSharedMemorySize, PV_SMEM);

    dim3 cgrid((NTOK*DMm)/(256*4), 3);
    convert_split_kernel<<<cgrid, 256>>>(q, k, v, 0);
    dim3 tgrid(DMm/32, DMm/32, 4);
    transW_kernel<<<tgrid, dim3(32, 8)>>>(Wq, Wk, Wv, Wo);

    dim3 ggrid3(DMm/128, NTOK/128, 3);
    proj_mma_kernel<<<ggrid3, 256, PROJ_SMEM>>>(bq, bk, bv, nullptr, 0);

    dim3 agrid(Ss/128, Hh, Bb);
    attn_sum_mma<<<agrid, 256, SUM_SMEM>>>(mask);
    attn_pv_mma<<<agrid, 256, PV_SMEM>>>(mask, attn, write_attn);

    dim3 cgrid1((NTOK*DMm)/(256*4), 1);
    convert_split_kernel<<<cgrid1, 256>>>(nullptr, nullptr, nullptr, 1);
    dim3 ggrid1(DMm/128, NTOK/128, 1);
    proj_mma_kernel<<<ggrid1, 256, PROJ_SMEM>>>(bo, bo, bo, out, 3);
}

// round 15
// speedup vs baseline: 2.7930x; 1.0189x over previous
#include <cuda_runtime.h>
#include <cuda_bf16.h>
#include <cstdint>

#define DMm  1024
#define Hh   16
#define Dd   64
#define Bb   2
#define Ss   2048
#define NTOK (Bb*Ss)   // 4096

// exp(x) = 2^(x*log2e); fold the 1/8 logit scale: 0.125*log2e
#define EXSCALE  0.1803368801111601f
#define MASKMUL  (-1.4426950408889634e9f)

// ---------------------------------------------------------------------------
// Static device scratch
// ---------------------------------------------------------------------------
__device__ float g_SUM[(size_t)Bb*Hh*Ss];
__device__ __nv_bfloat16 g_Xhi [(size_t)3*NTOK*DMm];   // slot 0 reused for O (pre out-proj)
__device__ __nv_bfloat16 g_Xlo [(size_t)3*NTOK*DMm];
__device__ __nv_bfloat16 g_WThi[(size_t)4*DMm*DMm];
__device__ __nv_bfloat16 g_WTlo[(size_t)4*DMm*DMm];
__device__ __nv_bfloat16 g_Qhi[(size_t)Bb*Hh*Ss*Dd];
__device__ __nv_bfloat16 g_Qlo[(size_t)Bb*Hh*Ss*Dd];
__device__ __nv_bfloat16 g_Khi[(size_t)Bb*Hh*Ss*Dd];
__device__ __nv_bfloat16 g_Klo[(size_t)Bb*Hh*Ss*Dd];
__device__ __nv_bfloat16 g_Vhi[(size_t)Bb*Hh*Ss*Dd];
__device__ __nv_bfloat16 g_Vlo[(size_t)Bb*Hh*Ss*Dd];

// ---------------------------------------------------------------------------
// Helpers (base ISA sm_80+, valid on compute_103)
// ---------------------------------------------------------------------------
__device__ __forceinline__ uint32_t smem_u32(const void* p) {
    uint32_t a;
    asm("{ .reg .u64 t; cvta.to.shared.u64 t, %1; cvt.u32.u64 %0, t; }"
        : "=r"(a) : "l"(p));
    return a;
}

__device__ __forceinline__ void ldsm_x4(uint32_t* r, uint32_t addr) {
    asm volatile("ldmatrix.sync.aligned.m8n8.x4.shared.b16 {%0,%1,%2,%3}, [%4];"
        : "=r"(r[0]), "=r"(r[1]), "=r"(r[2]), "=r"(r[3]) : "r"(addr));
}

__device__ __forceinline__ void ldsm_x4_t(uint32_t* r, uint32_t addr) {
    asm volatile("ldmatrix.sync.aligned.m8n8.x4.trans.shared.b16 {%0,%1,%2,%3}, [%4];"
        : "=r"(r[0]), "=r"(r[1]), "=r"(r[2]), "=r"(r[3]) : "r"(addr));
}

__device__ __forceinline__ void mma16816(float* c, const uint32_t* a, const uint32_t* b) {
    asm volatile(
        "mma.sync.aligned.m16n8k16.row.col.f32.bf16.bf16.f32 "
        "{%0,%1,%2,%3}, {%4,%5,%6,%7}, {%8,%9}, {%0,%1,%2,%3};"
        : "+f"(c[0]), "+f"(c[1]), "+f"(c[2]), "+f"(c[3])
        : "r"(a[0]), "r"(a[1]), "r"(a[2]), "r"(a[3]), "r"(b[0]), "r"(b[1]));
}

#define CP_ASYNC16(dst, src) \
    asm volatile("cp.async.cg.shared.global [%0], [%1], 16;" \
        :: "r"(dst), "l"(src))
#define CP_COMMIT() asm volatile("cp.async.commit_group;")
#define CP_WAIT0()  asm volatile("cp.async.wait_group 0;")

// hardware exp2 (MUFU.EX2)
__device__ __forceinline__ float ex2f(float x) {
    float r;
    asm("ex2.approx.f32 %0, %1;" : "=f"(r) : "f"(x));
    return r;
}

__device__ __forceinline__ ushort bfu(__nv_bfloat16 h) {
    return __bfloat16_as_ushort(h);
}

__device__ __forceinline__ void split4(float4 v, uint2& hi, uint2& lo) {
    __nv_bfloat16 h0 = __float2bfloat16_rn(v.x);
    __nv_bfloat16 h1 = __float2bfloat16_rn(v.y);
    __nv_bfloat16 h2 = __float2bfloat16_rn(v.z);
    __nv_bfloat16 h3 = __float2bfloat16_rn(v.w);
    hi.x = (uint32_t)bfu(h0) | ((uint32_t)bfu(h1) << 16);
    hi.y = (uint32_t)bfu(h2) | ((uint32_t)bfu(h3) << 16);
    __nv_bfloat16 l0 = __float2bfloat16_rn(v.x - __bfloat162float(h0));
    __nv_bfloat16 l1 = __float2bfloat16_rn(v.y - __bfloat162float(h1));
    __nv_bfloat16 l2 = __float2bfloat16_rn(v.z - __bfloat162float(h2));
    __nv_bfloat16 l3 = __float2bfloat16_rn(v.w - __bfloat162float(h3));
    lo.x = (uint32_t)bfu(l0) | ((uint32_t)bfu(l1) << 16);
    lo.y = (uint32_t)bfu(l2) | ((uint32_t)bfu(l3) << 16);
}

// fast bf16 hi/lo pack of (a,b): lo16 = a, hi16 = b.
__device__ __forceinline__ void pack2(float a, float b, uint32_t& hi, uint32_t& lo) {
    uint32_t u;
    asm("cvt.rn.bf16x2.f32 %0, %1, %2;" : "=r"(u) : "f"(b), "f"(a));
    float af = __uint_as_float(u << 16);
    float bf = __uint_as_float(u & 0xffff0000u);
    hi = u;
    float ra = a - af, rb = b - bf;
    asm("cvt.rn.bf16x2.f32 %0, %1, %2;" : "=r"(lo) : "f"(rb), "f"(ra));
}

// ---------------------------------------------------------------------------
// fp32 -> bf16 hi/lo split of q/k/v inputs.  grid.y selects input.
// ---------------------------------------------------------------------------
__global__ __launch_bounds__(256) void convert_split_kernel(
    const float* __restrict__ xq, const float* __restrict__ xk,
    const float* __restrict__ xv)
{
    int z = blockIdx.y;
    const float* X = (z == 0) ? xq : (z == 1) ? xk : xv;
    size_t slot = (size_t)z * NTOK * DMm;
    size_t i = ((size_t)blockIdx.x * 256 + threadIdx.x) * 4;
    float4 v = *(const float4*)(X + i);
    uint2 hi, lo;
    split4(v, hi, lo);
    *(uint2*)(g_Xhi + slot + i) = hi;
    *(uint2*)(g_Xlo + slot + i) = lo;
}

// ---------------------------------------------------------------------------
// W [K][N] fp32 -> WT [N][K] bf16 hi/lo.  grid.z selects weight slot.
// ---------------------------------------------------------------------------
__global__ __launch_bounds__(256) void transW_kernel(
    const float* __restrict__ Wq, const float* __restrict__ Wk,
    const float* __restrict__ Wv, const float* __restrict__ Wo)
{
    __shared__ float t[32][33];
    int z = blockIdx.z;
    const float* W = (z == 0) ? Wq : (z == 1) ? Wk : (z == 2) ? Wv : Wo;
    size_t slot = (size_t)z * DMm * DMm;
    int nx = blockIdx.x * 32, ky = blockIdx.y * 32;
    int txx = threadIdx.x, tyy = threadIdx.y;   // block (32, 8)
#pragma unroll
    for (int j = 0; j < 4; j++)
        t[tyy + j*8][txx] = W[(size_t)(ky + tyy + j*8)*DMm + nx + txx];
    __syncthreads();
#pragma unroll
    for (int j = 0; j < 4; j++) {
        float val = t[txx][tyy + j*8];
        __nv_bfloat16 h = __float2bfloat16_rn(val);
        size_t o = slot + (size_t)(nx + tyy + j*8)*DMm + ky + txx;
        g_WThi[o] = h;
        g_WTlo[o] = __float2bfloat16_rn(val - __bfloat162float(h));
    }
}

// ---------------------------------------------------------------------------
// HMMA projection GEMM, cp.async double-buffered (race-free order).
// ---------------------------------------------------------------------------
#define PRS    80
#define P_AHI  0
#define P_ALO  10240
#define P_BHI  20480
#define P_BLO  30720
#define P_SSTR 40960
#define PROJ_SMEM (2*P_SSTR)         // 81920

__global__ __launch_bounds__(256, 2) void proj_mma_kernel(
    const float* __restrict__ bq, const float* __restrict__ bk,
    const float* __restrict__ bv, float* __restrict__ Yext, int base_mode)
{
    extern __shared__ __align__(16) char psm[];
    uint32_t sb = smem_u32(psm);

    int mode = base_mode + blockIdx.z;
    const float* bias = (blockIdx.z == 0) ? bq : (blockIdx.z == 1) ? bk : bv;

    const __nv_bfloat16* Xhi = g_Xhi + (size_t)(mode == 3 ? 0 : mode) * NTOK * DMm;
    const __nv_bfloat16* Xlo = g_Xlo + (size_t)(mode == 3 ? 0 : mode) * NTOK * DMm;
    const __nv_bfloat16* WThi = g_WThi + (size_t)mode * DMm * DMm;
    const __nv_bfloat16* WTlo = g_WTlo + (size_t)mode * DMm * DMm;

    int tid  = threadIdx.x;
    int lane = tid & 31, wid = tid >> 5;
    int warp_m = wid & 1, warp_n = wid >> 1;
    int row0 = blockIdx.y * 128;
    int col0 = blockIdx.x * 128;

    float acc[4][4][4];
#pragma unroll
    for (int mt = 0; mt < 4; mt++)
#pragma unroll
        for (int nt = 0; nt < 4; nt++)
#pragma unroll
            for (int e = 0; e < 4; e++) acc[mt][nt][e] = 0.f;

    int ld_r = tid >> 1;
    int ld_c = (tid & 1) * 2;

    auto issue = [&](int ch, uint32_t st) {
        int k0 = ch * 32;
#pragma unroll
        for (int cc = 0; cc < 2; cc++) {
            int c = ld_c + cc;
            uint32_t doff = st + (uint32_t)ld_r*PRS + c*16;
            size_t ga = (size_t)(row0 + ld_r)*DMm + k0 + c*8;
            CP_ASYNC16(sb + P_AHI + doff, Xhi + ga);
            CP_ASYNC16(sb + P_ALO + doff, Xlo + ga);
            size_t gb = (size_t)(col0 + ld_r)*DMm + k0 + c*8;
            CP_ASYNC16(sb + P_BHI + doff, WThi + gb);
            CP_ASYNC16(sb + P_BLO + doff, WTlo + gb);
        }
        CP_COMMIT();
    };

    issue(0, 0);

    int a_row = lane & 15;
    int a_kb  = (lane >> 4) * 16;
    int b_row = (lane & 7) + ((lane >> 4) << 3);
    int b_kb  = ((lane >> 3) & 1) * 16;

    for (int ch = 0; ch < 32; ch++) {
        uint32_t st = (uint32_t)(ch & 1) * P_SSTR;
        CP_WAIT0();
        __syncthreads();
        if (ch + 1 < 32)
            issue(ch + 1, (uint32_t)((ch + 1) & 1) * P_SSTR);

#pragma unroll
        for (int kk = 0; kk < 2; kk++) {
            int kbyte = kk * 32;
            uint32_t ahi[4][4], alo[4][4];
            uint32_t bhi[4][2], blo[4][2];

#pragma unroll
            for (int mt = 0; mt < 4; mt++) {
                uint32_t ad = sb + st + P_AHI
                            + (uint32_t)(warp_m*64 + mt*16 + a_row)*PRS + kbyte + a_kb;
                ldsm_x4(ahi[mt], ad);
                ldsm_x4(alo[mt], ad + (P_ALO - P_AHI));
            }
#pragma unroll
            for (int p = 0; p < 2; p++) {
                uint32_t bd = sb + st + P_BHI
                            + (uint32_t)(warp_n*32 + p*16 + b_row)*PRS + kbyte + b_kb;
                uint32_t t[4];
                ldsm_x4(t, bd);
                bhi[2*p][0] = t[0]; bhi[2*p][1] = t[1];
                bhi[2*p+1][0] = t[2]; bhi[2*p+1][1] = t[3];
                ldsm_x4(t, bd + (P_BLO - P_BHI));
                blo[2*p][0] = t[0]; blo[2*p][1] = t[1];
                blo[2*p+1][0] = t[2]; blo[2*p+1][1] = t[3];
            }

#pragma unroll
            for (int mt = 0; mt < 4; mt++)
#pragma unroll
                for (int nt = 0; nt < 4; nt++) {
                    mma16816(acc[mt][nt], ahi[mt], bhi[nt]);
                    mma16816(acc[mt][nt], alo[mt], bhi[nt]);
                    mma16816(acc[mt][nt], ahi[mt], blo[nt]);
                }
        }
        __syncthreads();
    }

    int tg = lane >> 2, t4 = lane & 3;
    __nv_bfloat16 *Yhi = nullptr, *Ylo = nullptr;
    if (mode == 0) { Yhi = g_Qhi; Ylo = g_Qlo; }
    else if (mode == 1) { Yhi = g_Khi; Ylo = g_Klo; }
    else if (mode == 2) { Yhi = g_Vhi; Ylo = g_Vlo; }

#pragma unroll
    for (int mt = 0; mt < 4; mt++) {
        int rbase = row0 + warp_m*64 + mt*16 + tg;
#pragma unroll
        for (int nt = 0; nt < 4; nt++) {
            int col = col0 + warp_n*32 + nt*8 + t4*2;
            float b0 = bias[col], b1 = bias[col + 1];
#pragma unroll
            for (int half = 0; half < 2; half++) {
                int r = rbase + half*8;
                float v0 = acc[mt][nt][half*2 + 0] + b0;
                float v1 = acc[mt][nt][half*2 + 1] + b1;
                if (mode == 3) {
                    *(float2*)(Yext + (size_t)r*DMm + col) = make_float2(v0, v1);
                } else {
                    int bi = r >> 11, s = r & (Ss - 1);
                    int h = col >> 6, d = col & 63;
                    size_t off = (((size_t)bi*Hh + h)*Ss + s)*Dd + d;
                    uint32_t hi, lo;
                    pack2(v0, v1, hi, lo);
                    *(uint32_t*)(Yhi + off) = hi;
                    *(uint32_t*)(Ylo + off) = lo;
                }
            }
        }
    }
}

// ---------------------------------------------------------------------------
// Attention smem layouts.  RS = 144B row stride (ldmatrix conflict-free).
// ---------------------------------------------------------------------------
#define RS    144
#define S1QHI   0
#define S1KSTG  18432
#define S1KSTR  9216
#define S1MSK   36864
#define SUM_SMEM (S1MSK + 8192)        // 45056
// pass 2: Qhi/Qlo + 2 stages of (Khi,Vhi,Vlo) + fp32 P staging tile
#define SQHI    0
#define SQLO    18432
#define S2STG   36864
#define S2STR   27648
#define S2KHI   0
#define S2VHI   9216
#define S2VLO   18432
#define S2PS    92160                  // Ps[128][36] fp32 = 18432 B
#define PV_SMEM (S2PS + 18432)         // 110592

#define LOAD_TILE_128(SRC, SOFF)                                             \
    _Pragma("unroll")                                                        \
    for (int i = 0; i < 4; i++) {                                            \
        int f = tid + i*256;                                                 \
        int row = f >> 3, c8 = (f & 7) * 8;                                  \
        *(uint4*)(sm + (SOFF) + row*RS + c8*2) =                             \
            *(const uint4*)((SRC) + (size_t)row*Dd + c8);                    \
    }

// ---------------------------------------------------------------------------
// Pass 1: rowsums of exp(QK^T/8 + mask), HI-ONLY QK, cp.async K pipeline.
// ---------------------------------------------------------------------------
__global__ __launch_bounds__(256, 3) void attn_sum_mma(const float* __restrict__ mask)
{
    extern __shared__ __align__(16) char sm[];
    uint32_t sb = smem_u32(sm);
    float* smask = (float*)(sm + S1MSK);

    int tid  = threadIdx.x;
    int lane = tid & 31, w = tid >> 5;
    int tg = lane >> 2, t4 = lane & 3;
    int qt = blockIdx.x, h = blockIdx.y, b = blockIdx.z;

    size_t hb = ((size_t)b*Hh + h)*Ss;
    const __nv_bfloat16* Qh = g_Qhi + (hb + (size_t)qt*128)*Dd;
    const __nv_bfloat16* Kh = g_Khi + hb*Dd;

#pragma unroll
    for (int i = 0; i < 2; i++) {
        int f = tid + i*256;
        *(float4*)&smask[f*4] = *(const float4*)(mask + (size_t)b*Ss + f*4);
    }
    LOAD_TILE_128(Qh, S1QHI)

    int ld_row = tid >> 3, ld_c8 = (tid & 7) * 8;
    auto issue_k = [&](int kt, uint32_t stg) {
#pragma unroll
        for (int i = 0; i < 2; i++) {
            int row = ld_row + i*32;
            uint32_t doff = stg + (uint32_t)row*RS + ld_c8*2;
            CP_ASYNC16(sb + doff, Kh + (size_t)(kt + row)*Dd + ld_c8);
        }
        CP_COMMIT();
    };

    issue_k(0, S1KSTG);
    __syncthreads();

    int a_row = lane & 15;
    int a_kb  = (lane >> 4) * 16;
    int b_row = (lane & 7) + ((lane >> 4) << 3);
    int b_kb  = ((lane >> 3) & 1) * 16;

    float rs0 = 0.f, rs1 = 0.f;

    for (int kt = 0; kt < Ss; kt += 64) {
        uint32_t stg = S1KSTG + (uint32_t)((kt >> 6) & 1) * S1KSTR;
        CP_WAIT0();
        __syncthreads();
        if (kt + 64 < Ss)
            issue_k(kt + 64, S1KSTG + (uint32_t)(((kt >> 6) + 1) & 1) * S1KSTR);

#pragma unroll
        for (int nbp = 0; nbp < 2; nbp++) {
            float accS[4][4];
#pragma unroll
            for (int j = 0; j < 4; j++)
#pragma unroll
                for (int e = 0; e < 4; e++) accS[j][e] = 0.f;

#pragma unroll
            for (int ks = 0; ks < 4; ks++) {
                uint32_t qh[4];
                uint32_t qa = sb + S1QHI + (uint32_t)(w*16 + a_row)*RS + ks*32 + a_kb;
                ldsm_x4(qh, qa);
#pragma unroll
                for (int nb2 = 0; nb2 < 2; nb2++) {
                    int nb = nbp*2 + nb2;
                    uint32_t th[4];
                    uint32_t ad = sb + stg + (uint32_t)(nb*16 + b_row)*RS + ks*32 + b_kb;
                    ldsm_x4(th, ad);
                    int j0 = nb2*2;
                    mma16816(accS[j0],   qh, th);
                    mma16816(accS[j0+1], qh, th+2);
                }
            }

#pragma unroll
            for (int idx = 0; idx < 4; idx++) {
                int col = (nbp*4 + idx)*8 + t4*2;
                float2 mv = *(float2*)&smask[kt + col];
                float m0 = mv.x * MASKMUL, m1 = mv.y * MASKMUL;
                rs0 += ex2f(fmaf(accS[idx][0], EXSCALE, m0))
                     + ex2f(fmaf(accS[idx][1], EXSCALE, m1));
                rs1 += ex2f(fmaf(accS[idx][2], EXSCALE, m0))
                     + ex2f(fmaf(accS[idx][3], EXSCALE, m1));
            }
        }
        __syncthreads();
    }

    rs0 += __shfl_xor_sync(0xffffffffu, rs0, 1);
    rs0 += __shfl_xor_sync(0xffffffffu, rs0, 2);
    rs1 += __shfl_xor_sync(0xffffffffu, rs1, 1);
    rs1 += __shfl_xor_sync(0xffffffffu, rs1, 2);
    if (t4 == 0) {
        size_t base = hb + (size_t)qt*128;
        g_SUM[base + w*16 + tg]     = rs0;
        g_SUM[base + w*16 + tg + 8] = rs1;
    }
}

// ---------------------------------------------------------------------------
// Pass 2: QK (qh*kh + ql*kh), p = exp/rowsum, attn via staged coalesced rows,
// O += P V (bf16x3).  Q fragments pinned in registers.  Epilogue writes O
// directly as bf16 hi/lo into g_Xhi/g_Xlo slot 0 (feeds out-projection).
// ---------------------------------------------------------------------------
__global__ __launch_bounds__(256, 2) void attn_pv_mma(
    const float* __restrict__ mask, float* __restrict__ attn, int write_attn)
{
    extern __shared__ __align__(16) char sm[];
    uint32_t sb = smem_u32(sm);
    float* Ps = (float*)(sm + S2PS);

    int tid  = threadIdx.x;
    int lane = tid & 31, w = tid >> 5;
    int tg = lane >> 2, t4 = lane & 3;
    int qt = blockIdx.x, h = blockIdx.y, b = blockIdx.z;

    size_t hb = ((size_t)b*Hh + h)*Ss;
    const __nv_bfloat16* Qh = g_Qhi + (hb + (size_t)qt*128)*Dd;
    const __nv_bfloat16* Ql = g_Qlo + (hb + (size_t)qt*128)*Dd;
    const __nv_bfloat16* Kh = g_Khi + hb*Dd;
    const __nv_bfloat16* Vh = g_Vhi + hb*Dd;
    const __nv_bfloat16* Vl = g_Vlo + hb*Dd;
    const float* maskb = mask + (size_t)b*Ss;
    float* attn_base = attn + (hb + (size_t)qt*128)*Ss;

    LOAD_TILE_128(Qh, SQHI)
    LOAD_TILE_128(Ql, SQLO)

    int ld_row = tid >> 3, ld_c8 = (tid & 7) * 8;
    auto issue_kv = [&](int kt, uint32_t stg) {
#pragma unroll
        for (int i = 0; i < 2; i++) {
            int row = ld_row + i*32;
            uint32_t doff = stg + (uint32_t)row*RS + ld_c8*2;
            size_t ga = (size_t)(kt + row)*Dd + ld_c8;
            CP_ASYNC16(sb + doff + S2KHI, Kh + ga);
            CP_ASYNC16(sb + doff + S2VHI, Vh + ga);
            CP_ASYNC16(sb + doff + S2VLO, Vl + ga);
        }
        CP_COMMIT();
    };

    issue_kv(0, S2STG);
    __syncthreads();    // Q tiles visible

    int a_row = lane & 15;
    int a_kb  = (lane >> 4) * 16;
    int b_row = (lane & 7) + ((lane >> 4) << 3);
    int b_kb  = ((lane >> 3) & 1) * 16;
    int v_koff = ((lane >> 3) & 1) * 8 + (lane & 7);
    int v_noff = (lane >> 4) * 8;

    // pin Q fragments for all 4 k16 steps (Q region never overwritten)
    uint32_t qfh[4][4], qfl[4][4];
#pragma unroll
    for (int ks = 0; ks < 4; ks++) {
        uint32_t qa = sb + SQHI + (uint32_t)(w*16 + a_row)*RS + ks*32 + a_kb;
        ldsm_x4(qfh[ks], qa);
        ldsm_x4(qfl[ks], qa + (SQLO - SQHI));
    }

    size_t base = hb + (size_t)qt*128;
    float rinv0 = 1.0f / g_SUM[base + w*16 + tg];
    float rinv1 = 1.0f / g_SUM[base + w*16 + tg + 8];
    int r0g = w*16 + tg;

    float accO[8][4];
#pragma unroll
    for (int nt = 0; nt < 8; nt++)
#pragma unroll
        for (int e = 0; e < 4; e++) accO[nt][e] = 0.f;

    for (int kt = 0; kt < Ss; kt += 64) {
        uint32_t stg = S2STG + (uint32_t)((kt >> 6) & 1) * S2STR;
        CP_WAIT0();
        __syncthreads();
        if (kt + 64 < Ss)
            issue_kv(kt + 64, S2STG + (uint32_t)(((kt >> 6) + 1) & 1) * S2STR);

#pragma unroll
        for (int nbp = 0; nbp < 2; nbp++) {
            // ---- QK: (qh + ql) against kh ----
            float accS[4][4];
#pragma unroll
            for (int j = 0; j < 4; j++)
#pragma unroll
                for (int e = 0; e < 4; e++) accS[j][e] = 0.f;

#pragma unroll
            for (int ks = 0; ks < 4; ks++) {
#pragma unroll
                for (int nb2 = 0; nb2 < 2; nb2++) {
                    int nb = nbp*2 + nb2;
                    uint32_t th[4];
                    uint32_t ad = sb + stg + S2KHI + (uint32_t)(nb*16 + b_row)*RS + ks*32 + b_kb;
                    ldsm_x4(th, ad);
                    int j0 = nb2*2;
                    mma16816(accS[j0],   qfh[ks], th);
                    mma16816(accS[j0],   qfl[ks], th);
                    mma16816(accS[j0+1], qfh[ks], th+2);
                    mma16816(accS[j0+1], qfl[ks], th+2);
                }
            }

            // ---- exp, normalize, stage P in smem, pack for PV ----
            uint32_t ph0[4], ph1[4], pl0[4], pl1[4];
#pragma unroll
            for (int idx = 0; idx < 4; idx++) {
                int lc  = idx*8 + t4*2;
                int col = nbp*32 + lc;
                float2 mv = __ldg((const float2*)(maskb + kt + col));
                float m0 = mv.x * MASKMUL, m1 = mv.y * MASKMUL;
                float p0 = ex2f(fmaf(accS[idx][0], EXSCALE, m0)) * rinv0;
                float p1 = ex2f(fmaf(accS[idx][1], EXSCALE, m1)) * rinv0;
                float p2 = ex2f(fmaf(accS[idx][2], EXSCALE, m0)) * rinv1;
                float p3 = ex2f(fmaf(accS[idx][3], EXSCALE, m1)) * rinv1;
                if (write_attn) {
                    *(float2*)&Ps[(size_t)r0g*36 + lc]       = make_float2(p0, p1);
                    *(float2*)&Ps[(size_t)(r0g + 8)*36 + lc] = make_float2(p2, p3);
                }
                pack2(p0, p1, ph0[idx], pl0[idx]);
                pack2(p2, p3, ph1[idx], pl1[idx]);
            }

            if (write_attn) {
                __syncthreads();
#pragma unroll
                for (int i = 0; i < 4; i++) {
                    int row = (tid >> 3) + i*32;
                    int c4  = (tid & 7) * 4;
                    float4 v = *(float4*)&Ps[(size_t)row*36 + c4];
                    *(float4*)&attn_base[(size_t)row*Ss + kt + nbp*32 + c4] = v;
                }
            }

            // ---- PV (bf16x3) ----
#pragma unroll
            for (int nb2 = 0; nb2 < 2; nb2++) {
                int ksv = nbp*2 + nb2;
                uint32_t ah[4] = {ph0[2*nb2], ph1[2*nb2], ph0[2*nb2+1], ph1[2*nb2+1]};
                uint32_t al[4] = {pl0[2*nb2], pl1[2*nb2], pl0[2*nb2+1], pl1[2*nb2+1]};
#pragma unroll
                for (int vb = 0; vb < 4; vb++) {
                    uint32_t th[4], tl[4];
                    uint32_t ad = sb + stg + S2VHI + (uint32_t)(ksv*16 + v_koff)*RS
                                + (vb*16 + v_noff)*2;
                    ldsm_x4_t(th, ad);
                    ldsm_x4_t(tl, ad + (S2VLO - S2VHI));
                    int nt0 = vb*2;
                    mma16816(accO[nt0],   ah, th);
                    mma16816(accO[nt0],   al, th);
                    mma16816(accO[nt0],   ah, tl);
                    mma16816(accO[nt0+1], ah, th+2);
                    mma16816(accO[nt0+1], al, th+2);
                    mma16816(accO[nt0+1], ah, tl+2);
                }
            }
            if (write_attn)
                __syncthreads();
        }
        __syncthreads();
    }

    // Epilogue: O -> bf16 hi/lo directly into g_Xhi/g_Xlo slot 0 (out-proj input)
    int q0 = qt*128 + w*16 + tg;
#pragma unroll
    for (int nt = 0; nt < 8; nt++) {
        int d = nt*8 + t4*2;
        size_t off0 = ((size_t)b*Ss + q0)*DMm + h*64 + d;
        size_t off1 = ((size_t)b*Ss + q0 + 8)*DMm + h*64 + d;
        uint32_t hi, lo;
        pack2(accO[nt][0], accO[nt][1], hi, lo);
        *(uint32_t*)(g_Xhi + off0) = hi;
        *(uint32_t*)(g_Xlo + off0) = lo;
        pack2(accO[nt][2], accO[nt][3], hi, lo);
        *(uint32_t*)(g_Xhi + off1) = hi;
        *(uint32_t*)(g_Xlo + off1) = lo;
    }
}

// ---------------------------------------------------------------------------
// Launch
// ---------------------------------------------------------------------------
extern "C" void kernel_launch(void* const* d_in, const int* in_sizes, int n_in,
                              void* d_out, int out_size)
{
    const float* q    = (const float*)d_in[0];
    const float* k    = (const float*)d_in[1];
    const float* v    = (const float*)d_in[2];
    const float* mask = (const float*)d_in[3];
    const float* Wq   = (const float*)d_in[4];
    const float* bq   = (const float*)d_in[5];
    const float* Wk   = (const float*)d_in[6];
    const float* bk   = (const float*)d_in[7];
    const float* Wv   = (const float*)d_in[8];
    const float* bv   = (const float*)d_in[9];
    const float* Wo   = (const float*)d_in[10];
    const float* bo   = (const float*)d_in[11];

    float* out  = (float*)d_out;
    float* attn = out + (size_t)NTOK*DMm;

    long long need = (long long)NTOK*DMm + (long long)Bb*Hh*Ss*Ss;
    int write_attn = ((long long)out_size >= need) ? 1 : 0;

    cudaFuncSetAttribute(proj_mma_kernel,
                         cudaFuncAttributeMaxDynamicSharedMemorySize, PROJ_SMEM);
    cudaFuncSetAttribute(attn_sum_mma,
                         cudaFuncAttributeMaxDynamicSharedMemorySize, SUM_SMEM);
    cudaFuncSetAttribute(attn_pv_mma,
                         cudaFuncAttributeMaxDynamicSharedMemorySize, PV_SMEM);

    dim3 cgrid((NTOK*DMm)/(256*4), 3);
    convert_split_kernel<<<cgrid, 256>>>(q, k, v);
    dim3 tgrid(DMm/32, DMm/32, 4);
    transW_kernel<<<tgrid, dim3(32, 8)>>>(Wq, Wk, Wv, Wo);

    dim3 ggrid3(DMm/128, NTOK/128, 3);
    proj_mma_kernel<<<ggrid3, 256, PROJ_SMEM>>>(bq, bk, bv, nullptr, 0);

    dim3 agrid(Ss/128, Hh, Bb);
    attn_sum_mma<<<agrid, 256, SUM_SMEM>>>(mask);
    attn_pv_mma<<<agrid, 256, PV_SMEM>>>(mask, attn, write_attn);

    dim3 ggrid1(DMm/128, NTOK/128, 1);
    proj_mma_kernel<<<ggrid1, 256, PROJ_SMEM>>>(bo, bo, bo, out, 3);
}

// round 16
// speedup vs baseline: 2.8136x; 1.0074x over previous
#include <cuda_runtime.h>
#include <cuda_bf16.h>
#include <cstdint>

#define DMm  1024
#define Hh   16
#define Dd   64
#define Bb   2
#define Ss   2048
#define NTOK (Bb*Ss)   // 4096

// exp(x) = 2^(x*log2e); fold the 1/8 logit scale: 0.125*log2e
#define EXSCALE  0.1803368801111601f
#define MASKMUL  (-1.4426950408889634e9f)

// ---------------------------------------------------------------------------
// Static device scratch
// ---------------------------------------------------------------------------
__device__ float g_SUM[(size_t)Bb*Hh*Ss];
__device__ __nv_bfloat16 g_Xhi [(size_t)3*NTOK*DMm];   // slot 0 reused for O
__device__ __nv_bfloat16 g_Xlo [(size_t)3*NTOK*DMm];
__device__ __nv_bfloat16 g_WThi[(size_t)4*DMm*DMm];
__device__ __nv_bfloat16 g_WTlo[(size_t)4*DMm*DMm];
__device__ __nv_bfloat16 g_Qhi[(size_t)Bb*Hh*Ss*Dd];
__device__ __nv_bfloat16 g_Qlo[(size_t)Bb*Hh*Ss*Dd];
__device__ __nv_bfloat16 g_Khi[(size_t)Bb*Hh*Ss*Dd];
__device__ __nv_bfloat16 g_Klo[(size_t)Bb*Hh*Ss*Dd];
__device__ __nv_bfloat16 g_Vhi[(size_t)Bb*Hh*Ss*Dd];
__device__ __nv_bfloat16 g_Vlo[(size_t)Bb*Hh*Ss*Dd];

// ---------------------------------------------------------------------------
// Helpers (base ISA sm_80+, valid on compute_103)
// ---------------------------------------------------------------------------
__device__ __forceinline__ uint32_t smem_u32(const void* p) {
    uint32_t a;
    asm("{ .reg .u64 t; cvta.to.shared.u64 t, %1; cvt.u32.u64 %0, t; }"
        : "=r"(a) : "l"(p));
    return a;
}

__device__ __forceinline__ void ldsm_x4(uint32_t* r, uint32_t addr) {
    asm volatile("ldmatrix.sync.aligned.m8n8.x4.shared.b16 {%0,%1,%2,%3}, [%4];"
        : "=r"(r[0]), "=r"(r[1]), "=r"(r[2]), "=r"(r[3]) : "r"(addr));
}

__device__ __forceinline__ void ldsm_x4_t(uint32_t* r, uint32_t addr) {
    asm volatile("ldmatrix.sync.aligned.m8n8.x4.trans.shared.b16 {%0,%1,%2,%3}, [%4];"
        : "=r"(r[0]), "=r"(r[1]), "=r"(r[2]), "=r"(r[3]) : "r"(addr));
}

__device__ __forceinline__ void mma16816(float* c, const uint32_t* a, const uint32_t* b) {
    asm volatile(
        "mma.sync.aligned.m16n8k16.row.col.f32.bf16.bf16.f32 "
        "{%0,%1,%2,%3}, {%4,%5,%6,%7}, {%8,%9}, {%0,%1,%2,%3};"
        : "+f"(c[0]), "+f"(c[1]), "+f"(c[2]), "+f"(c[3])
        : "r"(a[0]), "r"(a[1]), "r"(a[2]), "r"(a[3]), "r"(b[0]), "r"(b[1]));
}

#define CP_ASYNC16(dst, src) \
    asm volatile("cp.async.cg.shared.global [%0], [%1], 16;" \
        :: "r"(dst), "l"(src))
#define CP_COMMIT() asm volatile("cp.async.commit_group;")
#define CP_WAIT0()  asm volatile("cp.async.wait_group 0;")

__device__ __forceinline__ float ex2f(float x) {
    float r;
    asm("ex2.approx.f32 %0, %1;" : "=f"(r) : "f"(x));
    return r;
}

__device__ __forceinline__ float lg2f(float x) {
    float r;
    asm("lg2.approx.f32 %0, %1;" : "=f"(r) : "f"(x));
    return r;
}

__device__ __forceinline__ ushort bfu(__nv_bfloat16 h) {
    return __bfloat16_as_ushort(h);
}

__device__ __forceinline__ void split4(float4 v, uint2& hi, uint2& lo) {
    __nv_bfloat16 h0 = __float2bfloat16_rn(v.x);
    __nv_bfloat16 h1 = __float2bfloat16_rn(v.y);
    __nv_bfloat16 h2 = __float2bfloat16_rn(v.z);
    __nv_bfloat16 h3 = __float2bfloat16_rn(v.w);
    hi.x = (uint32_t)bfu(h0) | ((uint32_t)bfu(h1) << 16);
    hi.y = (uint32_t)bfu(h2) | ((uint32_t)bfu(h3) << 16);
    __nv_bfloat16 l0 = __float2bfloat16_rn(v.x - __bfloat162float(h0));
    __nv_bfloat16 l1 = __float2bfloat16_rn(v.y - __bfloat162float(h1));
    __nv_bfloat16 l2 = __float2bfloat16_rn(v.z - __bfloat162float(h2));
    __nv_bfloat16 l3 = __float2bfloat16_rn(v.w - __bfloat162float(h3));
    lo.x = (uint32_t)bfu(l0) | ((uint32_t)bfu(l1) << 16);
    lo.y = (uint32_t)bfu(l2) | ((uint32_t)bfu(l3) << 16);
}

// fast bf16 hi/lo pack of (a,b): lo16 = a, hi16 = b.
__device__ __forceinline__ void pack2(float a, float b, uint32_t& hi, uint32_t& lo) {
    uint32_t u;
    asm("cvt.rn.bf16x2.f32 %0, %1, %2;" : "=r"(u) : "f"(b), "f"(a));
    float af = __uint_as_float(u << 16);
    float bf = __uint_as_float(u & 0xffff0000u);
    hi = u;
    float ra = a - af, rb = b - bf;
    asm("cvt.rn.bf16x2.f32 %0, %1, %2;" : "=r"(lo) : "f"(rb), "f"(ra));
}

// ---------------------------------------------------------------------------
// Fused prep: blocks [0, 12288) split q/k/v; [12288, 16384) transpose+split W.
// ---------------------------------------------------------------------------
__global__ __launch_bounds__(256) void prep_kernel(
    const float* __restrict__ xq, const float* __restrict__ xk,
    const float* __restrict__ xv,
    const float* __restrict__ Wq, const float* __restrict__ Wk,
    const float* __restrict__ Wv, const float* __restrict__ Wo)
{
    __shared__ float t[32][33];
    int bx = blockIdx.x;
    int tid = threadIdx.x;

    if (bx < 12288) {
        int z = bx >> 12;                   // /4096
        int bxx = bx & 4095;
        const float* X = (z == 0) ? xq : (z == 1) ? xk : xv;
        size_t slot = (size_t)z * NTOK * DMm;
        size_t i = ((size_t)bxx * 256 + tid) * 4;
        float4 v = *(const float4*)(X + i);
        uint2 hi, lo;
        split4(v, hi, lo);
        *(uint2*)(g_Xhi + slot + i) = hi;
        *(uint2*)(g_Xlo + slot + i) = lo;
    } else {
        int r = bx - 12288;                 // 0..4095
        int z = r >> 10;
        int tt = r & 1023;
        int bxw = tt & 31, byw = tt >> 5;
        const float* W = (z == 0) ? Wq : (z == 1) ? Wk : (z == 2) ? Wv : Wo;
        size_t slot = (size_t)z * DMm * DMm;
        int nx = bxw * 32, ky = byw * 32;
        int txx = tid & 31, tyy = tid >> 5;
#pragma unroll
        for (int j = 0; j < 4; j++)
            t[tyy + j*8][txx] = W[(size_t)(ky + tyy + j*8)*DMm + nx + txx];
        __syncthreads();
#pragma unroll
        for (int j = 0; j < 4; j++) {
            float val = t[txx][tyy + j*8];
            __nv_bfloat16 h = __float2bfloat16_rn(val);
            size_t o = slot + (size_t)(nx + tyy + j*8)*DMm + ky + txx;
            g_WThi[o] = h;
            g_WTlo[o] = __float2bfloat16_rn(val - __bfloat162float(h));
        }
    }
}

// ---------------------------------------------------------------------------
// HMMA projection GEMM, cp.async double-buffered.  Per-mt A-fragment loads
// keep live registers low (~105).
// ---------------------------------------------------------------------------
#define PRS    80
#define P_AHI  0
#define P_ALO  10240
#define P_BHI  20480
#define P_BLO  30720
#define P_SSTR 40960
#define PROJ_SMEM (2*P_SSTR)         // 81920

__global__ __launch_bounds__(256, 2) void proj_mma_kernel(
    const float* __restrict__ bq, const float* __restrict__ bk,
    const float* __restrict__ bv, float* __restrict__ Yext, int base_mode)
{
    extern __shared__ __align__(16) char psm[];
    uint32_t sb = smem_u32(psm);

    int mode = base_mode + blockIdx.z;
    const float* bias = (blockIdx.z == 0) ? bq : (blockIdx.z == 1) ? bk : bv;

    const __nv_bfloat16* Xhi = g_Xhi + (size_t)(mode == 3 ? 0 : mode) * NTOK * DMm;
    const __nv_bfloat16* Xlo = g_Xlo + (size_t)(mode == 3 ? 0 : mode) * NTOK * DMm;
    const __nv_bfloat16* WThi = g_WThi + (size_t)mode * DMm * DMm;
    const __nv_bfloat16* WTlo = g_WTlo + (size_t)mode * DMm * DMm;

    int tid  = threadIdx.x;
    int lane = tid & 31, wid = tid >> 5;
    int warp_m = wid & 1, warp_n = wid >> 1;
    int row0 = blockIdx.y * 128;
    int col0 = blockIdx.x * 128;

    float acc[4][4][4];
#pragma unroll
    for (int mt = 0; mt < 4; mt++)
#pragma unroll
        for (int nt = 0; nt < 4; nt++)
#pragma unroll
            for (int e = 0; e < 4; e++) acc[mt][nt][e] = 0.f;

    int ld_r = tid >> 1;
    int ld_c = (tid & 1) * 2;

    auto issue = [&](int ch, uint32_t st) {
        int k0 = ch * 32;
#pragma unroll
        for (int cc = 0; cc < 2; cc++) {
            int c = ld_c + cc;
            uint32_t doff = st + (uint32_t)ld_r*PRS + c*16;
            size_t ga = (size_t)(row0 + ld_r)*DMm + k0 + c*8;
            CP_ASYNC16(sb + P_AHI + doff, Xhi + ga);
            CP_ASYNC16(sb + P_ALO + doff, Xlo + ga);
            size_t gb = (size_t)(col0 + ld_r)*DMm + k0 + c*8;
            CP_ASYNC16(sb + P_BHI + doff, WThi + gb);
            CP_ASYNC16(sb + P_BLO + doff, WTlo + gb);
        }
        CP_COMMIT();
    };

    issue(0, 0);

    int a_row = lane & 15;
    int a_kb  = (lane >> 4) * 16;
    int b_row = (lane & 7) + ((lane >> 4) << 3);
    int b_kb  = ((lane >> 3) & 1) * 16;

    for (int ch = 0; ch < 32; ch++) {
        uint32_t st = (uint32_t)(ch & 1) * P_SSTR;
        CP_WAIT0();
        __syncthreads();
        if (ch + 1 < 32)
            issue(ch + 1, (uint32_t)((ch + 1) & 1) * P_SSTR);

#pragma unroll
        for (int kk = 0; kk < 2; kk++) {
            int kbyte = kk * 32;
            uint32_t bhi[4][2], blo[4][2];

#pragma unroll
            for (int p = 0; p < 2; p++) {
                uint32_t bd = sb + st + P_BHI
                            + (uint32_t)(warp_n*32 + p*16 + b_row)*PRS + kbyte + b_kb;
                uint32_t t[4];
                ldsm_x4(t, bd);
                bhi[2*p][0] = t[0]; bhi[2*p][1] = t[1];
                bhi[2*p+1][0] = t[2]; bhi[2*p+1][1] = t[3];
                ldsm_x4(t, bd + (P_BLO - P_BHI));
                blo[2*p][0] = t[0]; blo[2*p][1] = t[1];
                blo[2*p+1][0] = t[2]; blo[2*p+1][1] = t[3];
            }

#pragma unroll
            for (int mt = 0; mt < 4; mt++) {
                uint32_t ahi[4], alo[4];
                uint32_t ad = sb + st + P_AHI
                            + (uint32_t)(warp_m*64 + mt*16 + a_row)*PRS + kbyte + a_kb;
                ldsm_x4(ahi, ad);
                ldsm_x4(alo, ad + (P_ALO - P_AHI));
#pragma unroll
                for (int nt = 0; nt < 4; nt++) {
                    mma16816(acc[mt][nt], ahi, bhi[nt]);
                    mma16816(acc[mt][nt], alo, bhi[nt]);
                    mma16816(acc[mt][nt], ahi, blo[nt]);
                }
            }
        }
        __syncthreads();
    }

    int tg = lane >> 2, t4 = lane & 3;
    __nv_bfloat16 *Yhi = nullptr, *Ylo = nullptr;
    if (mode == 0) { Yhi = g_Qhi; Ylo = g_Qlo; }
    else if (mode == 1) { Yhi = g_Khi; Ylo = g_Klo; }
    else if (mode == 2) { Yhi = g_Vhi; Ylo = g_Vlo; }

#pragma unroll
    for (int mt = 0; mt < 4; mt++) {
        int rbase = row0 + warp_m*64 + mt*16 + tg;
#pragma unroll
        for (int nt = 0; nt < 4; nt++) {
            int col = col0 + warp_n*32 + nt*8 + t4*2;
            float b0 = bias[col], b1 = bias[col + 1];
#pragma unroll
            for (int half = 0; half < 2; half++) {
                int r = rbase + half*8;
                float v0 = acc[mt][nt][half*2 + 0] + b0;
                float v1 = acc[mt][nt][half*2 + 1] + b1;
                if (mode == 3) {
                    *(float2*)(Yext + (size_t)r*DMm + col) = make_float2(v0, v1);
                } else {
                    int bi = r >> 11, s = r & (Ss - 1);
                    int h = col >> 6, d = col & 63;
                    size_t off = (((size_t)bi*Hh + h)*Ss + s)*Dd + d;
                    uint32_t hi, lo;
                    pack2(v0, v1, hi, lo);
                    *(uint32_t*)(Yhi + off) = hi;
                    *(uint32_t*)(Ylo + off) = lo;
                }
            }
        }
    }
}

// ---------------------------------------------------------------------------
// Attention smem layouts.  RS = 144B row stride (ldmatrix conflict-free).
// ---------------------------------------------------------------------------
#define RS    144
#define S1QHI   0
#define S1KSTG  18432
#define S1KSTR  9216
#define S1MSK   36864
#define SUM_SMEM (S1MSK + 8192)        // 45056
#define SQHI    0
#define SQLO    18432
#define S2STG   36864
#define S2STR   27648
#define S2KHI   0
#define S2VHI   9216
#define S2VLO   18432
#define S2PS    92160                  // Ps[128][36] fp32 = 18432 B
#define PV_SMEM (S2PS + 18432)         // 110592

#define LOAD_TILE_128(SRC, SOFF)                                             \
    _Pragma("unroll")                                                        \
    for (int i = 0; i < 4; i++) {                                            \
        int f = tid + i*256;                                                 \
        int row = f >> 3, c8 = (f & 7) * 8;                                  \
        *(uint4*)(sm + (SOFF) + row*RS + c8*2) =                             \
            *(const uint4*)((SRC) + (size_t)row*Dd + c8);                    \
    }

// ---------------------------------------------------------------------------
// Pass 1: rowsums of exp(QK^T/8 + mask), HI-ONLY QK, cp.async K pipeline.
// ---------------------------------------------------------------------------
__global__ __launch_bounds__(256, 3) void attn_sum_mma(const float* __restrict__ mask)
{
    extern __shared__ __align__(16) char sm[];
    uint32_t sb = smem_u32(sm);
    float* smask = (float*)(sm + S1MSK);

    int tid  = threadIdx.x;
    int lane = tid & 31, w = tid >> 5;
    int tg = lane >> 2, t4 = lane & 3;
    int qt = blockIdx.x, h = blockIdx.y, b = blockIdx.z;

    size_t hb = ((size_t)b*Hh + h)*Ss;
    const __nv_bfloat16* Qh = g_Qhi + (hb + (size_t)qt*128)*Dd;
    const __nv_bfloat16* Kh = g_Khi + hb*Dd;

#pragma unroll
    for (int i = 0; i < 2; i++) {
        int f = tid + i*256;
        *(float4*)&smask[f*4] = *(const float4*)(mask + (size_t)b*Ss + f*4);
    }
    LOAD_TILE_128(Qh, S1QHI)

    int ld_row = tid >> 3, ld_c8 = (tid & 7) * 8;
    auto issue_k = [&](int kt, uint32_t stg) {
#pragma unroll
        for (int i = 0; i < 2; i++) {
            int row = ld_row + i*32;
            uint32_t doff = stg + (uint32_t)row*RS + ld_c8*2;
            CP_ASYNC16(sb + doff, Kh + (size_t)(kt + row)*Dd + ld_c8);
        }
        CP_COMMIT();
    };

    issue_k(0, S1KSTG);
    __syncthreads();

    int a_row = lane & 15;
    int a_kb  = (lane >> 4) * 16;
    int b_row = (lane & 7) + ((lane >> 4) << 3);
    int b_kb  = ((lane >> 3) & 1) * 16;

    float rs0 = 0.f, rs1 = 0.f;

    for (int kt = 0; kt < Ss; kt += 64) {
        uint32_t stg = S1KSTG + (uint32_t)((kt >> 6) & 1) * S1KSTR;
        CP_WAIT0();
        __syncthreads();
        if (kt + 64 < Ss)
            issue_k(kt + 64, S1KSTG + (uint32_t)(((kt >> 6) + 1) & 1) * S1KSTR);

#pragma unroll
        for (int nbp = 0; nbp < 2; nbp++) {
            float accS[4][4];
#pragma unroll
            for (int j = 0; j < 4; j++)
#pragma unroll
                for (int e = 0; e < 4; e++) accS[j][e] = 0.f;

#pragma unroll
            for (int ks = 0; ks < 4; ks++) {
                uint32_t qh[4];
                uint32_t qa = sb + S1QHI + (uint32_t)(w*16 + a_row)*RS + ks*32 + a_kb;
                ldsm_x4(qh, qa);
#pragma unroll
                for (int nb2 = 0; nb2 < 2; nb2++) {
                    int nb = nbp*2 + nb2;
                    uint32_t th[4];
                    uint32_t ad = sb + stg + (uint32_t)(nb*16 + b_row)*RS + ks*32 + b_kb;
                    ldsm_x4(th, ad);
                    int j0 = nb2*2;
                    mma16816(accS[j0],   qh, th);
                    mma16816(accS[j0+1], qh, th+2);
                }
            }

#pragma unroll
            for (int idx = 0; idx < 4; idx++) {
                int col = (nbp*4 + idx)*8 + t4*2;
                float2 mv = *(float2*)&smask[kt + col];
                float m0 = mv.x * MASKMUL, m1 = mv.y * MASKMUL;
                rs0 += ex2f(fmaf(accS[idx][0], EXSCALE, m0))
                     + ex2f(fmaf(accS[idx][1], EXSCALE, m1));
                rs1 += ex2f(fmaf(accS[idx][2], EXSCALE, m0))
                     + ex2f(fmaf(accS[idx][3], EXSCALE, m1));
            }
        }
        __syncthreads();
    }

    rs0 += __shfl_xor_sync(0xffffffffu, rs0, 1);
    rs0 += __shfl_xor_sync(0xffffffffu, rs0, 2);
    rs1 += __shfl_xor_sync(0xffffffffu, rs1, 1);
    rs1 += __shfl_xor_sync(0xffffffffu, rs1, 2);
    if (t4 == 0) {
        size_t base = hb + (size_t)qt*128;
        g_SUM[base + w*16 + tg]     = rs0;
        g_SUM[base + w*16 + tg + 8] = rs1;
    }
}

// ---------------------------------------------------------------------------
// Pass 2: QK (qh*kh + ql*kh), p = ex2(s*scale + mask + log2(1/sum)),
// attn via staged coalesced rows, O += P V (bf16x3).  Q frags pinned.
// Epilogue packs O straight into g_Xhi/g_Xlo slot 0.
// ---------------------------------------------------------------------------
__global__ __launch_bounds__(256, 2) void attn_pv_mma(
    const float* __restrict__ mask, float* __restrict__ attn, int write_attn)
{
    extern __shared__ __align__(16) char sm[];
    uint32_t sb = smem_u32(sm);
    float* Ps = (float*)(sm + S2PS);

    int tid  = threadIdx.x;
    int lane = tid & 31, w = tid >> 5;
    int tg = lane >> 2, t4 = lane & 3;
    int qt = blockIdx.x, h = blockIdx.y, b = blockIdx.z;

    size_t hb = ((size_t)b*Hh + h)*Ss;
    const __nv_bfloat16* Qh = g_Qhi + (hb + (size_t)qt*128)*Dd;
    const __nv_bfloat16* Ql = g_Qlo + (hb + (size_t)qt*128)*Dd;
    const __nv_bfloat16* Kh = g_Khi + hb*Dd;
    const __nv_bfloat16* Vh = g_Vhi + hb*Dd;
    const __nv_bfloat16* Vl = g_Vlo + hb*Dd;
    const float* maskb = mask + (size_t)b*Ss;
    float* attn_base = attn + (hb + (size_t)qt*128)*Ss;

    LOAD_TILE_128(Qh, SQHI)
    LOAD_TILE_128(Ql, SQLO)

    int ld_row = tid >> 3, ld_c8 = (tid & 7) * 8;
    auto issue_kv = [&](int kt, uint32_t stg) {
#pragma unroll
        for (int i = 0; i < 2; i++) {
            int row = ld_row + i*32;
            uint32_t doff = stg + (uint32_t)row*RS + ld_c8*2;
            size_t ga = (size_t)(kt + row)*Dd + ld_c8;
            CP_ASYNC16(sb + doff + S2KHI, Kh + ga);
            CP_ASYNC16(sb + doff + S2VHI, Vh + ga);
            CP_ASYNC16(sb + doff + S2VLO, Vl + ga);
        }
        CP_COMMIT();
    };

    issue_kv(0, S2STG);
    __syncthreads();    // Q tiles visible

    int a_row = lane & 15;
    int a_kb  = (lane >> 4) * 16;
    int b_row = (lane & 7) + ((lane >> 4) << 3);
    int b_kb  = ((lane >> 3) & 1) * 16;
    int v_koff = ((lane >> 3) & 1) * 8 + (lane & 7);
    int v_noff = (lane >> 4) * 8;

    uint32_t qfh[4][4], qfl[4][4];
#pragma unroll
    for (int ks = 0; ks < 4; ks++) {
        uint32_t qa = sb + SQHI + (uint32_t)(w*16 + a_row)*RS + ks*32 + a_kb;
        ldsm_x4(qfh[ks], qa);
        ldsm_x4(qfl[ks], qa + (SQLO - SQHI));
    }

    size_t base = hb + (size_t)qt*128;
    float lr0 = -lg2f(g_SUM[base + w*16 + tg]);
    float lr1 = -lg2f(g_SUM[base + w*16 + tg + 8]);
    int r0g = w*16 + tg;

    float accO[8][4];
#pragma unroll
    for (int nt = 0; nt < 8; nt++)
#pragma unroll
        for (int e = 0; e < 4; e++) accO[nt][e] = 0.f;

    for (int kt = 0; kt < Ss; kt += 64) {
        uint32_t stg = S2STG + (uint32_t)((kt >> 6) & 1) * S2STR;
        CP_WAIT0();
        __syncthreads();
        if (kt + 64 < Ss)
            issue_kv(kt + 64, S2STG + (uint32_t)(((kt >> 6) + 1) & 1) * S2STR);

#pragma unroll
        for (int nbp = 0; nbp < 2; nbp++) {
            // ---- QK: (qh + ql) against kh ----
            float accS[4][4];
#pragma unroll
            for (int j = 0; j < 4; j++)
#pragma unroll
                for (int e = 0; e < 4; e++) accS[j][e] = 0.f;

#pragma unroll
            for (int ks = 0; ks < 4; ks++) {
#pragma unroll
                for (int nb2 = 0; nb2 < 2; nb2++) {
                    int nb = nbp*2 + nb2;
                    uint32_t th[4];
                    uint32_t ad = sb + stg + S2KHI + (uint32_t)(nb*16 + b_row)*RS + ks*32 + b_kb;
                    ldsm_x4(th, ad);
                    int j0 = nb2*2;
                    mma16816(accS[j0],   qfh[ks], th);
                    mma16816(accS[j0],   qfl[ks], th);
                    mma16816(accS[j0+1], qfh[ks], th+2);
                    mma16816(accS[j0+1], qfl[ks], th+2);
                }
            }

            // ---- exp with folded 1/rowsum, stage P, pack for PV ----
            uint32_t ph0[4], ph1[4], pl0[4], pl1[4];
#pragma unroll
            for (int idx = 0; idx < 4; idx++) {
                int lc  = idx*8 + t4*2;
                int col = nbp*32 + lc;
                float2 mv = __ldg((const float2*)(maskb + kt + col));
                float b0r0 = fmaf(mv.x, MASKMUL, lr0);
                float b1r0 = fmaf(mv.y, MASKMUL, lr0);
                float b0r1 = fmaf(mv.x, MASKMUL, lr1);
                float b1r1 = fmaf(mv.y, MASKMUL, lr1);
                float p0 = ex2f(fmaf(accS[idx][0], EXSCALE, b0r0));
                float p1 = ex2f(fmaf(accS[idx][1], EXSCALE, b1r0));
                float p2 = ex2f(fmaf(accS[idx][2], EXSCALE, b0r1));
                float p3 = ex2f(fmaf(accS[idx][3], EXSCALE, b1r1));
                if (write_attn) {
                    *(float2*)&Ps[(size_t)r0g*36 + lc]       = make_float2(p0, p1);
                    *(float2*)&Ps[(size_t)(r0g + 8)*36 + lc] = make_float2(p2, p3);
                }
                pack2(p0, p1, ph0[idx], pl0[idx]);
                pack2(p2, p3, ph1[idx], pl1[idx]);
            }

            if (write_attn) {
                __syncthreads();
#pragma unroll
                for (int i = 0; i < 4; i++) {
                    int row = (tid >> 3) + i*32;
                    int c4  = (tid & 7) * 4;
                    float4 v = *(float4*)&Ps[(size_t)row*36 + c4];
                    *(float4*)&attn_base[(size_t)row*Ss + kt + nbp*32 + c4] = v;
                }
            }

            // ---- PV (bf16x3) ----
#pragma unroll
            for (int nb2 = 0; nb2 < 2; nb2++) {
                int ksv = nbp*2 + nb2;
                uint32_t ah[4] = {ph0[2*nb2], ph1[2*nb2], ph0[2*nb2+1], ph1[2*nb2+1]};
                uint32_t al[4] = {pl0[2*nb2], pl1[2*nb2], pl0[2*nb2+1], pl1[2*nb2+1]};
#pragma unroll
                for (int vb = 0; vb < 4; vb++) {
                    uint32_t th[4], tl[4];
                    uint32_t ad = sb + stg + S2VHI + (uint32_t)(ksv*16 + v_koff)*RS
                                + (vb*16 + v_noff)*2;
                    ldsm_x4_t(th, ad);
                    ldsm_x4_t(tl, ad + (S2VLO - S2VHI));
                    int nt0 = vb*2;
                    mma16816(accO[nt0],   ah, th);
                    mma16816(accO[nt0],   al, th);
                    mma16816(accO[nt0],   ah, tl);
                    mma16816(accO[nt0+1], ah, th+2);
                    mma16816(accO[nt0+1], al, th+2);
                    mma16816(accO[nt0+1], ah, tl+2);
                }
            }
            if (write_attn)
                __syncthreads();
        }
        __syncthreads();
    }

    // Epilogue: O -> bf16 hi/lo directly into g_Xhi/g_Xlo slot 0
    int q0 = qt*128 + w*16 + tg;
#pragma unroll
    for (int nt = 0; nt < 8; nt++) {
        int d = nt*8 + t4*2;
        size_t off0 = ((size_t)b*Ss + q0)*DMm + h*64 + d;
        size_t off1 = ((size_t)b*Ss + q0 + 8)*DMm + h*64 + d;
        uint32_t hi, lo;
        pack2(accO[nt][0], accO[nt][1], hi, lo);
        *(uint32_t*)(g_Xhi + off0) = hi;
        *(uint32_t*)(g_Xlo + off0) = lo;
        pack2(accO[nt][2], accO[nt][3], hi, lo);
        *(uint32_t*)(g_Xhi + off1) = hi;
        *(uint32_t*)(g_Xlo + off1) = lo;
    }
}

// ---------------------------------------------------------------------------
// Launch
// ---------------------------------------------------------------------------
extern "C" void kernel_launch(void* const* d_in, const int* in_sizes, int n_in,
                              void* d_out, int out_size)
{
    const float* q    = (const float*)d_in[0];
    const float* k    = (const float*)d_in[1];
    const float* v    = (const float*)d_in[2];
    const float* mask = (const float*)d_in[3];
    const float* Wq   = (const float*)d_in[4];
    const float* bq   = (const float*)d_in[5];
    const float* Wk   = (const float*)d_in[6];
    const float* bk   = (const float*)d_in[7];
    const float* Wv   = (const float*)d_in[8];
    const float* bv   = (const float*)d_in[9];
    const float* Wo   = (const float*)d_in[10];
    const float* bo   = (const float*)d_in[11];

    float* out  = (float*)d_out;
    float* attn = out + (size_t)NTOK*DMm;

    long long need = (long long)NTOK*DMm + (long long)Bb*Hh*Ss*Ss;
    int write_attn = ((long long)out_size >= need) ? 1 : 0;

    cudaFuncSetAttribute(proj_mma_kernel,
                         cudaFuncAttributeMaxDynamicSharedMemorySize, PROJ_SMEM);
    cudaFuncSetAttribute(attn_sum_mma,
                         cudaFuncAttributeMaxDynamicSharedMemorySize, SUM_SMEM);
    cudaFuncSetAttribute(attn_pv_mma,
                         cudaFuncAttributeMaxDynamicSharedMemorySize, PV_SMEM);

    prep_kernel<<<16384, 256>>>(q, k, v, Wq, Wk, Wv, Wo);

    dim3 ggrid3(DMm/128, NTOK/128, 3);
    proj_mma_kernel<<<ggrid3, 256, PROJ_SMEM>>>(bq, bk, bv, nullptr, 0);

    dim3 agrid(Ss/128, Hh, Bb);
    attn_sum_mma<<<agrid, 256, SUM_SMEM>>>(mask);
    attn_pv_mma<<<agrid, 256, PV_SMEM>>>(mask, attn, write_attn);

    dim3 ggrid1(DMm/128, NTOK/128, 1);
    proj_mma_kernel<<<ggrid1, 256, PROJ_SMEM>>>(bo, bo, bo, out, 3);
}